// round 1
// baseline (speedup 1.0000x reference)
#include <cuda_runtime.h>
#include <math.h>

// ---------------- problem constants ----------------
#define N_NODES 50000
#define N_EDGES 200000
#define E_TOT   (N_EDGES + N_NODES)   // + self loops = 250000
#define F0      74
#define H1      4
#define D1      256
#define HD1     (H1 * D1)             // 1024
#define D2      256
#define N_GRAPHS 256
#define OUT_DIM 12
#define NEG_SLOPE 0.2f

// ---------------- scratch (static device globals; no allocs allowed) ----
__device__ float g_h1  [(size_t)N_NODES * HD1];   // x @ W1
__device__ float g_out1[(size_t)N_NODES * HD1];   // layer1 output (post relu)
__device__ float g_h2  [(size_t)N_NODES * D2];    // out1 @ W2
__device__ float g_out2[(size_t)N_NODES * D2];    // layer2 output (post relu)
__device__ float g_als1[N_NODES * H1];
__device__ float g_ald1[N_NODES * H1];
__device__ float g_als2[N_NODES];
__device__ float g_ald2[N_NODES];
__device__ float g_e1[(size_t)E_TOT * H1];
__device__ float g_e2[E_TOT];
__device__ int   g_deg[N_NODES];
__device__ int   g_rowptr[N_NODES + 1];
__device__ int   g_cursor[N_NODES];
__device__ int   g_elist[E_TOT];
__device__ int   g_src[E_TOT];
__device__ int   g_dst[E_TOT];

// int64-vs-int32 runtime detection: for genuinely-int64 little-endian data
// with values < 2^31, every odd 32-bit word is zero.
__device__ __forceinline__ int detect_i64(const int* p) {
    return (p[1] | p[3] | p[5] | p[7]) == 0;
}

__device__ __forceinline__ float leaky(float v) {
    return v >= 0.f ? v : NEG_SLOPE * v;
}

// ---------------- CSR build ----------------
__global__ void k_zero_deg() {
    int i = blockIdx.x * blockDim.x + threadIdx.x;
    if (i < N_NODES) g_deg[i] = 0;
}

__global__ void k_prep_edges(const int* ei32) {
    int e = blockIdx.x * blockDim.x + threadIdx.x;
    if (e >= E_TOT) return;
    int is64 = detect_i64(ei32);
    int s, d;
    if (e < N_EDGES) {
        s = is64 ? ei32[2 * (size_t)e]            : ei32[e];
        d = is64 ? ei32[2 * ((size_t)N_EDGES + e)] : ei32[N_EDGES + e];
    } else {
        s = d = e - N_EDGES;    // self loop
    }
    g_src[e] = s;
    g_dst[e] = d;
    atomicAdd(&g_deg[d], 1);
}

__global__ void k_scan() {   // 1 block, 1024 threads
    __shared__ int sums[1024];
    int t = threadIdx.x;
    const int CH = (N_NODES + 1023) / 1024;
    int b = t * CH, e = min(b + CH, N_NODES);
    int s = 0;
    for (int i = b; i < e; i++) s += g_deg[i];
    sums[t] = s;
    __syncthreads();
    for (int off = 1; off < 1024; off <<= 1) {
        int v = (t >= off) ? sums[t - off] : 0;
        __syncthreads();
        sums[t] += v;
        __syncthreads();
    }
    int run = sums[t] - s;   // exclusive prefix
    for (int i = b; i < e; i++) { g_rowptr[i] = run; run += g_deg[i]; }
    if (t == 1023) g_rowptr[N_NODES] = sums[1023];
}

__global__ void k_init_cursor() {
    int i = blockIdx.x * blockDim.x + threadIdx.x;
    if (i < N_NODES) g_cursor[i] = g_rowptr[i];
}

__global__ void k_scatter() {
    int e = blockIdx.x * blockDim.x + threadIdx.x;
    if (e >= E_TOT) return;
    int p = atomicAdd(&g_cursor[g_dst[e]], 1);
    g_elist[p] = e;
}

// ---------------- tiled SGEMM: C[M,N] = A[M,K] * B[K,N] ----------------
__global__ __launch_bounds__(256) void k_sgemm(
    int M, int N, int K,
    const float* __restrict__ A, const float* __restrict__ B,
    float* __restrict__ C)
{
    const int BM = 128, BN = 128, BK = 16, TM = 8, TN = 8;
    __shared__ float As[BK][BM + 4];
    __shared__ float Bs[BK][BN];
    int tid = threadIdx.x;
    int brow = blockIdx.y * BM, bcol = blockIdx.x * BN;
    int tr = (tid / (BN / TN)) * TM;
    int tc = (tid % (BN / TN)) * TN;
    float acc[TM][TN];
#pragma unroll
    for (int m = 0; m < TM; m++)
#pragma unroll
        for (int n = 0; n < TN; n++) acc[m][n] = 0.f;

    for (int k0 = 0; k0 < K; k0 += BK) {
#pragma unroll
        for (int i = tid; i < BM * BK; i += 256) {
            int r = i >> 4, c = i & 15;
            int gr = brow + r, gc = k0 + c;
            As[c][r] = (gr < M && gc < K) ? A[(size_t)gr * K + gc] : 0.f;
        }
#pragma unroll
        for (int i = tid; i < BK * BN; i += 256) {
            int r = i >> 7, c = i & 127;
            int gr = k0 + r;
            Bs[r][c] = (gr < K) ? B[(size_t)gr * N + bcol + c] : 0.f;
        }
        __syncthreads();
#pragma unroll
        for (int k = 0; k < BK; k++) {
            float ra[TM], rb[TN];
#pragma unroll
            for (int m = 0; m < TM; m++) ra[m] = As[k][tr + m];
#pragma unroll
            for (int n = 0; n < TN; n++) rb[n] = Bs[k][tc + n];
#pragma unroll
            for (int m = 0; m < TM; m++)
#pragma unroll
                for (int n = 0; n < TN; n++) acc[m][n] = fmaf(ra[m], rb[n], acc[m][n]);
        }
        __syncthreads();
    }
#pragma unroll
    for (int m = 0; m < TM; m++) {
        int gr = brow + tr + m;
        if (gr >= M) continue;
#pragma unroll
        for (int n = 0; n < TN; n++)
            C[(size_t)gr * N + bcol + tc + n] = acc[m][n];
    }
}

// ---------------- attention logits: al_src/al_dst, layer 1 ----------------
// one block of 128 threads per node; warp w handles head w
__global__ void k_al1(const float* __restrict__ a_src, const float* __restrict__ a_dst) {
    int n = blockIdx.x;
    int w = threadIdx.x >> 5, l = threadIdx.x & 31;
    const float* row = g_h1 + (size_t)n * HD1 + w * D1;
    float ps = 0.f, pd = 0.f;
    for (int d = l; d < D1; d += 32) {
        float v = row[d];
        ps = fmaf(v, a_src[w * D1 + d], ps);
        pd = fmaf(v, a_dst[w * D1 + d], pd);
    }
#pragma unroll
    for (int o = 16; o; o >>= 1) {
        ps += __shfl_xor_sync(0xffffffffu, ps, o);
        pd += __shfl_xor_sync(0xffffffffu, pd, o);
    }
    if (l == 0) {
        g_als1[n * H1 + w] = ps;
        g_ald1[n * H1 + w] = pd;
    }
}

// layer-2 (single head): 8 nodes per 256-thread block, warp per node
__global__ void k_al2(const float* __restrict__ a_src, const float* __restrict__ a_dst) {
    int w = threadIdx.x >> 5, l = threadIdx.x & 31;
    int n = blockIdx.x * 8 + w;
    if (n >= N_NODES) return;
    const float* row = g_h2 + (size_t)n * D2;
    float ps = 0.f, pd = 0.f;
    for (int d = l; d < D2; d += 32) {
        float v = row[d];
        ps = fmaf(v, a_src[d], ps);
        pd = fmaf(v, a_dst[d], pd);
    }
#pragma unroll
    for (int o = 16; o; o >>= 1) {
        ps += __shfl_xor_sync(0xffffffffu, ps, o);
        pd += __shfl_xor_sync(0xffffffffu, pd, o);
    }
    if (l == 0) { g_als2[n] = ps; g_ald2[n] = pd; }
}

// ---------------- edge logits ----------------
__global__ void k_edge1() {
    int e = blockIdx.x * blockDim.x + threadIdx.x;
    if (e >= E_TOT) return;
    int s = g_src[e], d = g_dst[e];
    const float4 as = *(const float4*)(g_als1 + s * 4);
    const float4 ad = *(const float4*)(g_ald1 + d * 4);
    float4 o;
    o.x = leaky(as.x + ad.x);
    o.y = leaky(as.y + ad.y);
    o.z = leaky(as.z + ad.z);
    o.w = leaky(as.w + ad.w);
    *(float4*)(g_e1 + (size_t)e * 4) = o;
}

__global__ void k_edge2() {
    int e = blockIdx.x * blockDim.x + threadIdx.x;
    if (e >= E_TOT) return;
    g_e2[e] = leaky(g_als2[g_src[e]] + g_ald2[g_dst[e]]);
}

// ---------------- softmax + aggregate, layer 1 ----------------
// block per node, 256 threads; thread t owns feature column t in every head
__global__ __launch_bounds__(256) void k_agg1(const float* __restrict__ b1) {
    int n = blockIdx.x, t = threadIdx.x;
    int start = g_rowptr[n], deg = g_rowptr[n + 1] - start;
    __shared__ float sm[H1], sinv[H1];
    __shared__ float ash[64 * H1];
    __shared__ int   ssrc[64];

    if (t < 32) {
        float lm[H1] = {-1e30f, -1e30f, -1e30f, -1e30f};
        for (int j = t; j < deg; j += 32) {
            const float* ep = g_e1 + (size_t)g_elist[start + j] * H1;
#pragma unroll
            for (int h = 0; h < H1; h++) lm[h] = fmaxf(lm[h], ep[h]);
        }
#pragma unroll
        for (int o = 16; o; o >>= 1)
#pragma unroll
            for (int h = 0; h < H1; h++) lm[h] = fmaxf(lm[h], __shfl_xor_sync(0xffffffffu, lm[h], o));
        float ls[H1] = {0.f, 0.f, 0.f, 0.f};
        for (int j = t; j < deg; j += 32) {
            const float* ep = g_e1 + (size_t)g_elist[start + j] * H1;
#pragma unroll
            for (int h = 0; h < H1; h++) ls[h] += expf(ep[h] - lm[h]);
        }
#pragma unroll
        for (int o = 16; o; o >>= 1)
#pragma unroll
            for (int h = 0; h < H1; h++) ls[h] += __shfl_xor_sync(0xffffffffu, ls[h], o);
        if (t == 0) {
#pragma unroll
            for (int h = 0; h < H1; h++) { sm[h] = lm[h]; sinv[h] = 1.f / (ls[h] + 1e-16f); }
        }
    }
    __syncthreads();

    float acc0 = 0.f, acc1 = 0.f, acc2 = 0.f, acc3 = 0.f;
    for (int c0 = 0; c0 < deg; c0 += 64) {
        int cnt = min(64, deg - c0);
        if (t < cnt) ssrc[t] = g_src[g_elist[start + c0 + t]];
        if (t < cnt * 4) {
            int j = t >> 2, h = t & 3;
            int e = g_elist[start + c0 + j];
            ash[t] = expf(g_e1[(size_t)e * H1 + h] - sm[h]) * sinv[h];
        }
        __syncthreads();
        for (int j = 0; j < cnt; j++) {
            const float* hr = g_h1 + (size_t)ssrc[j] * HD1 + t;
            float a0 = ash[j * 4 + 0], a1 = ash[j * 4 + 1];
            float a2 = ash[j * 4 + 2], a3 = ash[j * 4 + 3];
            acc0 = fmaf(hr[0],       a0, acc0);
            acc1 = fmaf(hr[D1],      a1, acc1);
            acc2 = fmaf(hr[2 * D1],  a2, acc2);
            acc3 = fmaf(hr[3 * D1],  a3, acc3);
        }
        __syncthreads();
    }
    float* orow = g_out1 + (size_t)n * HD1;
    orow[t]          = fmaxf(acc0 + b1[t],          0.f);
    orow[t + D1]     = fmaxf(acc1 + b1[t + D1],     0.f);
    orow[t + 2 * D1] = fmaxf(acc2 + b1[t + 2 * D1], 0.f);
    orow[t + 3 * D1] = fmaxf(acc3 + b1[t + 3 * D1], 0.f);
}

// ---------------- softmax + aggregate, layer 2 (H=1) ----------------
__global__ __launch_bounds__(256) void k_agg2(const float* __restrict__ b2) {
    int n = blockIdx.x, t = threadIdx.x;
    int start = g_rowptr[n], deg = g_rowptr[n + 1] - start;
    __shared__ float sm, sinv;
    __shared__ float ash[64];
    __shared__ int   ssrc[64];

    if (t < 32) {
        float lm = -1e30f;
        for (int j = t; j < deg; j += 32) lm = fmaxf(lm, g_e2[g_elist[start + j]]);
#pragma unroll
        for (int o = 16; o; o >>= 1) lm = fmaxf(lm, __shfl_xor_sync(0xffffffffu, lm, o));
        float ls = 0.f;
        for (int j = t; j < deg; j += 32) ls += expf(g_e2[g_elist[start + j]] - lm);
#pragma unroll
        for (int o = 16; o; o >>= 1) ls += __shfl_xor_sync(0xffffffffu, ls, o);
        if (t == 0) { sm = lm; sinv = 1.f / (ls + 1e-16f); }
    }
    __syncthreads();

    float acc = 0.f;
    for (int c0 = 0; c0 < deg; c0 += 64) {
        int cnt = min(64, deg - c0);
        if (t < cnt) {
            int e = g_elist[start + c0 + t];
            ssrc[t] = g_src[e];
            ash[t] = expf(g_e2[e] - sm) * sinv;
        }
        __syncthreads();
        for (int j = 0; j < cnt; j++)
            acc = fmaf(g_h2[(size_t)ssrc[j] * D2 + t], ash[j], acc);
        __syncthreads();
    }
    g_out2[(size_t)n * D2 + t] = fmaxf(acc + b2[t], 0.f);
}

// ---------------- pool (mean per graph) + FC ----------------
__device__ __forceinline__ int lower_bound_batch(const int* b32, int is64, int key) {
    int lo = 0, hi = N_NODES;
    while (lo < hi) {
        int mid = (lo + hi) >> 1;
        int v = is64 ? b32[2 * mid] : b32[mid];   // low word holds the value either way
        if (v < key) lo = mid + 1; else hi = mid;
    }
    return lo;
}

__global__ __launch_bounds__(256) void k_pool_fc(
    const int* __restrict__ batch32, const int* __restrict__ ei32,
    const float* __restrict__ fcW, const float* __restrict__ fcb,
    float* __restrict__ out)
{
    int g = blockIdx.x, t = threadIdx.x;
    __shared__ int s_lo, s_hi;
    __shared__ float pooled[D2];
    if (t == 0) {
        int is64 = detect_i64(ei32);   // edge_index and batch share dtype
        s_lo = lower_bound_batch(batch32, is64, g);
        s_hi = lower_bound_batch(batch32, is64, g + 1);
    }
    __syncthreads();
    int lo = s_lo, hi = s_hi;
    float s = 0.f;
    for (int n = lo; n < hi; n++) s += g_out2[(size_t)n * D2 + t];
    float cnt = (float)(hi - lo);
    pooled[t] = s / fmaxf(cnt, 1.f);
    __syncthreads();
    if (t < OUT_DIM) {
        float acc = fcb[t];
        for (int d = 0; d < D2; d++) acc = fmaf(pooled[d], fcW[d * OUT_DIM + t], acc);
        out[g * OUT_DIM + t] = acc;
    }
}

// ---------------- launch ----------------
extern "C" void kernel_launch(void* const* d_in, const int* in_sizes, int n_in,
                              void* d_out, int out_size)
{
    const float* x      = (const float*)d_in[0];
    const int*   ei32   = (const int*)  d_in[1];
    const int*   bat32  = (const int*)  d_in[2];
    const float* W1     = (const float*)d_in[3];
    const float* a_src1 = (const float*)d_in[4];
    const float* a_dst1 = (const float*)d_in[5];
    const float* b1     = (const float*)d_in[6];
    const float* W2     = (const float*)d_in[7];
    const float* a_src2 = (const float*)d_in[8];
    const float* a_dst2 = (const float*)d_in[9];
    const float* b2     = (const float*)d_in[10];
    const float* fcW    = (const float*)d_in[11];
    const float* fcb    = (const float*)d_in[12];
    float* out = (float*)d_out;

    float* h1   = nullptr; cudaGetSymbolAddress((void**)&h1,   g_h1);
    float* out1 = nullptr; cudaGetSymbolAddress((void**)&out1, g_out1);
    float* h2   = nullptr; cudaGetSymbolAddress((void**)&h2,   g_h2);

    // CSR build
    k_zero_deg<<<(N_NODES + 255) / 256, 256>>>();
    k_prep_edges<<<(E_TOT + 255) / 256, 256>>>(ei32);
    k_scan<<<1, 1024>>>();
    k_init_cursor<<<(N_NODES + 255) / 256, 256>>>();
    k_scatter<<<(E_TOT + 255) / 256, 256>>>();

    // layer 1
    {
        dim3 grid(HD1 / 128, (N_NODES + 127) / 128);
        k_sgemm<<<grid, 256>>>(N_NODES, HD1, F0, x, W1, h1);
    }
    k_al1<<<N_NODES, 128>>>(a_src1, a_dst1);
    k_edge1<<<(E_TOT + 255) / 256, 256>>>();
    k_agg1<<<N_NODES, 256>>>(b1);

    // layer 2
    {
        dim3 grid(D2 / 128, (N_NODES + 127) / 128);
        k_sgemm<<<grid, 256>>>(N_NODES, D2, HD1, out1, W2, h2);
    }
    k_al2<<<(N_NODES + 7) / 8, 256>>>(a_src2, a_dst2);
    k_edge2<<<(E_TOT + 255) / 256, 256>>>();
    k_agg2<<<N_NODES, 256>>>(b2);

    // pool + fc
    k_pool_fc<<<N_GRAPHS, 256>>>(bat32, ei32, fcW, fcb, out);
}

// round 3
// speedup vs baseline: 1.5883x; 1.5883x over previous
#include <cuda_runtime.h>
#include <cuda_bf16.h>
#include <math.h>
#include <stdint.h>

// ---------------- problem constants ----------------
#define N_NODES 50000
#define N_EDGES 200000
#define E_TOT   (N_EDGES + N_NODES)   // 250000
#define F0      74
#define K1PAD   128                   // F0 padded up
#define H1      4
#define D1      256
#define HD1     (H1 * D1)             // 1024
#define D2      256
#define N_GRAPHS 256
#define OUT_DIM 12
#define NEG_SLOPE 0.2f

// ---------------- scratch ----------------
__device__ float g_h1  [(size_t)N_NODES * HD1];
__device__ float g_h2  [(size_t)N_NODES * D2];
__device__ float g_out2[(size_t)N_NODES * D2];
__device__ float g_als1[N_NODES * H1];
__device__ float g_ald1[N_NODES * H1];
__device__ float g_als2[N_NODES];
__device__ float g_ald2[N_NODES];
__device__ float g_e1[(size_t)E_TOT * H1];
__device__ float g_e2[E_TOT];
__device__ int   g_deg[N_NODES];
__device__ int   g_rowptr[N_NODES + 1];
__device__ int   g_cursor[N_NODES];
__device__ int   g_elist[E_TOT];
__device__ int   g_src[E_TOT];
__device__ int   g_dst[E_TOT];

// bf16 split operands (K-major rows, 16B-aligned)
__device__ uint4 g_xs1 [(size_t)N_NODES * K1PAD / 8];
__device__ uint4 g_xs2 [(size_t)N_NODES * K1PAD / 8];
__device__ uint4 g_w1a [(size_t)HD1 * K1PAD / 8];     // W1^T [1024,128]
__device__ uint4 g_w1b [(size_t)HD1 * K1PAD / 8];
__device__ uint4 g_o1a [(size_t)N_NODES * HD1 / 8];   // relu(out1) split
__device__ uint4 g_o1b [(size_t)N_NODES * HD1 / 8];
__device__ uint4 g_w2a [(size_t)D2 * HD1 / 8];        // W2^T [256,1024]
__device__ uint4 g_w2b [(size_t)D2 * HD1 / 8];

// ---------------- PTX helpers (baseline target, sm_80+) ----------------
__device__ __forceinline__ uint32_t smem_u32(const void* p) {
    uint32_t a;
    asm("{ .reg .u64 t; cvta.to.shared.u64 t, %1; cvt.u32.u64 %0, t; }" : "=r"(a) : "l"(p));
    return a;
}
#define CP_ASYNC16(dst, src) \
    asm volatile("cp.async.cg.shared.global [%0], [%1], 16;" :: "r"(dst), "l"(src))
#define CP_COMMIT() asm volatile("cp.async.commit_group;" ::: "memory")
#define CP_WAIT0()  asm volatile("cp.async.wait_group 0;" ::: "memory")
#define CP_WAIT1()  asm volatile("cp.async.wait_group 1;" ::: "memory")

#define LDSM_X4(r, addr) \
    asm volatile("ldmatrix.sync.aligned.m8n8.x4.shared.b16 {%0,%1,%2,%3}, [%4];" \
        : "=r"((r)[0]), "=r"((r)[1]), "=r"((r)[2]), "=r"((r)[3]) : "r"(addr))

#define MMA_BF16(d, a, b) \
    asm volatile("mma.sync.aligned.m16n8k16.row.col.f32.bf16.bf16.f32 " \
        "{%0,%1,%2,%3}, {%4,%5,%6,%7}, {%8,%9}, {%0,%1,%2,%3};" \
        : "+f"((d)[0]), "+f"((d)[1]), "+f"((d)[2]), "+f"((d)[3]) \
        : "r"((a)[0]), "r"((a)[1]), "r"((a)[2]), "r"((a)[3]), "r"((b)[0]), "r"((b)[1]))

// ---------------- misc ----------------
__device__ __forceinline__ int detect_i64(const int* p) {
    return (p[1] | p[3] | p[5] | p[7]) == 0;
}
__device__ __forceinline__ float leaky(float v) { return v >= 0.f ? v : NEG_SLOPE * v; }

// ---------------- bf16 split prep ----------------
__global__ void k_split_x(const float* __restrict__ x) {
    int i = blockIdx.x * blockDim.x + threadIdx.x;
    if (i >= N_NODES * K1PAD) return;
    int r = i >> 7, c = i & 127;
    float v = (c < F0) ? x[(size_t)r * F0 + c] : 0.f;
    __nv_bfloat16 hi = __float2bfloat16(v);
    ((__nv_bfloat16*)g_xs1)[i] = hi;
    ((__nv_bfloat16*)g_xs2)[i] = __float2bfloat16(v - __bfloat162float(hi));
}
__global__ void k_split_w1(const float* __restrict__ W1) {
    int i = blockIdx.x * blockDim.x + threadIdx.x;   // [1024 n][128 k]
    if (i >= HD1 * K1PAD) return;
    int n = i >> 7, k = i & 127;
    float v = (k < F0) ? W1[(size_t)k * HD1 + n] : 0.f;
    __nv_bfloat16 hi = __float2bfloat16(v);
    ((__nv_bfloat16*)g_w1a)[i] = hi;
    ((__nv_bfloat16*)g_w1b)[i] = __float2bfloat16(v - __bfloat162float(hi));
}
__global__ void k_split_w2(const float* __restrict__ W2) {
    int i = blockIdx.x * blockDim.x + threadIdx.x;   // [256 n][1024 k]
    if (i >= D2 * HD1) return;
    int n = i >> 10, k = i & 1023;
    float v = W2[(size_t)k * D2 + n];
    __nv_bfloat16 hi = __float2bfloat16(v);
    ((__nv_bfloat16*)g_w2a)[i] = hi;
    ((__nv_bfloat16*)g_w2b)[i] = __float2bfloat16(v - __bfloat162float(hi));
}

// ---------------- mma.sync GEMM ----------------
// C[M, gridDim.x*128] = A[M,K] @ B[N,K]^T with bf16 3-term compensated product.
// CTA 128x128, BK=32, 8 warps (2x4) of 64x32, 2-stage cp.async pipeline.
#define SMSTRIDE 80                          // bytes per 32-elem bf16 row (64B + 16B pad)
#define TILE_B   (128 * SMSTRIDE)            // 10240 B per operand tile
#define GM_SMEM  (2 * 4 * TILE_B)            // 81920 B

template <int KT, int LDC>                   // K = KT*32
__global__ __launch_bounds__(256, 2) void k_mma(
    const uint4* __restrict__ A1, const uint4* __restrict__ A2,
    const uint4* __restrict__ B1, const uint4* __restrict__ B2,
    float* __restrict__ C, int M)
{
    extern __shared__ char smem[];
    const uint32_t sbase = smem_u32(smem);
    const int tid = threadIdx.x, lane = tid & 31, wid = tid >> 5;
    const int wm = wid & 1, wn = wid >> 1;        // warp 64-row half, 32-col quarter
    const int m0 = blockIdx.y * 128, n0 = blockIdx.x * 128;
    const int KW = KT * 4;                        // uint4 per global row

    float acc[4][4][4];
#pragma unroll
    for (int a = 0; a < 4; a++)
#pragma unroll
        for (int b = 0; b < 4; b++)
#pragma unroll
            for (int c = 0; c < 4; c++) acc[a][b][c] = 0.f;

    // per-thread load slots: idx in [0,512): row=idx/4, 16B chunk=idx%3..
    const int row_a = tid >> 1;                   // not used; see loop below
    (void)row_a;

    auto load_stage = [&](int ki, int s) {
        uint32_t sb = sbase + s * (4 * TILE_B);
#pragma unroll
        for (int i = 0; i < 2; i++) {
            int idx = tid + i * 256;              // 0..511
            int row = idx >> 2, ch = idx & 3;
            uint32_t soff = row * SMSTRIDE + ch * 16;
            int ar = min(m0 + row, M - 1);
            size_t ga = (size_t)ar * KW + ki * 4 + ch;
            size_t gb = (size_t)(n0 + row) * KW + ki * 4 + ch;
            CP_ASYNC16(sb + soff,              A1 + ga);
            CP_ASYNC16(sb + TILE_B + soff,     A2 + ga);
            CP_ASYNC16(sb + 2 * TILE_B + soff, B1 + gb);
            CP_ASYNC16(sb + 3 * TILE_B + soff, B2 + gb);
        }
        CP_COMMIT();
    };

    load_stage(0, 0);

    for (int ki = 0; ki < KT; ki++) {
        if (ki + 1 < KT) load_stage(ki + 1, (ki + 1) & 1);
        if (ki + 1 < KT) CP_WAIT1(); else CP_WAIT0();
        __syncthreads();

        uint32_t sb  = sbase + (ki & 1) * (4 * TILE_B);
        uint32_t a1b = sb, a2b = sb + TILE_B, b1b = sb + 2 * TILE_B, b2b = sb + 3 * TILE_B;

#pragma unroll
        for (int k16 = 0; k16 < 2; k16++) {
            // B fragments: 2 x4-ldmatrix per split cover 4 n8-tiles
            uint32_t bf1[8], bf2[8];
#pragma unroll
            for (int g = 0; g < 2; g++) {
                int nrow = wn * 32 + g * 16 + (lane & 7) + ((lane >> 4) << 3);
                int kb   = k16 * 32 + (((lane >> 3) & 1) << 4);
                uint32_t ao = nrow * SMSTRIDE + kb;
                LDSM_X4(&bf1[g * 4], b1b + ao);
                LDSM_X4(&bf2[g * 4], b2b + ao);
            }
#pragma unroll
            for (int mt = 0; mt < 4; mt++) {
                int arow = wm * 64 + mt * 16 + (lane & 7) + (((lane >> 3) & 1) << 3);
                int kb   = k16 * 32 + ((lane >> 4) << 4);
                uint32_t ao = arow * SMSTRIDE + kb;
                uint32_t af[4];
                LDSM_X4(af, a1b + ao);
#pragma unroll
                for (int nt = 0; nt < 4; nt++) MMA_BF16(acc[mt][nt], af, &bf1[nt * 2]);
#pragma unroll
                for (int nt = 0; nt < 4; nt++) MMA_BF16(acc[mt][nt], af, &bf2[nt * 2]);
                LDSM_X4(af, a2b + ao);
#pragma unroll
                for (int nt = 0; nt < 4; nt++) MMA_BF16(acc[mt][nt], af, &bf1[nt * 2]);
            }
        }
        __syncthreads();
    }

    // epilogue
#pragma unroll
    for (int mt = 0; mt < 4; mt++) {
        int r = m0 + wm * 64 + mt * 16 + (lane >> 2);
#pragma unroll
        for (int nt = 0; nt < 4; nt++) {
            int c = n0 + wn * 32 + nt * 8 + (lane & 3) * 2;
            if (r < M)
                *(float2*)&C[(size_t)r * LDC + c] = make_float2(acc[mt][nt][0], acc[mt][nt][1]);
            if (r + 8 < M)
                *(float2*)&C[(size_t)(r + 8) * LDC + c] = make_float2(acc[mt][nt][2], acc[mt][nt][3]);
        }
    }
}

// ---------------- attention logits ----------------
__global__ void k_al1(const float* __restrict__ a_src, const float* __restrict__ a_dst) {
    int n = blockIdx.x;
    int w = threadIdx.x >> 5, l = threadIdx.x & 31;
    const float* row = g_h1 + (size_t)n * HD1 + w * D1;
    float ps = 0.f, pd = 0.f;
    for (int d = l; d < D1; d += 32) {
        float v = row[d];
        ps = fmaf(v, a_src[w * D1 + d], ps);
        pd = fmaf(v, a_dst[w * D1 + d], pd);
    }
#pragma unroll
    for (int o = 16; o; o >>= 1) {
        ps += __shfl_xor_sync(0xffffffffu, ps, o);
        pd += __shfl_xor_sync(0xffffffffu, pd, o);
    }
    if (l == 0) { g_als1[n * H1 + w] = ps; g_ald1[n * H1 + w] = pd; }
}
__global__ void k_al2(const float* __restrict__ a_src, const float* __restrict__ a_dst) {
    int w = threadIdx.x >> 5, l = threadIdx.x & 31;
    int n = blockIdx.x * 8 + w;
    if (n >= N_NODES) return;
    const float* row = g_h2 + (size_t)n * D2;
    float ps = 0.f, pd = 0.f;
    for (int d = l; d < D2; d += 32) {
        float v = row[d];
        ps = fmaf(v, a_src[d], ps);
        pd = fmaf(v, a_dst[d], pd);
    }
#pragma unroll
    for (int o = 16; o; o >>= 1) {
        ps += __shfl_xor_sync(0xffffffffu, ps, o);
        pd += __shfl_xor_sync(0xffffffffu, pd, o);
    }
    if (l == 0) { g_als2[n] = ps; g_ald2[n] = pd; }
}

// ---------------- CSR build ----------------
__global__ void k_zero_deg() {
    int i = blockIdx.x * blockDim.x + threadIdx.x;
    if (i < N_NODES) g_deg[i] = 0;
}
__global__ void k_prep_edges(const int* ei32) {
    int e = blockIdx.x * blockDim.x + threadIdx.x;
    if (e >= E_TOT) return;
    int is64 = detect_i64(ei32);
    int s, d;
    if (e < N_EDGES) {
        s = is64 ? ei32[2 * (size_t)e]             : ei32[e];
        d = is64 ? ei32[2 * ((size_t)N_EDGES + e)] : ei32[N_EDGES + e];
    } else {
        s = d = e - N_EDGES;
    }
    g_src[e] = s;
    g_dst[e] = d;
    atomicAdd(&g_deg[d], 1);
}
__global__ void k_scan() {
    __shared__ int sums[1024];
    int t = threadIdx.x;
    const int CH = (N_NODES + 1023) / 1024;
    int b = t * CH, e = min(b + CH, N_NODES);
    int s = 0;
    for (int i = b; i < e; i++) s += g_deg[i];
    sums[t] = s;
    __syncthreads();
    for (int off = 1; off < 1024; off <<= 1) {
        int v = (t >= off) ? sums[t - off] : 0;
        __syncthreads();
        sums[t] += v;
        __syncthreads();
    }
    int run = sums[t] - s;
    for (int i = b; i < e; i++) { g_rowptr[i] = run; run += g_deg[i]; }
    if (t == 1023) g_rowptr[N_NODES] = sums[1023];
}
__global__ void k_init_cursor() {
    int i = blockIdx.x * blockDim.x + threadIdx.x;
    if (i < N_NODES) g_cursor[i] = g_rowptr[i];
}
__global__ void k_scatter() {
    int e = blockIdx.x * blockDim.x + threadIdx.x;
    if (e >= E_TOT) return;
    int p = atomicAdd(&g_cursor[g_dst[e]], 1);
    g_elist[p] = e;
}

// ---------------- edge logits ----------------
__global__ void k_edge1() {
    int e = blockIdx.x * blockDim.x + threadIdx.x;
    if (e >= E_TOT) return;
    int s = g_src[e], d = g_dst[e];
    const float4 as = *(const float4*)(g_als1 + s * 4);
    const float4 ad = *(const float4*)(g_ald1 + d * 4);
    float4 o;
    o.x = leaky(as.x + ad.x);
    o.y = leaky(as.y + ad.y);
    o.z = leaky(as.z + ad.z);
    o.w = leaky(as.w + ad.w);
    *(float4*)(g_e1 + (size_t)e * 4) = o;
}
__global__ void k_edge2() {
    int e = blockIdx.x * blockDim.x + threadIdx.x;
    if (e >= E_TOT) return;
    g_e2[e] = leaky(g_als2[g_src[e]] + g_ald2[g_dst[e]]);
}

// ---------------- softmax + aggregate, layer 1 ----------------
__global__ __launch_bounds__(256) void k_agg1(const float* __restrict__ b1) {
    int n = blockIdx.x, t = threadIdx.x;
    int start = g_rowptr[n], deg = g_rowptr[n + 1] - start;
    __shared__ float sm[H1], sinv[H1];
    __shared__ float ash[64 * H1];
    __shared__ int   ssrc[64];

    if (t < 32) {
        float lm[H1] = {-1e30f, -1e30f, -1e30f, -1e30f};
        for (int j = t; j < deg; j += 32) {
            const float* ep = g_e1 + (size_t)g_elist[start + j] * H1;
#pragma unroll
            for (int h = 0; h < H1; h++) lm[h] = fmaxf(lm[h], ep[h]);
        }
#pragma unroll
        for (int o = 16; o; o >>= 1)
#pragma unroll
            for (int h = 0; h < H1; h++) lm[h] = fmaxf(lm[h], __shfl_xor_sync(0xffffffffu, lm[h], o));
        float ls[H1] = {0.f, 0.f, 0.f, 0.f};
        for (int j = t; j < deg; j += 32) {
            const float* ep = g_e1 + (size_t)g_elist[start + j] * H1;
#pragma unroll
            for (int h = 0; h < H1; h++) ls[h] += expf(ep[h] - lm[h]);
        }
#pragma unroll
        for (int o = 16; o; o >>= 1)
#pragma unroll
            for (int h = 0; h < H1; h++) ls[h] += __shfl_xor_sync(0xffffffffu, ls[h], o);
        if (t == 0) {
#pragma unroll
            for (int h = 0; h < H1; h++) { sm[h] = lm[h]; sinv[h] = 1.f / (ls[h] + 1e-16f); }
        }
    }
    __syncthreads();

    float acc0 = 0.f, acc1 = 0.f, acc2 = 0.f, acc3 = 0.f;
    for (int c0 = 0; c0 < deg; c0 += 64) {
        int cnt = min(64, deg - c0);
        if (t < cnt) ssrc[t] = g_src[g_elist[start + c0 + t]];
        if (t < cnt * 4) {
            int j = t >> 2, h = t & 3;
            int e = g_elist[start + c0 + j];
            ash[t] = expf(g_e1[(size_t)e * H1 + h] - sm[h]) * sinv[h];
        }
        __syncthreads();
        for (int j = 0; j < cnt; j++) {
            const float* hr = g_h1 + (size_t)ssrc[j] * HD1 + t;
            float a0 = ash[j * 4 + 0], a1 = ash[j * 4 + 1];
            float a2 = ash[j * 4 + 2], a3 = ash[j * 4 + 3];
            acc0 = fmaf(hr[0],      a0, acc0);
            acc1 = fmaf(hr[D1],     a1, acc1);
            acc2 = fmaf(hr[2 * D1], a2, acc2);
            acc3 = fmaf(hr[3 * D1], a3, acc3);
        }
        __syncthreads();
    }
    // relu + bias, write bf16 split (GEMM2 input)
    __nv_bfloat16* oa = (__nv_bfloat16*)g_o1a;
    __nv_bfloat16* ob = (__nv_bfloat16*)g_o1b;
    size_t rb = (size_t)n * HD1;
#pragma unroll
    for (int h = 0; h < H1; h++) {
        float v;
        if (h == 0) v = acc0; else if (h == 1) v = acc1; else if (h == 2) v = acc2; else v = acc3;
        int c = h * D1 + t;
        v = fmaxf(v + b1[c], 0.f);
        __nv_bfloat16 hi = __float2bfloat16(v);
        oa[rb + c] = hi;
        ob[rb + c] = __float2bfloat16(v - __bfloat162float(hi));
    }
}

// ---------------- softmax + aggregate, layer 2 (H=1) ----------------
__global__ __launch_bounds__(256) void k_agg2(const float* __restrict__ b2) {
    int n = blockIdx.x, t = threadIdx.x;
    int start = g_rowptr[n], deg = g_rowptr[n + 1] - start;
    __shared__ float sm, sinv;
    __shared__ float ash[64];
    __shared__ int   ssrc[64];

    if (t < 32) {
        float lm = -1e30f;
        for (int j = t; j < deg; j += 32) lm = fmaxf(lm, g_e2[g_elist[start + j]]);
#pragma unroll
        for (int o = 16; o; o >>= 1) lm = fmaxf(lm, __shfl_xor_sync(0xffffffffu, lm, o));
        float ls = 0.f;
        for (int j = t; j < deg; j += 32) ls += expf(g_e2[g_elist[start + j]] - lm);
#pragma unroll
        for (int o = 16; o; o >>= 1) ls += __shfl_xor_sync(0xffffffffu, ls, o);
        if (t == 0) { sm = lm; sinv = 1.f / (ls + 1e-16f); }
    }
    __syncthreads();

    float acc = 0.f;
    for (int c0 = 0; c0 < deg; c0 += 64) {
        int cnt = min(64, deg - c0);
        if (t < cnt) {
            int e = g_elist[start + c0 + t];
            ssrc[t] = g_src[e];
            ash[t] = expf(g_e2[e] - sm) * sinv;
        }
        __syncthreads();
        for (int j = 0; j < cnt; j++)
            acc = fmaf(g_h2[(size_t)ssrc[j] * D2 + t], ash[j], acc);
        __syncthreads();
    }
    g_out2[(size_t)n * D2 + t] = fmaxf(acc + b2[t], 0.f);
}

// ---------------- pool + FC ----------------
__device__ __forceinline__ int lower_bound_batch(const int* b32, int is64, int key) {
    int lo = 0, hi = N_NODES;
    while (lo < hi) {
        int mid = (lo + hi) >> 1;
        int v = is64 ? b32[2 * mid] : b32[mid];
        if (v < key) lo = mid + 1; else hi = mid;
    }
    return lo;
}
__global__ __launch_bounds__(256) void k_pool_fc(
    const int* __restrict__ batch32, const int* __restrict__ ei32,
    const float* __restrict__ fcW, const float* __restrict__ fcb,
    float* __restrict__ out)
{
    int g = blockIdx.x, t = threadIdx.x;
    __shared__ int s_lo, s_hi;
    __shared__ float pooled[D2];
    if (t == 0) {
        int is64 = detect_i64(ei32);
        s_lo = lower_bound_batch(batch32, is64, g);
        s_hi = lower_bound_batch(batch32, is64, g + 1);
    }
    __syncthreads();
    int lo = s_lo, hi = s_hi;
    float s = 0.f;
    for (int n = lo; n < hi; n++) s += g_out2[(size_t)n * D2 + t];
    float cnt = (float)(hi - lo);
    pooled[t] = s / fmaxf(cnt, 1.f);
    __syncthreads();
    if (t < OUT_DIM) {
        float acc = fcb[t];
        for (int d = 0; d < D2; d++) acc = fmaf(pooled[d], fcW[d * OUT_DIM + t], acc);
        out[g * OUT_DIM + t] = acc;
    }
}

// ---------------- launch ----------------
extern "C" void kernel_launch(void* const* d_in, const int* in_sizes, int n_in,
                              void* d_out, int out_size)
{
    const float* x      = (const float*)d_in[0];
    const int*   ei32   = (const int*)  d_in[1];
    const int*   bat32  = (const int*)  d_in[2];
    const float* W1     = (const float*)d_in[3];
    const float* a_src1 = (const float*)d_in[4];
    const float* a_dst1 = (const float*)d_in[5];
    const float* b1     = (const float*)d_in[6];
    const float* W2     = (const float*)d_in[7];
    const float* a_src2 = (const float*)d_in[8];
    const float* a_dst2 = (const float*)d_in[9];
    const float* b2     = (const float*)d_in[10];
    const float* fcW    = (const float*)d_in[11];
    const float* fcb    = (const float*)d_in[12];
    float* out = (float*)d_out;

    uint4 *xs1, *xs2, *w1a, *w1b, *o1a, *o1b, *w2a, *w2b;
    float *h1, *h2;
    cudaGetSymbolAddress((void**)&xs1, g_xs1);
    cudaGetSymbolAddress((void**)&xs2, g_xs2);
    cudaGetSymbolAddress((void**)&w1a, g_w1a);
    cudaGetSymbolAddress((void**)&w1b, g_w1b);
    cudaGetSymbolAddress((void**)&o1a, g_o1a);
    cudaGetSymbolAddress((void**)&o1b, g_o1b);
    cudaGetSymbolAddress((void**)&w2a, g_w2a);
    cudaGetSymbolAddress((void**)&w2b, g_w2b);
    cudaGetSymbolAddress((void**)&h1,  g_h1);
    cudaGetSymbolAddress((void**)&h2,  g_h2);

    cudaFuncSetAttribute(k_mma<4, HD1>,  cudaFuncAttributeMaxDynamicSharedMemorySize, GM_SMEM);
    cudaFuncSetAttribute(k_mma<32, D2>, cudaFuncAttributeMaxDynamicSharedMemorySize, GM_SMEM);

    const int MT = (N_NODES + 127) / 128;   // 391

    k_split_x <<<(N_NODES * K1PAD + 255) / 256, 256>>>(x);
    k_split_w1<<<(HD1 * K1PAD + 255) / 256, 256>>>(W1);
    k_split_w2<<<(D2 * HD1 + 255) / 256, 256>>>(W2);

    // GEMM1: h1 = x @ W1   (grid: 8 col tiles x 391 row tiles)
    k_mma<4, HD1><<<dim3(HD1 / 128, MT), 256, GM_SMEM>>>(xs1, xs2, w1a, w1b, h1, N_NODES);

    k_al1<<<N_NODES, 128>>>(a_src1, a_dst1);

    // CSR
    k_zero_deg   <<<(N_NODES + 255) / 256, 256>>>();
    k_prep_edges <<<(E_TOT + 255) / 256, 256>>>(ei32);
    k_scan       <<<1, 1024>>>();
    k_init_cursor<<<(N_NODES + 255) / 256, 256>>>();
    k_scatter    <<<(E_TOT + 255) / 256, 256>>>();

    k_edge1<<<(E_TOT + 255) / 256, 256>>>();
    k_agg1 <<<N_NODES, 256>>>(b1);

    // GEMM2: h2 = out1 @ W2  (grid: 2 x 391)
    k_mma<32, D2><<<dim3(D2 / 128, MT), 256, GM_SMEM>>>(o1a, o1b, w2a, w2b, h2, N_NODES);

    k_al2<<<(N_NODES + 7) / 8, 256>>>(a_src2, a_dst2);
    k_edge2<<<(E_TOT + 255) / 256, 256>>>();
    k_agg2 <<<N_NODES, 256>>>(b2);

    k_pool_fc<<<N_GRAPHS, 256>>>(bat32, ei32, fcW, fcb, out);
}

// round 4
// speedup vs baseline: 2.0789x; 1.3089x over previous
#include <cuda_runtime.h>
#include <cuda_bf16.h>
#include <math.h>
#include <stdint.h>

// ---------------- problem constants ----------------
#define N_NODES 50000
#define N_EDGES 200000
#define E_TOT   (N_EDGES + N_NODES)   // 250000
#define F0      74
#define K1PAD   96                    // F0 padded to 3*32
#define H1      4
#define D1      256
#define HD1     (H1 * D1)             // 1024
#define D2      256
#define N_GRAPHS 256
#define OUT_DIM 12
#define NEG_SLOPE 0.2f

// ---------------- scratch ----------------
__device__ float g_h1  [(size_t)N_NODES * HD1];
__device__ float g_h2  [(size_t)N_NODES * D2];
__device__ float g_out2[(size_t)N_NODES * D2];
__device__ float g_als1[N_NODES * H1];
__device__ float g_ald1[N_NODES * H1];
__device__ float g_den1[N_NODES * H1];
__device__ float g_als2[N_NODES];
__device__ float g_ald2[N_NODES];
__device__ float g_den2[N_NODES];
__device__ float g_e1[(size_t)E_TOT * H1];   // exp(leaky(logit))
__device__ float g_e2[E_TOT];
__device__ int   g_deg[N_NODES];
__device__ int   g_rowptr[N_NODES + 1];
__device__ int   g_cursor[N_NODES];
__device__ int   g_elist[E_TOT];
__device__ int   g_src[E_TOT];
__device__ int   g_dst[E_TOT];

// bf16 split operands (K-major rows, 16B-aligned)
__device__ uint4 g_xs1 [(size_t)N_NODES * K1PAD / 8];
__device__ uint4 g_xs2 [(size_t)N_NODES * K1PAD / 8];
__device__ uint4 g_w1a [(size_t)HD1 * K1PAD / 8];     // W1^T [1024,96]
__device__ uint4 g_w1b [(size_t)HD1 * K1PAD / 8];
__device__ uint4 g_o1a [(size_t)N_NODES * HD1 / 8];   // relu(out1) split
__device__ uint4 g_o1b [(size_t)N_NODES * HD1 / 8];
__device__ uint4 g_w2a [(size_t)D2 * HD1 / 8];        // W2^T [256,1024]
__device__ uint4 g_w2b [(size_t)D2 * HD1 / 8];

// ---------------- PTX helpers ----------------
__device__ __forceinline__ uint32_t smem_u32(const void* p) {
    uint32_t a;
    asm("{ .reg .u64 t; cvta.to.shared.u64 t, %1; cvt.u32.u64 %0, t; }" : "=r"(a) : "l"(p));
    return a;
}
#define CP_ASYNC16(dst, src) \
    asm volatile("cp.async.cg.shared.global [%0], [%1], 16;" :: "r"(dst), "l"(src))
#define CP_COMMIT() asm volatile("cp.async.commit_group;" ::: "memory")
#define CP_WAIT0()  asm volatile("cp.async.wait_group 0;" ::: "memory")
#define CP_WAIT1()  asm volatile("cp.async.wait_group 1;" ::: "memory")

#define LDSM_X4(r, addr) \
    asm volatile("ldmatrix.sync.aligned.m8n8.x4.shared.b16 {%0,%1,%2,%3}, [%4];" \
        : "=r"((r)[0]), "=r"((r)[1]), "=r"((r)[2]), "=r"((r)[3]) : "r"(addr))

#define MMA_BF16(d, a, b) \
    asm volatile("mma.sync.aligned.m16n8k16.row.col.f32.bf16.bf16.f32 " \
        "{%0,%1,%2,%3}, {%4,%5,%6,%7}, {%8,%9}, {%0,%1,%2,%3};" \
        : "+f"((d)[0]), "+f"((d)[1]), "+f"((d)[2]), "+f"((d)[3]) \
        : "r"((a)[0]), "r"((a)[1]), "r"((a)[2]), "r"((a)[3]), "r"((b)[0]), "r"((b)[1]))

// ---------------- misc ----------------
__device__ __forceinline__ int detect_i64(const int* p) {
    return (p[1] | p[3] | p[5] | p[7]) == 0;
}
__device__ __forceinline__ float leaky(float v) { return v >= 0.f ? v : NEG_SLOPE * v; }

// ---------------- zero init (deg, logits, denominators) ----------------
__global__ void k_zero() {
    int i = blockIdx.x * blockDim.x + threadIdx.x;
    if (i < N_NODES) {
        g_deg[i]  = 0;
        g_als2[i] = 0.f; g_ald2[i] = 0.f; g_den2[i] = 0.f;
    }
    if (i < N_NODES * H1) {
        g_als1[i] = 0.f; g_ald1[i] = 0.f; g_den1[i] = 0.f;
    }
}

// ---------------- bf16 split prep ----------------
__global__ void k_split_x(const float* __restrict__ x) {
    int i = blockIdx.x * blockDim.x + threadIdx.x;
    if (i >= N_NODES * K1PAD) return;
    int r = i / K1PAD, c = i - r * K1PAD;
    float v = (c < F0) ? x[(size_t)r * F0 + c] : 0.f;
    __nv_bfloat16 hi = __float2bfloat16(v);
    ((__nv_bfloat16*)g_xs1)[i] = hi;
    ((__nv_bfloat16*)g_xs2)[i] = __float2bfloat16(v - __bfloat162float(hi));
}
__global__ void k_split_w1(const float* __restrict__ W1) {
    int i = blockIdx.x * blockDim.x + threadIdx.x;   // [1024 n][96 k]
    if (i >= HD1 * K1PAD) return;
    int n = i / K1PAD, k = i - n * K1PAD;
    float v = (k < F0) ? W1[(size_t)k * HD1 + n] : 0.f;
    __nv_bfloat16 hi = __float2bfloat16(v);
    ((__nv_bfloat16*)g_w1a)[i] = hi;
    ((__nv_bfloat16*)g_w1b)[i] = __float2bfloat16(v - __bfloat162float(hi));
}
__global__ void k_split_w2(const float* __restrict__ W2) {
    int i = blockIdx.x * blockDim.x + threadIdx.x;   // [256 n][1024 k]
    if (i >= D2 * HD1) return;
    int n = i >> 10, k = i & 1023;
    float v = W2[(size_t)k * D2 + n];
    __nv_bfloat16 hi = __float2bfloat16(v);
    ((__nv_bfloat16*)g_w2a)[i] = hi;
    ((__nv_bfloat16*)g_w2b)[i] = __float2bfloat16(v - __bfloat162float(hi));
}

// ---------------- mma.sync GEMM + fused attention-logit epilogue ----------
// C[M, gridDim.x*128] = A[M,K] @ B[N,K]^T, bf16 3-term compensated.
// CTA 128x128, BK=32, 8 warps (2x4) of 64x32, 2-stage cp.async.
// Epilogue: als[r*ALS+head] += sum_c C[r,c]*asrc[c] (atomics), same for ald.
#define SMSTRIDE 80
#define TILE_B   (128 * SMSTRIDE)
#define GM_SMEM  (2 * 4 * TILE_B)            // 81920 B

template <int KT, int LDC, int ALS>          // K = KT*32
__global__ __launch_bounds__(256, 2) void k_mma(
    const uint4* __restrict__ A1, const uint4* __restrict__ A2,
    const uint4* __restrict__ B1, const uint4* __restrict__ B2,
    float* __restrict__ C, int M,
    const float* __restrict__ asrc, const float* __restrict__ adst,
    float* __restrict__ als, float* __restrict__ ald)
{
    extern __shared__ char smem[];
    const uint32_t sbase = smem_u32(smem);
    const int tid = threadIdx.x, lane = tid & 31, wid = tid >> 5;
    const int wm = wid & 1, wn = wid >> 1;
    const int m0 = blockIdx.y * 128, n0 = blockIdx.x * 128;
    const int KW = KT * 4;

    float acc[4][4][4];
#pragma unroll
    for (int a = 0; a < 4; a++)
#pragma unroll
        for (int b = 0; b < 4; b++)
#pragma unroll
            for (int c = 0; c < 4; c++) acc[a][b][c] = 0.f;

    auto load_stage = [&](int ki, int s) {
        uint32_t sb = sbase + s * (4 * TILE_B);
#pragma unroll
        for (int i = 0; i < 2; i++) {
            int idx = tid + i * 256;
            int row = idx >> 2, ch = idx & 3;
            uint32_t soff = row * SMSTRIDE + ch * 16;
            int ar = min(m0 + row, M - 1);
            size_t ga = (size_t)ar * KW + ki * 4 + ch;
            size_t gb = (size_t)(n0 + row) * KW + ki * 4 + ch;
            CP_ASYNC16(sb + soff,              A1 + ga);
            CP_ASYNC16(sb + TILE_B + soff,     A2 + ga);
            CP_ASYNC16(sb + 2 * TILE_B + soff, B1 + gb);
            CP_ASYNC16(sb + 3 * TILE_B + soff, B2 + gb);
        }
        CP_COMMIT();
    };

    load_stage(0, 0);

    for (int ki = 0; ki < KT; ki++) {
        if (ki + 1 < KT) load_stage(ki + 1, (ki + 1) & 1);
        if (ki + 1 < KT) CP_WAIT1(); else CP_WAIT0();
        __syncthreads();

        uint32_t sb  = sbase + (ki & 1) * (4 * TILE_B);
        uint32_t a1b = sb, a2b = sb + TILE_B, b1b = sb + 2 * TILE_B, b2b = sb + 3 * TILE_B;

#pragma unroll
        for (int k16 = 0; k16 < 2; k16++) {
            uint32_t bf1[8], bf2[8];
#pragma unroll
            for (int g = 0; g < 2; g++) {
                int nrow = wn * 32 + g * 16 + (lane & 7) + ((lane >> 4) << 3);
                int kb   = k16 * 32 + (((lane >> 3) & 1) << 4);
                uint32_t ao = nrow * SMSTRIDE + kb;
                LDSM_X4(&bf1[g * 4], b1b + ao);
                LDSM_X4(&bf2[g * 4], b2b + ao);
            }
#pragma unroll
            for (int mt = 0; mt < 4; mt++) {
                int arow = wm * 64 + mt * 16 + (lane & 7) + (((lane >> 3) & 1) << 3);
                int kb   = k16 * 32 + ((lane >> 4) << 4);
                uint32_t ao = arow * SMSTRIDE + kb;
                uint32_t af[4];
                LDSM_X4(af, a1b + ao);
#pragma unroll
                for (int nt = 0; nt < 4; nt++) MMA_BF16(acc[mt][nt], af, &bf1[nt * 2]);
#pragma unroll
                for (int nt = 0; nt < 4; nt++) MMA_BF16(acc[mt][nt], af, &bf2[nt * 2]);
                LDSM_X4(af, a2b + ao);
#pragma unroll
                for (int nt = 0; nt < 4; nt++) MMA_BF16(acc[mt][nt], af, &bf1[nt * 2]);
            }
        }
        __syncthreads();
    }

    // ---- attention-vector values for this thread's 8 columns ----
    float av_s[4][2], av_d[4][2];
#pragma unroll
    for (int nt = 0; nt < 4; nt++) {
        int c = n0 + wn * 32 + nt * 8 + (lane & 3) * 2;
        av_s[nt][0] = asrc[c];     av_s[nt][1] = asrc[c + 1];
        av_d[nt][0] = adst[c];     av_d[nt][1] = adst[c + 1];
    }
    const int head = (ALS == 1) ? 0 : (n0 >> 8);

    // ---- store C + fused logit reduction ----
#pragma unroll
    for (int mt = 0; mt < 4; mt++) {
        int r = m0 + wm * 64 + mt * 16 + (lane >> 2);
        float s0 = 0.f, s1 = 0.f, d0 = 0.f, d1 = 0.f;
#pragma unroll
        for (int nt = 0; nt < 4; nt++) {
            int c = n0 + wn * 32 + nt * 8 + (lane & 3) * 2;
            if (r < M)
                *(float2*)&C[(size_t)r * LDC + c] = make_float2(acc[mt][nt][0], acc[mt][nt][1]);
            if (r + 8 < M)
                *(float2*)&C[(size_t)(r + 8) * LDC + c] = make_float2(acc[mt][nt][2], acc[mt][nt][3]);
            s0 = fmaf(acc[mt][nt][0], av_s[nt][0], fmaf(acc[mt][nt][1], av_s[nt][1], s0));
            s1 = fmaf(acc[mt][nt][2], av_s[nt][0], fmaf(acc[mt][nt][3], av_s[nt][1], s1));
            d0 = fmaf(acc[mt][nt][0], av_d[nt][0], fmaf(acc[mt][nt][1], av_d[nt][1], d0));
            d1 = fmaf(acc[mt][nt][2], av_d[nt][0], fmaf(acc[mt][nt][3], av_d[nt][1], d1));
        }
        // reduce across quad (lane&3)
        s0 += __shfl_xor_sync(0xffffffffu, s0, 1); s0 += __shfl_xor_sync(0xffffffffu, s0, 2);
        s1 += __shfl_xor_sync(0xffffffffu, s1, 1); s1 += __shfl_xor_sync(0xffffffffu, s1, 2);
        d0 += __shfl_xor_sync(0xffffffffu, d0, 1); d0 += __shfl_xor_sync(0xffffffffu, d0, 2);
        d1 += __shfl_xor_sync(0xffffffffu, d1, 1); d1 += __shfl_xor_sync(0xffffffffu, d1, 2);
        if ((lane & 3) == 0) {
            if (r < M) {
                atomicAdd(&als[(size_t)r * ALS + head], s0);
                atomicAdd(&ald[(size_t)r * ALS + head], d0);
            }
            if (r + 8 < M) {
                atomicAdd(&als[(size_t)(r + 8) * ALS + head], s1);
                atomicAdd(&ald[(size_t)(r + 8) * ALS + head], d1);
            }
        }
    }
}

// ---------------- CSR build ----------------
__global__ void k_prep_edges(const int* ei32) {
    int e = blockIdx.x * blockDim.x + threadIdx.x;
    if (e >= E_TOT) return;
    int is64 = detect_i64(ei32);
    int s, d;
    if (e < N_EDGES) {
        s = is64 ? ei32[2 * (size_t)e]             : ei32[e];
        d = is64 ? ei32[2 * ((size_t)N_EDGES + e)] : ei32[N_EDGES + e];
    } else {
        s = d = e - N_EDGES;
    }
    g_src[e] = s;
    g_dst[e] = d;
    atomicAdd(&g_deg[d], 1);
}
__global__ void k_scan() {
    __shared__ int sums[1024];
    int t = threadIdx.x;
    const int CH = (N_NODES + 1023) / 1024;
    int b = t * CH, e = min(b + CH, N_NODES);
    int s = 0;
    for (int i = b; i < e; i++) s += g_deg[i];
    sums[t] = s;
    __syncthreads();
    for (int off = 1; off < 1024; off <<= 1) {
        int v = (t >= off) ? sums[t - off] : 0;
        __syncthreads();
        sums[t] += v;
        __syncthreads();
    }
    int run = sums[t] - s;
    for (int i = b; i < e; i++) { g_rowptr[i] = run; run += g_deg[i]; }
    if (t == 1023) g_rowptr[N_NODES] = sums[1023];
}
__global__ void k_init_cursor() {
    int i = blockIdx.x * blockDim.x + threadIdx.x;
    if (i < N_NODES) g_cursor[i] = g_rowptr[i];
}
__global__ void k_scatter() {
    int e = blockIdx.x * blockDim.x + threadIdx.x;
    if (e >= E_TOT) return;
    int p = atomicAdd(&g_cursor[g_dst[e]], 1);
    g_elist[p] = e;
}

// ---------------- edge kernels: exp(logit) + denominator atomics ----------
__global__ void k_edge1() {
    int e = blockIdx.x * blockDim.x + threadIdx.x;
    if (e >= E_TOT) return;
    int s = g_src[e], d = g_dst[e];
    const float4 as = *(const float4*)(g_als1 + s * 4);
    const float4 ad = *(const float4*)(g_ald1 + d * 4);
    float4 o;
    o.x = expf(leaky(as.x + ad.x));
    o.y = expf(leaky(as.y + ad.y));
    o.z = expf(leaky(as.z + ad.z));
    o.w = expf(leaky(as.w + ad.w));
    *(float4*)(g_e1 + (size_t)e * 4) = o;
    atomicAdd(&g_den1[d * 4 + 0], o.x);
    atomicAdd(&g_den1[d * 4 + 1], o.y);
    atomicAdd(&g_den1[d * 4 + 2], o.z);
    atomicAdd(&g_den1[d * 4 + 3], o.w);
}
__global__ void k_edge2() {
    int e = blockIdx.x * blockDim.x + threadIdx.x;
    if (e >= E_TOT) return;
    int d = g_dst[e];
    float v = expf(leaky(g_als2[g_src[e]] + g_ald2[d]));
    g_e2[e] = v;
    atomicAdd(&g_den2[d], v);
}

// ---------------- aggregate layer 1 (single gather pass) ----------------
__global__ __launch_bounds__(256) void k_agg1(const float* __restrict__ b1) {
    int n = blockIdx.x, t = threadIdx.x;
    int start = g_rowptr[n], deg = g_rowptr[n + 1] - start;
    __shared__ float ash[64 * H1];
    __shared__ int   ssrc[64];

    const float4 den = *(const float4*)(g_den1 + n * 4);
    float4 inv;
    inv.x = 1.f / (den.x + 1e-16f);
    inv.y = 1.f / (den.y + 1e-16f);
    inv.z = 1.f / (den.z + 1e-16f);
    inv.w = 1.f / (den.w + 1e-16f);

    float acc0 = 0.f, acc1 = 0.f, acc2 = 0.f, acc3 = 0.f;
    for (int c0 = 0; c0 < deg; c0 += 64) {
        int cnt = min(64, deg - c0);
        if (t < cnt) {
            int e = g_elist[start + c0 + t];
            ssrc[t] = g_src[e];
            float4 ex = *(const float4*)(g_e1 + (size_t)e * 4);
            ash[t * 4 + 0] = ex.x * inv.x;
            ash[t * 4 + 1] = ex.y * inv.y;
            ash[t * 4 + 2] = ex.z * inv.z;
            ash[t * 4 + 3] = ex.w * inv.w;
        }
        __syncthreads();
#pragma unroll 2
        for (int j = 0; j < cnt; j++) {
            const float* hr = g_h1 + (size_t)ssrc[j] * HD1 + t;
            float a0 = ash[j * 4 + 0], a1 = ash[j * 4 + 1];
            float a2 = ash[j * 4 + 2], a3 = ash[j * 4 + 3];
            acc0 = fmaf(__ldg(hr),          a0, acc0);
            acc1 = fmaf(__ldg(hr + D1),     a1, acc1);
            acc2 = fmaf(__ldg(hr + 2 * D1), a2, acc2);
            acc3 = fmaf(__ldg(hr + 3 * D1), a3, acc3);
        }
        __syncthreads();
    }
    // relu + bias, write bf16 split (GEMM2 input)
    __nv_bfloat16* oa = (__nv_bfloat16*)g_o1a;
    __nv_bfloat16* ob = (__nv_bfloat16*)g_o1b;
    size_t rb = (size_t)n * HD1;
#pragma unroll
    for (int h = 0; h < H1; h++) {
        float v;
        if (h == 0) v = acc0; else if (h == 1) v = acc1; else if (h == 2) v = acc2; else v = acc3;
        int c = h * D1 + t;
        v = fmaxf(v + b1[c], 0.f);
        __nv_bfloat16 hi = __float2bfloat16(v);
        oa[rb + c] = hi;
        ob[rb + c] = __float2bfloat16(v - __bfloat162float(hi));
    }
}

// ---------------- aggregate layer 2 ----------------
__global__ __launch_bounds__(256) void k_agg2(const float* __restrict__ b2) {
    int n = blockIdx.x, t = threadIdx.x;
    int start = g_rowptr[n], deg = g_rowptr[n + 1] - start;
    __shared__ float ash[64];
    __shared__ int   ssrc[64];

    float inv = 1.f / (g_den2[n] + 1e-16f);

    float acc = 0.f;
    for (int c0 = 0; c0 < deg; c0 += 64) {
        int cnt = min(64, deg - c0);
        if (t < cnt) {
            int e = g_elist[start + c0 + t];
            ssrc[t] = g_src[e];
            ash[t] = g_e2[e] * inv;
        }
        __syncthreads();
#pragma unroll 2
        for (int j = 0; j < cnt; j++)
            acc = fmaf(__ldg(g_h2 + (size_t)ssrc[j] * D2 + t), ash[j], acc);
        __syncthreads();
    }
    g_out2[(size_t)n * D2 + t] = fmaxf(acc + b2[t], 0.f);
}

// ---------------- pool + FC ----------------
__device__ __forceinline__ int lower_bound_batch(const int* b32, int is64, int key) {
    int lo = 0, hi = N_NODES;
    while (lo < hi) {
        int mid = (lo + hi) >> 1;
        int v = is64 ? b32[2 * mid] : b32[mid];
        if (v < key) lo = mid + 1; else hi = mid;
    }
    return lo;
}
__global__ __launch_bounds__(256) void k_pool_fc(
    const int* __restrict__ batch32, const int* __restrict__ ei32,
    const float* __restrict__ fcW, const float* __restrict__ fcb,
    float* __restrict__ out)
{
    int g = blockIdx.x, t = threadIdx.x;
    __shared__ int s_lo, s_hi;
    __shared__ float pooled[D2];
    if (t == 0) {
        int is64 = detect_i64(ei32);
        s_lo = lower_bound_batch(batch32, is64, g);
        s_hi = lower_bound_batch(batch32, is64, g + 1);
    }
    __syncthreads();
    int lo = s_lo, hi = s_hi;
    float s = 0.f;
    for (int n = lo; n < hi; n++) s += g_out2[(size_t)n * D2 + t];
    float cnt = (float)(hi - lo);
    pooled[t] = s / fmaxf(cnt, 1.f);
    __syncthreads();
    if (t < OUT_DIM) {
        float acc = fcb[t];
        for (int d = 0; d < D2; d++) acc = fmaf(pooled[d], fcW[d * OUT_DIM + t], acc);
        out[g * OUT_DIM + t] = acc;
    }
}

// ---------------- launch ----------------
extern "C" void kernel_launch(void* const* d_in, const int* in_sizes, int n_in,
                              void* d_out, int out_size)
{
    const float* x      = (const float*)d_in[0];
    const int*   ei32   = (const int*)  d_in[1];
    const int*   bat32  = (const int*)  d_in[2];
    const float* W1     = (const float*)d_in[3];
    const float* a_src1 = (const float*)d_in[4];
    const float* a_dst1 = (const float*)d_in[5];
    const float* b1     = (const float*)d_in[6];
    const float* W2     = (const float*)d_in[7];
    const float* a_src2 = (const float*)d_in[8];
    const float* a_dst2 = (const float*)d_in[9];
    const float* b2     = (const float*)d_in[10];
    const float* fcW    = (const float*)d_in[11];
    const float* fcb    = (const float*)d_in[12];
    float* out = (float*)d_out;

    uint4 *xs1, *xs2, *w1a, *w1b, *o1a, *o1b, *w2a, *w2b;
    float *h1, *h2, *als1, *ald1, *als2, *ald2;
    cudaGetSymbolAddress((void**)&xs1, g_xs1);
    cudaGetSymbolAddress((void**)&xs2, g_xs2);
    cudaGetSymbolAddress((void**)&w1a, g_w1a);
    cudaGetSymbolAddress((void**)&w1b, g_w1b);
    cudaGetSymbolAddress((void**)&o1a, g_o1a);
    cudaGetSymbolAddress((void**)&o1b, g_o1b);
    cudaGetSymbolAddress((void**)&w2a, g_w2a);
    cudaGetSymbolAddress((void**)&w2b, g_w2b);
    cudaGetSymbolAddress((void**)&h1,  g_h1);
    cudaGetSymbolAddress((void**)&h2,  g_h2);
    cudaGetSymbolAddress((void**)&als1, g_als1);
    cudaGetSymbolAddress((void**)&ald1, g_ald1);
    cudaGetSymbolAddress((void**)&als2, g_als2);
    cudaGetSymbolAddress((void**)&ald2, g_ald2);

    cudaFuncSetAttribute(k_mma<3, HD1, H1>, cudaFuncAttributeMaxDynamicSharedMemorySize, GM_SMEM);
    cudaFuncSetAttribute(k_mma<32, D2, 1>,  cudaFuncAttributeMaxDynamicSharedMemorySize, GM_SMEM);

    const int MT = (N_NODES + 127) / 128;   // 391

    k_zero    <<<(N_NODES * H1 + 255) / 256, 256>>>();
    k_split_x <<<(N_NODES * K1PAD + 255) / 256, 256>>>(x);
    k_split_w1<<<(HD1 * K1PAD + 255) / 256, 256>>>(W1);
    k_split_w2<<<(D2 * HD1 + 255) / 256, 256>>>(W2);

    // GEMM1: h1 = x @ W1 + fused als1/ald1
    k_mma<3, HD1, H1><<<dim3(HD1 / 128, MT), 256, GM_SMEM>>>(
        xs1, xs2, w1a, w1b, h1, N_NODES, a_src1, a_dst1, als1, ald1);

    // CSR
    k_prep_edges <<<(E_TOT + 255) / 256, 256>>>(ei32);
    k_scan       <<<1, 1024>>>();
    k_init_cursor<<<(N_NODES + 255) / 256, 256>>>();
    k_scatter    <<<(E_TOT + 255) / 256, 256>>>();

    k_edge1<<<(E_TOT + 255) / 256, 256>>>();
    k_agg1 <<<N_NODES, 256>>>(b1);

    // GEMM2: h2 = out1 @ W2 + fused als2/ald2
    k_mma<32, D2, 1><<<dim3(D2 / 128, MT), 256, GM_SMEM>>>(
        o1a, o1b, w2a, w2b, h2, N_NODES, a_src2, a_dst2, als2, ald2);

    k_edge2<<<(E_TOT + 255) / 256, 256>>>();
    k_agg2 <<<N_NODES, 256>>>(b2);

    k_pool_fc<<<N_GRAPHS, 256>>>(bat32, ei32, fcW, fcb, out);
}

// round 5
// speedup vs baseline: 2.4971x; 1.2012x over previous
#include <cuda_runtime.h>
#include <cuda_bf16.h>
#include <cuda_fp16.h>
#include <math.h>
#include <stdint.h>

// ---------------- problem constants ----------------
#define N_NODES 50000
#define N_EDGES 200000
#define E_TOT   (N_EDGES + N_NODES)   // 250000
#define F0      74
#define K1PAD   96                    // F0 padded to 3*32
#define H1      4
#define D1      256
#define HD1     (H1 * D1)             // 1024
#define D2      256
#define N_GRAPHS 256
#define OUT_DIM 12
#define NEG_SLOPE 0.2f

// ---------------- scratch ----------------
__device__ __half g_h1 [(size_t)N_NODES * HD1];   // layer1 features (fp16)
__device__ __half g_h2 [(size_t)N_NODES * D2];    // layer2 features (fp16)
__device__ float  g_out2[(size_t)N_NODES * D2];   // layer2 output (fp32, post relu)
__device__ float g_als1[N_NODES * H1];
__device__ float g_ald1[N_NODES * H1];
__device__ float g_den1[N_NODES * H1];
__device__ float g_als2[N_NODES];
__device__ float g_ald2[N_NODES];
__device__ float g_den2[N_NODES];
__device__ float g_e1[(size_t)E_TOT * H1];   // exp(leaky(logit))
__device__ float g_e2[E_TOT];
__device__ int   g_deg[N_NODES];
__device__ int   g_rowptr[N_NODES + 1];
__device__ int   g_cursor[N_NODES];
__device__ int   g_elist[E_TOT];
__device__ int   g_src[E_TOT];
__device__ int   g_dst[E_TOT];

// GEMM operands (K-major rows, 16B-aligned)
__device__ uint4 g_xs1[(size_t)N_NODES * K1PAD / 8];   // bf16 hi
__device__ uint4 g_xs2[(size_t)N_NODES * K1PAD / 8];   // bf16 lo
__device__ uint4 g_w1a[(size_t)HD1 * K1PAD / 8];       // W1^T bf16 hi
__device__ uint4 g_w1b[(size_t)HD1 * K1PAD / 8];       // W1^T bf16 lo
__device__ uint4 g_o1 [(size_t)N_NODES * HD1 / 8];     // relu(out1) fp16
__device__ uint4 g_w2a[(size_t)D2 * HD1 / 8];          // W2^T fp16 hi
__device__ uint4 g_w2b[(size_t)D2 * HD1 / 8];          // W2^T fp16 lo

// ---------------- PTX helpers ----------------
__device__ __forceinline__ uint32_t smem_u32(const void* p) {
    uint32_t a;
    asm("{ .reg .u64 t; cvta.to.shared.u64 t, %1; cvt.u32.u64 %0, t; }" : "=r"(a) : "l"(p));
    return a;
}
#define CP_ASYNC16(dst, src) \
    asm volatile("cp.async.cg.shared.global [%0], [%1], 16;" :: "r"(dst), "l"(src))
#define CP_COMMIT() asm volatile("cp.async.commit_group;" ::: "memory")
#define CP_WAIT0()  asm volatile("cp.async.wait_group 0;" ::: "memory")
#define CP_WAIT1()  asm volatile("cp.async.wait_group 1;" ::: "memory")

#define LDSM_X4(r, addr) \
    asm volatile("ldmatrix.sync.aligned.m8n8.x4.shared.b16 {%0,%1,%2,%3}, [%4];" \
        : "=r"((r)[0]), "=r"((r)[1]), "=r"((r)[2]), "=r"((r)[3]) : "r"(addr))

#define MMA_BF16(d, a, b) \
    asm volatile("mma.sync.aligned.m16n8k16.row.col.f32.bf16.bf16.f32 " \
        "{%0,%1,%2,%3}, {%4,%5,%6,%7}, {%8,%9}, {%0,%1,%2,%3};" \
        : "+f"((d)[0]), "+f"((d)[1]), "+f"((d)[2]), "+f"((d)[3]) \
        : "r"((a)[0]), "r"((a)[1]), "r"((a)[2]), "r"((a)[3]), "r"((b)[0]), "r"((b)[1]))

#define MMA_FP16(d, a, b) \
    asm volatile("mma.sync.aligned.m16n8k16.row.col.f32.f16.f16.f32 " \
        "{%0,%1,%2,%3}, {%4,%5,%6,%7}, {%8,%9}, {%0,%1,%2,%3};" \
        : "+f"((d)[0]), "+f"((d)[1]), "+f"((d)[2]), "+f"((d)[3]) \
        : "r"((a)[0]), "r"((a)[1]), "r"((a)[2]), "r"((a)[3]), "r"((b)[0]), "r"((b)[1]))

// ---------------- misc ----------------
__device__ __forceinline__ int detect_i64(const int* p) {
    return (p[1] | p[3] | p[5] | p[7]) == 0;
}
__device__ __forceinline__ float leaky(float v) { return v >= 0.f ? v : NEG_SLOPE * v; }

// ---------------- zero init ----------------
__global__ void k_zero() {
    int i = blockIdx.x * blockDim.x + threadIdx.x;
    if (i < N_NODES) {
        g_deg[i]  = 0;
        g_als2[i] = 0.f; g_ald2[i] = 0.f; g_den2[i] = 0.f;
    }
    if (i < N_NODES * H1) {
        g_als1[i] = 0.f; g_ald1[i] = 0.f; g_den1[i] = 0.f;
    }
}

// ---------------- operand prep ----------------
__global__ void k_split_x(const float* __restrict__ x) {
    int i = blockIdx.x * blockDim.x + threadIdx.x;
    if (i >= N_NODES * K1PAD) return;
    int r = i / K1PAD, c = i - r * K1PAD;
    float v = (c < F0) ? x[(size_t)r * F0 + c] : 0.f;
    __nv_bfloat16 hi = __float2bfloat16(v);
    ((__nv_bfloat16*)g_xs1)[i] = hi;
    ((__nv_bfloat16*)g_xs2)[i] = __float2bfloat16(v - __bfloat162float(hi));
}
__global__ void k_split_w1(const float* __restrict__ W1) {
    int i = blockIdx.x * blockDim.x + threadIdx.x;   // [1024 n][96 k]
    if (i >= HD1 * K1PAD) return;
    int n = i / K1PAD, k = i - n * K1PAD;
    float v = (k < F0) ? W1[(size_t)k * HD1 + n] : 0.f;
    __nv_bfloat16 hi = __float2bfloat16(v);
    ((__nv_bfloat16*)g_w1a)[i] = hi;
    ((__nv_bfloat16*)g_w1b)[i] = __float2bfloat16(v - __bfloat162float(hi));
}
__global__ void k_split_w2(const float* __restrict__ W2) {
    int i = blockIdx.x * blockDim.x + threadIdx.x;   // [256 n][1024 k]
    if (i >= D2 * HD1) return;
    int n = i >> 10, k = i & 1023;
    float v = W2[(size_t)k * D2 + n];
    __half hi = __float2half_rn(v);
    ((__half*)g_w2a)[i] = hi;
    ((__half*)g_w2b)[i] = __float2half_rn(v - __half2float(hi));
}

// ---------------- GEMM common bits ----------------
#define SMSTRIDE 80
#define TILE_B   (128 * SMSTRIDE)
#define GM1_SMEM (2 * 4 * TILE_B)            // 81920 B (A1,A2,B1,B2)
#define GM2_SMEM (2 * 3 * TILE_B)            // 61440 B (A,B1,B2)

// Epilogue helper: store fp16 C, fused logit reduction into als/ald
template <int LDC, int ALS>
__device__ __forceinline__ void gemm_epilogue(
    float acc[4][4][4], __half* C, int M, int m0, int n0, int wm, int wn, int lane,
    const float* __restrict__ asrc, const float* __restrict__ adst,
    float* __restrict__ als, float* __restrict__ ald)
{
    float av_s[4][2], av_d[4][2];
#pragma unroll
    for (int nt = 0; nt < 4; nt++) {
        int c = n0 + wn * 32 + nt * 8 + (lane & 3) * 2;
        av_s[nt][0] = asrc[c]; av_s[nt][1] = asrc[c + 1];
        av_d[nt][0] = adst[c]; av_d[nt][1] = adst[c + 1];
    }
    const int head = (ALS == 1) ? 0 : (n0 >> 8);

#pragma unroll
    for (int mt = 0; mt < 4; mt++) {
        int r = m0 + wm * 64 + mt * 16 + (lane >> 2);
        float s0 = 0.f, s1 = 0.f, d0 = 0.f, d1 = 0.f;
#pragma unroll
        for (int nt = 0; nt < 4; nt++) {
            int c = n0 + wn * 32 + nt * 8 + (lane & 3) * 2;
            if (r < M)
                *(__half2*)&C[(size_t)r * LDC + c] = __floats2half2_rn(acc[mt][nt][0], acc[mt][nt][1]);
            if (r + 8 < M)
                *(__half2*)&C[(size_t)(r + 8) * LDC + c] = __floats2half2_rn(acc[mt][nt][2], acc[mt][nt][3]);
            s0 = fmaf(acc[mt][nt][0], av_s[nt][0], fmaf(acc[mt][nt][1], av_s[nt][1], s0));
            s1 = fmaf(acc[mt][nt][2], av_s[nt][0], fmaf(acc[mt][nt][3], av_s[nt][1], s1));
            d0 = fmaf(acc[mt][nt][0], av_d[nt][0], fmaf(acc[mt][nt][1], av_d[nt][1], d0));
            d1 = fmaf(acc[mt][nt][2], av_d[nt][0], fmaf(acc[mt][nt][3], av_d[nt][1], d1));
        }
        s0 += __shfl_xor_sync(0xffffffffu, s0, 1); s0 += __shfl_xor_sync(0xffffffffu, s0, 2);
        s1 += __shfl_xor_sync(0xffffffffu, s1, 1); s1 += __shfl_xor_sync(0xffffffffu, s1, 2);
        d0 += __shfl_xor_sync(0xffffffffu, d0, 1); d0 += __shfl_xor_sync(0xffffffffu, d0, 2);
        d1 += __shfl_xor_sync(0xffffffffu, d1, 1); d1 += __shfl_xor_sync(0xffffffffu, d1, 2);
        if ((lane & 3) == 0) {
            if (r < M) {
                atomicAdd(&als[(size_t)r * ALS + head], s0);
                atomicAdd(&ald[(size_t)r * ALS + head], d0);
            }
            if (r + 8 < M) {
                atomicAdd(&als[(size_t)(r + 8) * ALS + head], s1);
                atomicAdd(&ald[(size_t)(r + 8) * ALS + head], d1);
            }
        }
    }
}

// ---------------- GEMM1: bf16 3-term compensated ----------------
template <int KT, int LDC, int ALS>
__global__ __launch_bounds__(256, 2) void k_mma3(
    const uint4* __restrict__ A1, const uint4* __restrict__ A2,
    const uint4* __restrict__ B1, const uint4* __restrict__ B2,
    __half* __restrict__ C, int M,
    const float* __restrict__ asrc, const float* __restrict__ adst,
    float* __restrict__ als, float* __restrict__ ald)
{
    extern __shared__ char smem[];
    const uint32_t sbase = smem_u32(smem);
    const int tid = threadIdx.x, lane = tid & 31, wid = tid >> 5;
    const int wm = wid & 1, wn = wid >> 1;
    const int m0 = blockIdx.y * 128, n0 = blockIdx.x * 128;
    const int KW = KT * 4;

    float acc[4][4][4];
#pragma unroll
    for (int a = 0; a < 4; a++)
#pragma unroll
        for (int b = 0; b < 4; b++)
#pragma unroll
            for (int c = 0; c < 4; c++) acc[a][b][c] = 0.f;

    auto load_stage = [&](int ki, int s) {
        uint32_t sb = sbase + s * (4 * TILE_B);
#pragma unroll
        for (int i = 0; i < 2; i++) {
            int idx = tid + i * 256;
            int row = idx >> 2, ch = idx & 3;
            uint32_t soff = row * SMSTRIDE + ch * 16;
            int ar = min(m0 + row, M - 1);
            size_t ga = (size_t)ar * KW + ki * 4 + ch;
            size_t gb = (size_t)(n0 + row) * KW + ki * 4 + ch;
            CP_ASYNC16(sb + soff,              A1 + ga);
            CP_ASYNC16(sb + TILE_B + soff,     A2 + ga);
            CP_ASYNC16(sb + 2 * TILE_B + soff, B1 + gb);
            CP_ASYNC16(sb + 3 * TILE_B + soff, B2 + gb);
        }
        CP_COMMIT();
    };

    load_stage(0, 0);

    for (int ki = 0; ki < KT; ki++) {
        if (ki + 1 < KT) load_stage(ki + 1, (ki + 1) & 1);
        if (ki + 1 < KT) CP_WAIT1(); else CP_WAIT0();
        __syncthreads();

        uint32_t sb  = sbase + (ki & 1) * (4 * TILE_B);
        uint32_t a1b = sb, a2b = sb + TILE_B, b1b = sb + 2 * TILE_B, b2b = sb + 3 * TILE_B;

#pragma unroll
        for (int k16 = 0; k16 < 2; k16++) {
            uint32_t bf1[8], bf2[8];
#pragma unroll
            for (int g = 0; g < 2; g++) {
                int nrow = wn * 32 + g * 16 + (lane & 7) + ((lane >> 4) << 3);
                int kb   = k16 * 32 + (((lane >> 3) & 1) << 4);
                uint32_t ao = nrow * SMSTRIDE + kb;
                LDSM_X4(&bf1[g * 4], b1b + ao);
                LDSM_X4(&bf2[g * 4], b2b + ao);
            }
#pragma unroll
            for (int mt = 0; mt < 4; mt++) {
                int arow = wm * 64 + mt * 16 + (lane & 7) + (((lane >> 3) & 1) << 3);
                int kb   = k16 * 32 + ((lane >> 4) << 4);
                uint32_t ao = arow * SMSTRIDE + kb;
                uint32_t af[4];
                LDSM_X4(af, a1b + ao);
#pragma unroll
                for (int nt = 0; nt < 4; nt++) MMA_BF16(acc[mt][nt], af, &bf1[nt * 2]);
#pragma unroll
                for (int nt = 0; nt < 4; nt++) MMA_BF16(acc[mt][nt], af, &bf2[nt * 2]);
                LDSM_X4(af, a2b + ao);
#pragma unroll
                for (int nt = 0; nt < 4; nt++) MMA_BF16(acc[mt][nt], af, &bf1[nt * 2]);
            }
        }
        __syncthreads();
    }
    gemm_epilogue<LDC, ALS>(acc, C, M, m0, n0, wm, wn, lane, asrc, adst, als, ald);
}

// ---------------- GEMM2: fp16, A single + B 2-term split ----------------
template <int KT, int LDC, int ALS>
__global__ __launch_bounds__(256, 2) void k_mma2(
    const uint4* __restrict__ A1,
    const uint4* __restrict__ B1, const uint4* __restrict__ B2,
    __half* __restrict__ C, int M,
    const float* __restrict__ asrc, const float* __restrict__ adst,
    float* __restrict__ als, float* __restrict__ ald)
{
    extern __shared__ char smem[];
    const uint32_t sbase = smem_u32(smem);
    const int tid = threadIdx.x, lane = tid & 31, wid = tid >> 5;
    const int wm = wid & 1, wn = wid >> 1;
    const int m0 = blockIdx.y * 128, n0 = blockIdx.x * 128;
    const int KW = KT * 4;

    float acc[4][4][4];
#pragma unroll
    for (int a = 0; a < 4; a++)
#pragma unroll
        for (int b = 0; b < 4; b++)
#pragma unroll
            for (int c = 0; c < 4; c++) acc[a][b][c] = 0.f;

    auto load_stage = [&](int ki, int s) {
        uint32_t sb = sbase + s * (3 * TILE_B);
#pragma unroll
        for (int i = 0; i < 2; i++) {
            int idx = tid + i * 256;
            int row = idx >> 2, ch = idx & 3;
            uint32_t soff = row * SMSTRIDE + ch * 16;
            int ar = min(m0 + row, M - 1);
            size_t ga = (size_t)ar * KW + ki * 4 + ch;
            size_t gb = (size_t)(n0 + row) * KW + ki * 4 + ch;
            CP_ASYNC16(sb + soff,              A1 + ga);
            CP_ASYNC16(sb + TILE_B + soff,     B1 + gb);
            CP_ASYNC16(sb + 2 * TILE_B + soff, B2 + gb);
        }
        CP_COMMIT();
    };

    load_stage(0, 0);

    for (int ki = 0; ki < KT; ki++) {
        if (ki + 1 < KT) load_stage(ki + 1, (ki + 1) & 1);
        if (ki + 1 < KT) CP_WAIT1(); else CP_WAIT0();
        __syncthreads();

        uint32_t sb  = sbase + (ki & 1) * (3 * TILE_B);
        uint32_t a1b = sb, b1b = sb + TILE_B, b2b = sb + 2 * TILE_B;

#pragma unroll
        for (int k16 = 0; k16 < 2; k16++) {
            uint32_t bf1[8], bf2[8];
#pragma unroll
            for (int g = 0; g < 2; g++) {
                int nrow = wn * 32 + g * 16 + (lane & 7) + ((lane >> 4) << 3);
                int kb   = k16 * 32 + (((lane >> 3) & 1) << 4);
                uint32_t ao = nrow * SMSTRIDE + kb;
                LDSM_X4(&bf1[g * 4], b1b + ao);
                LDSM_X4(&bf2[g * 4], b2b + ao);
            }
#pragma unroll
            for (int mt = 0; mt < 4; mt++) {
                int arow = wm * 64 + mt * 16 + (lane & 7) + (((lane >> 3) & 1) << 3);
                int kb   = k16 * 32 + ((lane >> 4) << 4);
                uint32_t ao = arow * SMSTRIDE + kb;
                uint32_t af[4];
                LDSM_X4(af, a1b + ao);
#pragma unroll
                for (int nt = 0; nt < 4; nt++) MMA_FP16(acc[mt][nt], af, &bf1[nt * 2]);
#pragma unroll
                for (int nt = 0; nt < 4; nt++) MMA_FP16(acc[mt][nt], af, &bf2[nt * 2]);
            }
        }
        __syncthreads();
    }
    gemm_epilogue<LDC, ALS>(acc, C, M, m0, n0, wm, wn, lane, asrc, adst, als, ald);
}

// ---------------- CSR build ----------------
__global__ void k_prep_edges(const int* ei32) {
    int e = blockIdx.x * blockDim.x + threadIdx.x;
    if (e >= E_TOT) return;
    int is64 = detect_i64(ei32);
    int s, d;
    if (e < N_EDGES) {
        s = is64 ? ei32[2 * (size_t)e]             : ei32[e];
        d = is64 ? ei32[2 * ((size_t)N_EDGES + e)] : ei32[N_EDGES + e];
    } else {
        s = d = e - N_EDGES;
    }
    g_src[e] = s;
    g_dst[e] = d;
    atomicAdd(&g_deg[d], 1);
}
__global__ void k_scan() {
    __shared__ int sums[1024];
    int t = threadIdx.x;
    const int CH = (N_NODES + 1023) / 1024;
    int b = t * CH, e = min(b + CH, N_NODES);
    int s = 0;
    for (int i = b; i < e; i++) s += g_deg[i];
    sums[t] = s;
    __syncthreads();
    for (int off = 1; off < 1024; off <<= 1) {
        int v = (t >= off) ? sums[t - off] : 0;
        __syncthreads();
        sums[t] += v;
        __syncthreads();
    }
    int run = sums[t] - s;
    for (int i = b; i < e; i++) { g_rowptr[i] = run; run += g_deg[i]; }
    if (t == 1023) g_rowptr[N_NODES] = sums[1023];
}
__global__ void k_init_cursor() {
    int i = blockIdx.x * blockDim.x + threadIdx.x;
    if (i < N_NODES) g_cursor[i] = g_rowptr[i];
}
__global__ void k_scatter() {
    int e = blockIdx.x * blockDim.x + threadIdx.x;
    if (e >= E_TOT) return;
    int p = atomicAdd(&g_cursor[g_dst[e]], 1);
    g_elist[p] = e;
}

// ---------------- edge kernels ----------------
__global__ void k_edge1() {
    int e = blockIdx.x * blockDim.x + threadIdx.x;
    if (e >= E_TOT) return;
    int s = g_src[e], d = g_dst[e];
    const float4 as = *(const float4*)(g_als1 + s * 4);
    const float4 ad = *(const float4*)(g_ald1 + d * 4);
    float4 o;
    o.x = expf(leaky(as.x + ad.x));
    o.y = expf(leaky(as.y + ad.y));
    o.z = expf(leaky(as.z + ad.z));
    o.w = expf(leaky(as.w + ad.w));
    *(float4*)(g_e1 + (size_t)e * 4) = o;
    atomicAdd(&g_den1[d * 4 + 0], o.x);
    atomicAdd(&g_den1[d * 4 + 1], o.y);
    atomicAdd(&g_den1[d * 4 + 2], o.z);
    atomicAdd(&g_den1[d * 4 + 3], o.w);
}
__global__ void k_edge2() {
    int e = blockIdx.x * blockDim.x + threadIdx.x;
    if (e >= E_TOT) return;
    int d = g_dst[e];
    float v = expf(leaky(g_als2[g_src[e]] + g_ald2[d]));
    g_e2[e] = v;
    atomicAdd(&g_den2[d], v);
}

// ---------------- aggregate layer 1 ----------------
__global__ __launch_bounds__(256) void k_agg1(const float* __restrict__ b1) {
    int n = blockIdx.x, t = threadIdx.x;
    int start = g_rowptr[n], deg = g_rowptr[n + 1] - start;
    __shared__ float ash[64 * H1];
    __shared__ int   ssrc[64];

    const float4 den = *(const float4*)(g_den1 + n * 4);
    float4 inv;
    inv.x = 1.f / (den.x + 1e-16f);
    inv.y = 1.f / (den.y + 1e-16f);
    inv.z = 1.f / (den.z + 1e-16f);
    inv.w = 1.f / (den.w + 1e-16f);

    float acc0 = 0.f, acc1 = 0.f, acc2 = 0.f, acc3 = 0.f;
    for (int c0 = 0; c0 < deg; c0 += 64) {
        int cnt = min(64, deg - c0);
        if (t < cnt) {
            int e = g_elist[start + c0 + t];
            ssrc[t] = g_src[e];
            float4 ex = *(const float4*)(g_e1 + (size_t)e * 4);
            ash[t * 4 + 0] = ex.x * inv.x;
            ash[t * 4 + 1] = ex.y * inv.y;
            ash[t * 4 + 2] = ex.z * inv.z;
            ash[t * 4 + 3] = ex.w * inv.w;
        }
        __syncthreads();
#pragma unroll 2
        for (int j = 0; j < cnt; j++) {
            const __half* hr = g_h1 + (size_t)ssrc[j] * HD1 + t;
            float a0 = ash[j * 4 + 0], a1 = ash[j * 4 + 1];
            float a2 = ash[j * 4 + 2], a3 = ash[j * 4 + 3];
            acc0 = fmaf(__half2float(__ldg(hr)),          a0, acc0);
            acc1 = fmaf(__half2float(__ldg(hr + D1)),     a1, acc1);
            acc2 = fmaf(__half2float(__ldg(hr + 2 * D1)), a2, acc2);
            acc3 = fmaf(__half2float(__ldg(hr + 3 * D1)), a3, acc3);
        }
        __syncthreads();
    }
    // relu + bias, write fp16 (GEMM2 A operand)
    __half* oa = (__half*)g_o1;
    size_t rb = (size_t)n * HD1;
#pragma unroll
    for (int h = 0; h < H1; h++) {
        float v;
        if (h == 0) v = acc0; else if (h == 1) v = acc1; else if (h == 2) v = acc2; else v = acc3;
        int c = h * D1 + t;
        v = fmaxf(v + b1[c], 0.f);
        oa[rb + c] = __float2half_rn(v);
    }
}

// ---------------- aggregate layer 2 ----------------
__global__ __launch_bounds__(256) void k_agg2(const float* __restrict__ b2) {
    int n = blockIdx.x, t = threadIdx.x;
    int start = g_rowptr[n], deg = g_rowptr[n + 1] - start;
    __shared__ float ash[64];
    __shared__ int   ssrc[64];

    float inv = 1.f / (g_den2[n] + 1e-16f);

    float acc = 0.f;
    for (int c0 = 0; c0 < deg; c0 += 64) {
        int cnt = min(64, deg - c0);
        if (t < cnt) {
            int e = g_elist[start + c0 + t];
            ssrc[t] = g_src[e];
            ash[t] = g_e2[e] * inv;
        }
        __syncthreads();
#pragma unroll 2
        for (int j = 0; j < cnt; j++)
            acc = fmaf(__half2float(__ldg(g_h2 + (size_t)ssrc[j] * D2 + t)), ash[j], acc);
        __syncthreads();
    }
    g_out2[(size_t)n * D2 + t] = fmaxf(acc + b2[t], 0.f);
}

// ---------------- pool + FC ----------------
__device__ __forceinline__ int lower_bound_batch(const int* b32, int is64, int key) {
    int lo = 0, hi = N_NODES;
    while (lo < hi) {
        int mid = (lo + hi) >> 1;
        int v = is64 ? b32[2 * mid] : b32[mid];
        if (v < key) lo = mid + 1; else hi = mid;
    }
    return lo;
}
__global__ __launch_bounds__(256) void k_pool_fc(
    const int* __restrict__ batch32, const int* __restrict__ ei32,
    const float* __restrict__ fcW, const float* __restrict__ fcb,
    float* __restrict__ out)
{
    int g = blockIdx.x, t = threadIdx.x;
    __shared__ int s_lo, s_hi;
    __shared__ float pooled[D2];
    if (t == 0) {
        int is64 = detect_i64(ei32);
        s_lo = lower_bound_batch(batch32, is64, g);
        s_hi = lower_bound_batch(batch32, is64, g + 1);
    }
    __syncthreads();
    int lo = s_lo, hi = s_hi;
    float s = 0.f;
    for (int n = lo; n < hi; n++) s += g_out2[(size_t)n * D2 + t];
    float cnt = (float)(hi - lo);
    pooled[t] = s / fmaxf(cnt, 1.f);
    __syncthreads();
    if (t < OUT_DIM) {
        float acc = fcb[t];
        for (int d = 0; d < D2; d++) acc = fmaf(pooled[d], fcW[d * OUT_DIM + t], acc);
        out[g * OUT_DIM + t] = acc;
    }
}

// ---------------- launch ----------------
extern "C" void kernel_launch(void* const* d_in, const int* in_sizes, int n_in,
                              void* d_out, int out_size)
{
    const float* x      = (const float*)d_in[0];
    const int*   ei32   = (const int*)  d_in[1];
    const int*   bat32  = (const int*)  d_in[2];
    const float* W1     = (const float*)d_in[3];
    const float* a_src1 = (const float*)d_in[4];
    const float* a_dst1 = (const float*)d_in[5];
    const float* b1     = (const float*)d_in[6];
    const float* W2     = (const float*)d_in[7];
    const float* a_src2 = (const float*)d_in[8];
    const float* a_dst2 = (const float*)d_in[9];
    const float* b2     = (const float*)d_in[10];
    const float* fcW    = (const float*)d_in[11];
    const float* fcb    = (const float*)d_in[12];
    float* out = (float*)d_out;

    uint4 *xs1, *xs2, *w1a, *w1b, *o1, *w2a, *w2b;
    __half *h1, *h2;
    float *als1, *ald1, *als2, *ald2;
    cudaGetSymbolAddress((void**)&xs1, g_xs1);
    cudaGetSymbolAddress((void**)&xs2, g_xs2);
    cudaGetSymbolAddress((void**)&w1a, g_w1a);
    cudaGetSymbolAddress((void**)&w1b, g_w1b);
    cudaGetSymbolAddress((void**)&o1,  g_o1);
    cudaGetSymbolAddress((void**)&w2a, g_w2a);
    cudaGetSymbolAddress((void**)&w2b, g_w2b);
    cudaGetSymbolAddress((void**)&h1,  g_h1);
    cudaGetSymbolAddress((void**)&h2,  g_h2);
    cudaGetSymbolAddress((void**)&als1, g_als1);
    cudaGetSymbolAddress((void**)&ald1, g_ald1);
    cudaGetSymbolAddress((void**)&als2, g_als2);
    cudaGetSymbolAddress((void**)&ald2, g_ald2);

    cudaFuncSetAttribute(k_mma3<3, HD1, H1>, cudaFuncAttributeMaxDynamicSharedMemorySize, GM1_SMEM);
    cudaFuncSetAttribute(k_mma2<32, D2, 1>,  cudaFuncAttributeMaxDynamicSharedMemorySize, GM2_SMEM);

    const int MT = (N_NODES + 127) / 128;   // 391

    k_zero    <<<(N_NODES * H1 + 255) / 256, 256>>>();
    k_split_x <<<(N_NODES * K1PAD + 255) / 256, 256>>>(x);
    k_split_w1<<<(HD1 * K1PAD + 255) / 256, 256>>>(W1);

    // GEMM1 (launch index 3 for the ncu window): h1 = x @ W1 + fused als1/ald1
    k_mma3<3, HD1, H1><<<dim3(HD1 / 128, MT), 256, GM1_SMEM>>>(
        xs1, xs2, w1a, w1b, h1, N_NODES, a_src1, a_dst1, als1, ald1);

    k_split_w2<<<(D2 * HD1 + 255) / 256, 256>>>(W2);

    // CSR
    k_prep_edges <<<(E_TOT + 255) / 256, 256>>>(ei32);
    k_scan       <<<1, 1024>>>();
    k_init_cursor<<<(N_NODES + 255) / 256, 256>>>();
    k_scatter    <<<(E_TOT + 255) / 256, 256>>>();

    k_edge1<<<(E_TOT + 255) / 256, 256>>>();
    k_agg1 <<<N_NODES, 256>>>(b1);

    // GEMM2: h2 = out1 @ W2 + fused als2/ald2 (fp16 2-term)
    k_mma2<32, D2, 1><<<dim3(D2 / 128, MT), 256, GM2_SMEM>>>(
        o1, w2a, w2b, h2, N_NODES, a_src2, a_dst2, als2, ald2);

    k_edge2<<<(E_TOT + 255) / 256, 256>>>();
    k_agg2 <<<N_NODES, 256>>>(b2);

    k_pool_fc<<<N_GRAPHS, 256>>>(bat32, ei32, fcW, fcb, out);
}

// round 6
// speedup vs baseline: 2.8778x; 1.1525x over previous
#include <cuda_runtime.h>
#include <cuda_fp16.h>
#include <math.h>
#include <stdint.h>

// ---------------- problem constants ----------------
#define N_NODES 50000
#define N_EDGES 200000
#define E_TOT   (N_EDGES + N_NODES)   // 250000
#define F0      74
#define K1PAD   96                    // F0 padded to 3*32
#define H1      4
#define D1      256
#define HD1     (H1 * D1)             // 1024
#define D2      256
#define N_GRAPHS 256
#define OUT_DIM 12
#define NEG_SLOPE 0.2f

// ---------------- scratch ----------------
__device__ __half g_h1 [(size_t)N_NODES * HD1];   // layer1 features (fp16)
__device__ __half g_h2 [(size_t)N_NODES * D2];    // layer2 features (fp16)
__device__ float  g_out2[(size_t)N_NODES * D2];   // layer2 output (fp32, post relu)
__device__ float g_als1[N_NODES * H1];
__device__ float g_ald1[N_NODES * H1];
__device__ float g_den1[N_NODES * H1];
__device__ float g_als2[N_NODES];
__device__ float g_ald2[N_NODES];
__device__ float g_den2[N_NODES];
__device__ float g_e1[(size_t)E_TOT * H1];   // exp(leaky(logit))
__device__ float g_e2[E_TOT];
__device__ int   g_deg[N_NODES];
__device__ int   g_rowptr[N_NODES + 1];
__device__ int   g_cursor[N_NODES];
__device__ int   g_elist[E_TOT];
__device__ int   g_src[E_TOT];
__device__ int   g_dst[E_TOT];

// GEMM operands (fp16, K-major rows, 16B-aligned)
__device__ uint4 g_x16[(size_t)N_NODES * K1PAD / 8];   // x fp16 [50000,96]
__device__ uint4 g_w1a[(size_t)HD1 * K1PAD / 8];       // W1^T fp16 hi [1024,96]
__device__ uint4 g_w1b[(size_t)HD1 * K1PAD / 8];       // W1^T fp16 lo
__device__ uint4 g_o1 [(size_t)N_NODES * HD1 / 8];     // relu(out1) fp16 [50000,1024]
__device__ uint4 g_w2 [(size_t)D2 * HD1 / 8];          // W2^T fp16 [256,1024]

// ---------------- PTX helpers ----------------
__device__ __forceinline__ uint32_t smem_u32(const void* p) {
    uint32_t a;
    asm("{ .reg .u64 t; cvta.to.shared.u64 t, %1; cvt.u32.u64 %0, t; }" : "=r"(a) : "l"(p));
    return a;
}
#define CP_ASYNC16(dst, src) \
    asm volatile("cp.async.cg.shared.global [%0], [%1], 16;" :: "r"(dst), "l"(src))
#define CP_COMMIT() asm volatile("cp.async.commit_group;" ::: "memory")
#define CP_WAIT0()  asm volatile("cp.async.wait_group 0;" ::: "memory")
#define CP_WAIT1()  asm volatile("cp.async.wait_group 1;" ::: "memory")

#define LDSM_X4(r, addr) \
    asm volatile("ldmatrix.sync.aligned.m8n8.x4.shared.b16 {%0,%1,%2,%3}, [%4];" \
        : "=r"((r)[0]), "=r"((r)[1]), "=r"((r)[2]), "=r"((r)[3]) : "r"(addr))

#define MMA_FP16(d, a, b) \
    asm volatile("mma.sync.aligned.m16n8k16.row.col.f32.f16.f16.f32 " \
        "{%0,%1,%2,%3}, {%4,%5,%6,%7}, {%8,%9}, {%0,%1,%2,%3};" \
        : "+f"((d)[0]), "+f"((d)[1]), "+f"((d)[2]), "+f"((d)[3]) \
        : "r"((a)[0]), "r"((a)[1]), "r"((a)[2]), "r"((a)[3]), "r"((b)[0]), "r"((b)[1]))

// ---------------- misc ----------------
__device__ __forceinline__ int detect_i64(const int* p) {
    return (p[1] | p[3] | p[5] | p[7]) == 0;
}
__device__ __forceinline__ float leaky(float v) { return v >= 0.f ? v : NEG_SLOPE * v; }

// ---------------- zero init ----------------
__global__ void k_zero() {
    int i = blockIdx.x * blockDim.x + threadIdx.x;
    if (i < N_NODES) {
        g_deg[i]  = 0;
        g_als2[i] = 0.f; g_ald2[i] = 0.f; g_den2[i] = 0.f;
    }
    if (i < N_NODES * H1) {
        g_als1[i] = 0.f; g_ald1[i] = 0.f; g_den1[i] = 0.f;
    }
}

// ---------------- operand prep ----------------
__global__ void k_prep_x(const float* __restrict__ x) {
    int i = blockIdx.x * blockDim.x + threadIdx.x;
    if (i >= N_NODES * K1PAD) return;
    int r = i / K1PAD, c = i - r * K1PAD;
    float v = (c < F0) ? x[(size_t)r * F0 + c] : 0.f;
    ((__half*)g_x16)[i] = __float2half_rn(v);
}
__global__ void k_prep_w1(const float* __restrict__ W1) {
    int i = blockIdx.x * blockDim.x + threadIdx.x;   // [1024 n][96 k]
    if (i >= HD1 * K1PAD) return;
    int n = i / K1PAD, k = i - n * K1PAD;
    float v = (k < F0) ? W1[(size_t)k * HD1 + n] : 0.f;
    __half hi = __float2half_rn(v);
    ((__half*)g_w1a)[i] = hi;
    ((__half*)g_w1b)[i] = __float2half_rn(v - __half2float(hi));
}
__global__ void k_prep_w2(const float* __restrict__ W2) {
    int i = blockIdx.x * blockDim.x + threadIdx.x;   // [256 n][1024 k]
    if (i >= D2 * HD1) return;
    int n = i >> 10, k = i & 1023;
    ((__half*)g_w2)[i] = __float2half_rn(W2[(size_t)k * D2 + n]);
}

// ---------------- GEMM common ----------------
#define SMSTRIDE 80
#define TILE_B   (128 * SMSTRIDE)

// Epilogue: store fp16 C + fused attention-logit reduction into als/ald
template <int LDC, int ALS>
__device__ __forceinline__ void gemm_epilogue(
    float acc[4][4][4], __half* C, int M, int m0, int n0, int wm, int wn, int lane,
    const float* __restrict__ asrc, const float* __restrict__ adst,
    float* __restrict__ als, float* __restrict__ ald)
{
    float av_s[4][2], av_d[4][2];
#pragma unroll
    for (int nt = 0; nt < 4; nt++) {
        int c = n0 + wn * 32 + nt * 8 + (lane & 3) * 2;
        av_s[nt][0] = asrc[c]; av_s[nt][1] = asrc[c + 1];
        av_d[nt][0] = adst[c]; av_d[nt][1] = adst[c + 1];
    }
    const int head = (ALS == 1) ? 0 : (n0 >> 8);

#pragma unroll
    for (int mt = 0; mt < 4; mt++) {
        int r = m0 + wm * 64 + mt * 16 + (lane >> 2);
        float s0 = 0.f, s1 = 0.f, d0 = 0.f, d1 = 0.f;
#pragma unroll
        for (int nt = 0; nt < 4; nt++) {
            int c = n0 + wn * 32 + nt * 8 + (lane & 3) * 2;
            if (r < M)
                *(__half2*)&C[(size_t)r * LDC + c] = __floats2half2_rn(acc[mt][nt][0], acc[mt][nt][1]);
            if (r + 8 < M)
                *(__half2*)&C[(size_t)(r + 8) * LDC + c] = __floats2half2_rn(acc[mt][nt][2], acc[mt][nt][3]);
            s0 = fmaf(acc[mt][nt][0], av_s[nt][0], fmaf(acc[mt][nt][1], av_s[nt][1], s0));
            s1 = fmaf(acc[mt][nt][2], av_s[nt][0], fmaf(acc[mt][nt][3], av_s[nt][1], s1));
            d0 = fmaf(acc[mt][nt][0], av_d[nt][0], fmaf(acc[mt][nt][1], av_d[nt][1], d0));
            d1 = fmaf(acc[mt][nt][2], av_d[nt][0], fmaf(acc[mt][nt][3], av_d[nt][1], d1));
        }
        s0 += __shfl_xor_sync(0xffffffffu, s0, 1); s0 += __shfl_xor_sync(0xffffffffu, s0, 2);
        s1 += __shfl_xor_sync(0xffffffffu, s1, 1); s1 += __shfl_xor_sync(0xffffffffu, s1, 2);
        d0 += __shfl_xor_sync(0xffffffffu, d0, 1); d0 += __shfl_xor_sync(0xffffffffu, d0, 2);
        d1 += __shfl_xor_sync(0xffffffffu, d1, 1); d1 += __shfl_xor_sync(0xffffffffu, d1, 2);
        if ((lane & 3) == 0) {
            if (r < M) {
                atomicAdd(&als[(size_t)r * ALS + head], s0);
                atomicAdd(&ald[(size_t)r * ALS + head], d0);
            }
            if (r + 8 < M) {
                atomicAdd(&als[(size_t)(r + 8) * ALS + head], s1);
                atomicAdd(&ald[(size_t)(r + 8) * ALS + head], d1);
            }
        }
    }
}

// ---------------- fp16 GEMM: C = A[M,K] @ B[N,K]^T, NB B-terms --------------
// CTA 128x128, BK=32, 8 warps (2x4) of 64x32, 2-stage cp.async.
template <int KT, int LDC, int ALS, int NB>   // K = KT*32
__global__ __launch_bounds__(256, 2) void k_mma(
    const uint4* __restrict__ A1,
    const uint4* __restrict__ B1, const uint4* __restrict__ B2,
    __half* __restrict__ C, int M,
    const float* __restrict__ asrc, const float* __restrict__ adst,
    float* __restrict__ als, float* __restrict__ ald)
{
    extern __shared__ char smem[];
    const uint32_t sbase = smem_u32(smem);
    const int tid = threadIdx.x, lane = tid & 31, wid = tid >> 5;
    const int wm = wid & 1, wn = wid >> 1;
    const int m0 = blockIdx.y * 128, n0 = blockIdx.x * 128;
    const int KW = KT * 4;
    constexpr int NT = 1 + NB;                 // tiles per stage

    float acc[4][4][4];
#pragma unroll
    for (int a = 0; a < 4; a++)
#pragma unroll
        for (int b = 0; b < 4; b++)
#pragma unroll
            for (int c = 0; c < 4; c++) acc[a][b][c] = 0.f;

    auto load_stage = [&](int ki, int s) {
        uint32_t sb = sbase + s * (NT * TILE_B);
#pragma unroll
        for (int i = 0; i < 2; i++) {
            int idx = tid + i * 256;
            int row = idx >> 2, ch = idx & 3;
            uint32_t soff = row * SMSTRIDE + ch * 16;
            int ar = min(m0 + row, M - 1);
            size_t ga = (size_t)ar * KW + ki * 4 + ch;
            size_t gb = (size_t)(n0 + row) * KW + ki * 4 + ch;
            CP_ASYNC16(sb + soff,          A1 + ga);
            CP_ASYNC16(sb + TILE_B + soff, B1 + gb);
            if (NB == 2) CP_ASYNC16(sb + 2 * TILE_B + soff, B2 + gb);
        }
        CP_COMMIT();
    };

    load_stage(0, 0);

    for (int ki = 0; ki < KT; ki++) {
        if (ki + 1 < KT) load_stage(ki + 1, (ki + 1) & 1);
        if (ki + 1 < KT) CP_WAIT1(); else CP_WAIT0();
        __syncthreads();

        uint32_t sb  = sbase + (ki & 1) * (NT * TILE_B);
        uint32_t a1b = sb, b1b = sb + TILE_B, b2b = sb + 2 * TILE_B;

#pragma unroll
        for (int k16 = 0; k16 < 2; k16++) {
            uint32_t bf1[8], bf2[8];
#pragma unroll
            for (int g = 0; g < 2; g++) {
                int nrow = wn * 32 + g * 16 + (lane & 7) + ((lane >> 4) << 3);
                int kb   = k16 * 32 + (((lane >> 3) & 1) << 4);
                uint32_t ao = nrow * SMSTRIDE + kb;
                LDSM_X4(&bf1[g * 4], b1b + ao);
                if (NB == 2) LDSM_X4(&bf2[g * 4], b2b + ao);
            }
#pragma unroll
            for (int mt = 0; mt < 4; mt++) {
                int arow = wm * 64 + mt * 16 + (lane & 7) + (((lane >> 3) & 1) << 3);
                int kb   = k16 * 32 + ((lane >> 4) << 4);
                uint32_t ao = arow * SMSTRIDE + kb;
                uint32_t af[4];
                LDSM_X4(af, a1b + ao);
#pragma unroll
                for (int nt = 0; nt < 4; nt++) MMA_FP16(acc[mt][nt], af, &bf1[nt * 2]);
                if (NB == 2) {
#pragma unroll
                    for (int nt = 0; nt < 4; nt++) MMA_FP16(acc[mt][nt], af, &bf2[nt * 2]);
                }
            }
        }
        __syncthreads();
    }
    gemm_epilogue<LDC, ALS>(acc, C, M, m0, n0, wm, wn, lane, asrc, adst, als, ald);
}

// ---------------- CSR build ----------------
__global__ void k_prep_edges(const int* ei32) {
    int e = blockIdx.x * blockDim.x + threadIdx.x;
    if (e >= E_TOT) return;
    int is64 = detect_i64(ei32);
    int s, d;
    if (e < N_EDGES) {
        s = is64 ? ei32[2 * (size_t)e]             : ei32[e];
        d = is64 ? ei32[2 * ((size_t)N_EDGES + e)] : ei32[N_EDGES + e];
    } else {
        s = d = e - N_EDGES;
    }
    g_src[e] = s;
    g_dst[e] = d;
    atomicAdd(&g_deg[d], 1);
}
__global__ void k_scan() {
    __shared__ int sums[1024];
    int t = threadIdx.x;
    const int CH = (N_NODES + 1023) / 1024;
    int b = t * CH, e = min(b + CH, N_NODES);
    int s = 0;
    for (int i = b; i < e; i++) s += g_deg[i];
    sums[t] = s;
    __syncthreads();
    for (int off = 1; off < 1024; off <<= 1) {
        int v = (t >= off) ? sums[t - off] : 0;
        __syncthreads();
        sums[t] += v;
        __syncthreads();
    }
    int run = sums[t] - s;
    for (int i = b; i < e; i++) { g_rowptr[i] = run; run += g_deg[i]; }
    if (t == 1023) g_rowptr[N_NODES] = sums[1023];
}
__global__ void k_init_cursor() {
    int i = blockIdx.x * blockDim.x + threadIdx.x;
    if (i < N_NODES) g_cursor[i] = g_rowptr[i];
}
__global__ void k_scatter() {
    int e = blockIdx.x * blockDim.x + threadIdx.x;
    if (e >= E_TOT) return;
    int p = atomicAdd(&g_cursor[g_dst[e]], 1);
    g_elist[p] = e;
}

// ---------------- edge kernels ----------------
__global__ void k_edge1() {
    int e = blockIdx.x * blockDim.x + threadIdx.x;
    if (e >= E_TOT) return;
    int s = g_src[e], d = g_dst[e];
    const float4 as = *(const float4*)(g_als1 + s * 4);
    const float4 ad = *(const float4*)(g_ald1 + d * 4);
    float4 o;
    o.x = expf(leaky(as.x + ad.x));
    o.y = expf(leaky(as.y + ad.y));
    o.z = expf(leaky(as.z + ad.z));
    o.w = expf(leaky(as.w + ad.w));
    *(float4*)(g_e1 + (size_t)e * 4) = o;
    atomicAdd(&g_den1[d * 4 + 0], o.x);
    atomicAdd(&g_den1[d * 4 + 1], o.y);
    atomicAdd(&g_den1[d * 4 + 2], o.z);
    atomicAdd(&g_den1[d * 4 + 3], o.w);
}
__global__ void k_edge2() {
    int e = blockIdx.x * blockDim.x + threadIdx.x;
    if (e >= E_TOT) return;
    int d = g_dst[e];
    float v = expf(leaky(g_als2[g_src[e]] + g_ald2[d]));
    g_e2[e] = v;
    atomicAdd(&g_den2[d], v);
}

// ---------------- aggregate layer 1 (half2 gather) ----------------
// thread t owns cols {2t, 2t+1} (head t>>7) and {512+2t, 512+2t+1} (head 2+(t>>7))
__global__ __launch_bounds__(256) void k_agg1(const float* __restrict__ b1) {
    int n = blockIdx.x, t = threadIdx.x;
    int start = g_rowptr[n], deg = g_rowptr[n + 1] - start;
    __shared__ float ash[64 * H1];
    __shared__ int   ssrc[64];

    const float4 den = *(const float4*)(g_den1 + n * 4);
    float4 inv;
    inv.x = 1.f / (den.x + 1e-16f);
    inv.y = 1.f / (den.y + 1e-16f);
    inv.z = 1.f / (den.z + 1e-16f);
    inv.w = 1.f / (den.w + 1e-16f);

    const int hA = t >> 7;          // 0 or 1
    const int hB = 2 + hA;          // 2 or 3

    float2 accA = make_float2(0.f, 0.f), accB = make_float2(0.f, 0.f);
    for (int c0 = 0; c0 < deg; c0 += 64) {
        int cnt = min(64, deg - c0);
        if (t < cnt) {
            int e = g_elist[start + c0 + t];
            ssrc[t] = g_src[e];
            float4 ex = *(const float4*)(g_e1 + (size_t)e * 4);
            ash[t * 4 + 0] = ex.x * inv.x;
            ash[t * 4 + 1] = ex.y * inv.y;
            ash[t * 4 + 2] = ex.z * inv.z;
            ash[t * 4 + 3] = ex.w * inv.w;
        }
        __syncthreads();
#pragma unroll 2
        for (int j = 0; j < cnt; j++) {
            const __half2* hr = (const __half2*)(g_h1 + (size_t)ssrc[j] * HD1);
            float aA = ash[j * 4 + hA], aB = ash[j * 4 + hB];
            float2 vA = __half22float2(__ldg(hr + t));
            float2 vB = __half22float2(__ldg(hr + 256 + t));
            accA.x = fmaf(vA.x, aA, accA.x);
            accA.y = fmaf(vA.y, aA, accA.y);
            accB.x = fmaf(vB.x, aB, accB.x);
            accB.y = fmaf(vB.y, aB, accB.y);
        }
        __syncthreads();
    }
    // relu + bias, write fp16 (GEMM2 A operand)
    __half2* oa = (__half2*)((__half*)g_o1 + (size_t)n * HD1);
    int cA = 2 * t, cB = 512 + 2 * t;
    float2 vA, vB;
    vA.x = fmaxf(accA.x + b1[cA],     0.f);
    vA.y = fmaxf(accA.y + b1[cA + 1], 0.f);
    vB.x = fmaxf(accB.x + b1[cB],     0.f);
    vB.y = fmaxf(accB.y + b1[cB + 1], 0.f);
    oa[t]       = __floats2half2_rn(vA.x, vA.y);
    oa[256 + t] = __floats2half2_rn(vB.x, vB.y);
}

// ---------------- aggregate layer 2 ----------------
__global__ __launch_bounds__(256) void k_agg2(const float* __restrict__ b2) {
    int n = blockIdx.x, t = threadIdx.x;
    int start = g_rowptr[n], deg = g_rowptr[n + 1] - start;
    __shared__ float ash[64];
    __shared__ int   ssrc[64];

    float inv = 1.f / (g_den2[n] + 1e-16f);

    float acc = 0.f;
    for (int c0 = 0; c0 < deg; c0 += 64) {
        int cnt = min(64, deg - c0);
        if (t < cnt) {
            int e = g_elist[start + c0 + t];
            ssrc[t] = g_src[e];
            ash[t] = g_e2[e] * inv;
        }
        __syncthreads();
#pragma unroll 2
        for (int j = 0; j < cnt; j++)
            acc = fmaf(__half2float(__ldg(g_h2 + (size_t)ssrc[j] * D2 + t)), ash[j], acc);
        __syncthreads();
    }
    g_out2[(size_t)n * D2 + t] = fmaxf(acc + b2[t], 0.f);
}

// ---------------- pool + FC ----------------
__device__ __forceinline__ int lower_bound_batch(const int* b32, int is64, int key) {
    int lo = 0, hi = N_NODES;
    while (lo < hi) {
        int mid = (lo + hi) >> 1;
        int v = is64 ? b32[2 * mid] : b32[mid];
        if (v < key) lo = mid + 1; else hi = mid;
    }
    return lo;
}
__global__ __launch_bounds__(256) void k_pool_fc(
    const int* __restrict__ batch32, const int* __restrict__ ei32,
    const float* __restrict__ fcW, const float* __restrict__ fcb,
    float* __restrict__ out)
{
    int g = blockIdx.x, t = threadIdx.x;
    __shared__ int s_lo, s_hi;
    __shared__ float pooled[D2];
    if (t == 0) {
        int is64 = detect_i64(ei32);
        s_lo = lower_bound_batch(batch32, is64, g);
        s_hi = lower_bound_batch(batch32, is64, g + 1);
    }
    __syncthreads();
    int lo = s_lo, hi = s_hi;
    float s = 0.f;
    for (int n = lo; n < hi; n++) s += g_out2[(size_t)n * D2 + t];
    float cnt = (float)(hi - lo);
    pooled[t] = s / fmaxf(cnt, 1.f);
    __syncthreads();
    if (t < OUT_DIM) {
        float acc = fcb[t];
        for (int d = 0; d < D2; d++) acc = fmaf(pooled[d], fcW[d * OUT_DIM + t], acc);
        out[g * OUT_DIM + t] = acc;
    }
}

// ---------------- launch ----------------
extern "C" void kernel_launch(void* const* d_in, const int* in_sizes, int n_in,
                              void* d_out, int out_size)
{
    const float* x      = (const float*)d_in[0];
    const int*   ei32   = (const int*)  d_in[1];
    const int*   bat32  = (const int*)  d_in[2];
    const float* W1     = (const float*)d_in[3];
    const float* a_src1 = (const float*)d_in[4];
    const float* a_dst1 = (const float*)d_in[5];
    const float* b1     = (const float*)d_in[6];
    const float* W2     = (const float*)d_in[7];
    const float* a_src2 = (const float*)d_in[8];
    const float* a_dst2 = (const float*)d_in[9];
    const float* b2     = (const float*)d_in[10];
    const float* fcW    = (const float*)d_in[11];
    const float* fcb    = (const float*)d_in[12];
    float* out = (float*)d_out;

    uint4 *x16, *w1a, *w1b, *o1, *w2;
    __half *h1, *h2;
    float *als1, *ald1, *als2, *ald2;
    cudaGetSymbolAddress((void**)&x16, g_x16);
    cudaGetSymbolAddress((void**)&w1a, g_w1a);
    cudaGetSymbolAddress((void**)&w1b, g_w1b);
    cudaGetSymbolAddress((void**)&o1,  g_o1);
    cudaGetSymbolAddress((void**)&w2,  g_w2);
    cudaGetSymbolAddress((void**)&h1,  g_h1);
    cudaGetSymbolAddress((void**)&h2,  g_h2);
    cudaGetSymbolAddress((void**)&als1, g_als1);
    cudaGetSymbolAddress((void**)&ald1, g_ald1);
    cudaGetSymbolAddress((void**)&als2, g_als2);
    cudaGetSymbolAddress((void**)&ald2, g_ald2);

    const int SM1 = 2 * 3 * TILE_B;   // GEMM1: A,B1,B2 x 2 stages = 61440
    const int SM2 = 2 * 2 * TILE_B;   // GEMM2: A,B x 2 stages = 40960
    cudaFuncSetAttribute(k_mma<3, HD1, H1, 2>, cudaFuncAttributeMaxDynamicSharedMemorySize, SM1);
    cudaFuncSetAttribute(k_mma<32, D2, 1, 1>,  cudaFuncAttributeMaxDynamicSharedMemorySize, SM2);

    const int MT = (N_NODES + 127) / 128;   // 391

    k_zero   <<<(N_NODES * H1 + 255) / 256, 256>>>();
    k_prep_x <<<(N_NODES * K1PAD + 255) / 256, 256>>>(x);
    k_prep_w1<<<(HD1 * K1PAD + 255) / 256, 256>>>(W1);

    // GEMM1 (launch slot 3 for ncu): h1 = x @ W1 + fused als1/ald1 (fp16, W1 2-term)
    k_mma<3, HD1, H1, 2><<<dim3(HD1 / 128, MT), 256, SM1>>>(
        x16, w1a, w1b, h1, N_NODES, a_src1, a_dst1, als1, ald1);

    k_prep_w2<<<(D2 * HD1 + 255) / 256, 256>>>(W2);

    // CSR
    k_prep_edges <<<(E_TOT + 255) / 256, 256>>>(ei32);
    k_scan       <<<1, 1024>>>();
    k_init_cursor<<<(N_NODES + 255) / 256, 256>>>();
    k_scatter    <<<(E_TOT + 255) / 256, 256>>>();

    k_edge1<<<(E_TOT + 255) / 256, 256>>>();
    k_agg1 <<<N_NODES, 256>>>(b1);

    // GEMM2: h2 = out1 @ W2 + fused als2/ald2 (fp16 single-term)
    k_mma<32, D2, 1, 1><<<dim3(D2 / 128, MT), 256, SM2>>>(
        o1, w2, w2, h2, N_NODES, a_src2, a_dst2, als2, ald2);

    k_edge2<<<(E_TOT + 255) / 256, 256>>>();
    k_agg2 <<<N_NODES, 256>>>(b2);

    k_pool_fc<<<N_GRAPHS, 256>>>(bat32, ei32, fcW, fcb, out);
}

// round 7
// speedup vs baseline: 3.5641x; 1.2385x over previous
#include <cuda_runtime.h>
#include <cuda_fp16.h>
#include <math.h>
#include <stdint.h>

// ---------------- problem constants ----------------
#define N_NODES 50000
#define N_EDGES 200000
#define E_TOT   (N_EDGES + N_NODES)   // 250000
#define F0      74
#define K1PAD   96                    // F0 padded to 3*32
#define H1      4
#define D1      256
#define HD1     (H1 * D1)             // 1024
#define D2      256
#define N_GRAPHS 256
#define OUT_DIM 12
#define NEG_SLOPE 0.2f

// ---------------- scratch ----------------
__device__ __half g_h2 [(size_t)N_NODES * D2];    // layer2 features (fp16)
__device__ float  g_out2[(size_t)N_NODES * D2];   // layer2 output (fp32, post relu)
__device__ float g_als1[N_NODES * H1];
__device__ float g_ald1[N_NODES * H1];
__device__ float g_den1[N_NODES * H1];
__device__ float g_als2[N_NODES];
__device__ float g_ald2[N_NODES];
__device__ float g_den2[N_NODES];
__device__ float g_e1[(size_t)E_TOT * H1];   // exp(leaky(logit))
__device__ float g_e2[E_TOT];
__device__ int   g_deg[N_NODES];
__device__ int   g_rowptr[N_NODES + 1];
__device__ int   g_cursor[N_NODES];
__device__ int   g_elist[E_TOT];
__device__ int   g_src[E_TOT];
__device__ int   g_dst[E_TOT];

// attention projection vectors
__device__ float g_was1[K1PAD * H1];   // (W1 @ a_src1)[k, h], k<74 valid
__device__ float g_wad1[K1PAD * H1];
__device__ float g_was2[HD1];          // W2 @ a_src2
__device__ float g_wad2[HD1];

// GEMM operands (fp16, K-major rows, 16B-aligned)
__device__ uint4 g_xagg[(size_t)N_NODES * H1 * K1PAD / 8]; // per-head agg x [50000,4,96]
__device__ uint4 g_w1a [(size_t)HD1 * K1PAD / 8];          // W1^T fp16 hi [1024,96]
__device__ uint4 g_w1b [(size_t)HD1 * K1PAD / 8];          // W1^T fp16 lo
__device__ uint4 g_o1  [(size_t)N_NODES * HD1 / 8];        // relu(out1) fp16 [50000,1024]
__device__ uint4 g_w2  [(size_t)D2 * HD1 / 8];             // W2^T fp16 [256,1024]

// ---------------- PTX helpers ----------------
__device__ __forceinline__ uint32_t smem_u32(const void* p) {
    uint32_t a;
    asm("{ .reg .u64 t; cvta.to.shared.u64 t, %1; cvt.u32.u64 %0, t; }" : "=r"(a) : "l"(p));
    return a;
}
#define CP_ASYNC16(dst, src) \
    asm volatile("cp.async.cg.shared.global [%0], [%1], 16;" :: "r"(dst), "l"(src))
#define CP_COMMIT() asm volatile("cp.async.commit_group;" ::: "memory")
#define CP_WAIT0()  asm volatile("cp.async.wait_group 0;" ::: "memory")
#define CP_WAIT1()  asm volatile("cp.async.wait_group 1;" ::: "memory")

#define LDSM_X4(r, addr) \
    asm volatile("ldmatrix.sync.aligned.m8n8.x4.shared.b16 {%0,%1,%2,%3}, [%4];" \
        : "=r"((r)[0]), "=r"((r)[1]), "=r"((r)[2]), "=r"((r)[3]) : "r"(addr))

#define MMA_FP16(d, a, b) \
    asm volatile("mma.sync.aligned.m16n8k16.row.col.f32.f16.f16.f32 " \
        "{%0,%1,%2,%3}, {%4,%5,%6,%7}, {%8,%9}, {%0,%1,%2,%3};" \
        : "+f"((d)[0]), "+f"((d)[1]), "+f"((d)[2]), "+f"((d)[3]) \
        : "r"((a)[0]), "r"((a)[1]), "r"((a)[2]), "r"((a)[3]), "r"((b)[0]), "r"((b)[1]))

// ---------------- misc ----------------
__device__ __forceinline__ int detect_i64(const int* p) {
    return (p[1] | p[3] | p[5] | p[7]) == 0;
}
__device__ __forceinline__ float leaky(float v) { return v >= 0.f ? v : NEG_SLOPE * v; }

// ---------------- zero init ----------------
__global__ void k_zero() {
    int i = blockIdx.x * blockDim.x + threadIdx.x;
    if (i < N_NODES) {
        g_deg[i]  = 0;
        g_als2[i] = 0.f; g_ald2[i] = 0.f; g_den2[i] = 0.f;
    }
    if (i < N_NODES * H1) g_den1[i] = 0.f;
}

// ---------------- weight prep ----------------
__global__ void k_prep_w1(const float* __restrict__ W1) {
    int i = blockIdx.x * blockDim.x + threadIdx.x;   // [1024 n][96 k]
    if (i >= HD1 * K1PAD) return;
    int n = i / K1PAD, k = i - n * K1PAD;
    float v = (k < F0) ? W1[(size_t)k * HD1 + n] : 0.f;
    __half hi = __float2half_rn(v);
    ((__half*)g_w1a)[i] = hi;
    ((__half*)g_w1b)[i] = __float2half_rn(v - __half2float(hi));
}
__global__ void k_prep_w2(const float* __restrict__ W2) {
    int i = blockIdx.x * blockDim.x + threadIdx.x;   // [256 n][1024 k]
    if (i >= D2 * HD1) return;
    int n = i >> 10, k = i & 1023;
    ((__half*)g_w2)[i] = __float2half_rn(W2[(size_t)k * D2 + n]);
}

// attvec layer1: g_was1[k*4+h] = sum_d W1[k, h*256+d] * a_src1[h,d]
__global__ void k_prep_av1(const float* __restrict__ W1,
                           const float* __restrict__ as1, const float* __restrict__ ad1) {
    int w = (blockIdx.x * blockDim.x + threadIdx.x) >> 5;
    int lane = threadIdx.x & 31;
    if (w >= F0 * H1) return;
    int k = w >> 2, h = w & 3;
    float s = 0.f, d = 0.f;
    for (int j = lane; j < D1; j += 32) {
        float wv = W1[(size_t)k * HD1 + h * D1 + j];
        s = fmaf(wv, as1[h * D1 + j], s);
        d = fmaf(wv, ad1[h * D1 + j], d);
    }
#pragma unroll
    for (int o = 16; o; o >>= 1) {
        s += __shfl_xor_sync(0xffffffffu, s, o);
        d += __shfl_xor_sync(0xffffffffu, d, o);
    }
    if (lane == 0) { g_was1[k * 4 + h] = s; g_wad1[k * 4 + h] = d; }
}
// attvec layer2: g_was2[k] = sum_j W2[k, j] * a_src2[j]
__global__ void k_prep_av2(const float* __restrict__ W2,
                           const float* __restrict__ as2, const float* __restrict__ ad2) {
    int w = (blockIdx.x * blockDim.x + threadIdx.x) >> 5;
    int lane = threadIdx.x & 31;
    if (w >= HD1) return;
    float s = 0.f, d = 0.f;
    for (int j = lane; j < D2; j += 32) {
        float wv = W2[(size_t)w * D2 + j];
        s = fmaf(wv, as2[j], s);
        d = fmaf(wv, ad2[j], d);
    }
#pragma unroll
    for (int o = 16; o; o >>= 1) {
        s += __shfl_xor_sync(0xffffffffu, s, o);
        d += __shfl_xor_sync(0xffffffffu, d, o);
    }
    if (lane == 0) { g_was2[w] = s; g_wad2[w] = d; }
}

// layer-1 logits: als1[n,h] = x[n,:] . was1[:,h]   (warp per node)
__global__ void k_logit1(const float* __restrict__ x) {
    int n = (blockIdx.x * blockDim.x + threadIdx.x) >> 5;
    int lane = threadIdx.x & 31;
    if (n >= N_NODES) return;
    float4 s = make_float4(0, 0, 0, 0), d = make_float4(0, 0, 0, 0);
    for (int k = lane; k < F0; k += 32) {
        float xv = __ldg(&x[(size_t)n * F0 + k]);
        float4 a = *(const float4*)(g_was1 + k * 4);
        float4 b = *(const float4*)(g_wad1 + k * 4);
        s.x = fmaf(xv, a.x, s.x); s.y = fmaf(xv, a.y, s.y);
        s.z = fmaf(xv, a.z, s.z); s.w = fmaf(xv, a.w, s.w);
        d.x = fmaf(xv, b.x, d.x); d.y = fmaf(xv, b.y, d.y);
        d.z = fmaf(xv, b.z, d.z); d.w = fmaf(xv, b.w, d.w);
    }
#pragma unroll
    for (int o = 16; o; o >>= 1) {
        s.x += __shfl_xor_sync(0xffffffffu, s.x, o);
        s.y += __shfl_xor_sync(0xffffffffu, s.y, o);
        s.z += __shfl_xor_sync(0xffffffffu, s.z, o);
        s.w += __shfl_xor_sync(0xffffffffu, s.w, o);
        d.x += __shfl_xor_sync(0xffffffffu, d.x, o);
        d.y += __shfl_xor_sync(0xffffffffu, d.y, o);
        d.z += __shfl_xor_sync(0xffffffffu, d.z, o);
        d.w += __shfl_xor_sync(0xffffffffu, d.w, o);
    }
    if (lane == 0) {
        *(float4*)(g_als1 + n * 4) = s;
        *(float4*)(g_ald1 + n * 4) = d;
    }
}

// ---------------- CSR build ----------------
__global__ void k_prep_edges(const int* ei32) {
    int e = blockIdx.x * blockDim.x + threadIdx.x;
    if (e >= E_TOT) return;
    int is64 = detect_i64(ei32);
    int s, d;
    if (e < N_EDGES) {
        s = is64 ? ei32[2 * (size_t)e]             : ei32[e];
        d = is64 ? ei32[2 * ((size_t)N_EDGES + e)] : ei32[N_EDGES + e];
    } else {
        s = d = e - N_EDGES;
    }
    g_src[e] = s;
    g_dst[e] = d;
    atomicAdd(&g_deg[d], 1);
}
__global__ void k_scan() {
    __shared__ int sums[1024];
    int t = threadIdx.x;
    const int CH = (N_NODES + 1023) / 1024;
    int b = t * CH, e = min(b + CH, N_NODES);
    int s = 0;
    for (int i = b; i < e; i++) s += g_deg[i];
    sums[t] = s;
    __syncthreads();
    for (int off = 1; off < 1024; off <<= 1) {
        int v = (t >= off) ? sums[t - off] : 0;
        __syncthreads();
        sums[t] += v;
        __syncthreads();
    }
    int run = sums[t] - s;
    for (int i = b; i < e; i++) { g_rowptr[i] = run; run += g_deg[i]; }
    if (t == 1023) g_rowptr[N_NODES] = sums[1023];
}
__global__ void k_init_cursor() {
    int i = blockIdx.x * blockDim.x + threadIdx.x;
    if (i < N_NODES) g_cursor[i] = g_rowptr[i];
}
__global__ void k_scatter() {
    int e = blockIdx.x * blockDim.x + threadIdx.x;
    if (e >= E_TOT) return;
    int p = atomicAdd(&g_cursor[g_dst[e]], 1);
    g_elist[p] = e;
}

// ---------------- edge kernels ----------------
__global__ void k_edge1() {
    int e = blockIdx.x * blockDim.x + threadIdx.x;
    if (e >= E_TOT) return;
    int s = g_src[e], d = g_dst[e];
    const float4 as = *(const float4*)(g_als1 + s * 4);
    const float4 ad = *(const float4*)(g_ald1 + d * 4);
    float4 o;
    o.x = expf(leaky(as.x + ad.x));
    o.y = expf(leaky(as.y + ad.y));
    o.z = expf(leaky(as.z + ad.z));
    o.w = expf(leaky(as.w + ad.w));
    *(float4*)(g_e1 + (size_t)e * 4) = o;
    atomicAdd(&g_den1[d * 4 + 0], o.x);
    atomicAdd(&g_den1[d * 4 + 1], o.y);
    atomicAdd(&g_den1[d * 4 + 2], o.z);
    atomicAdd(&g_den1[d * 4 + 3], o.w);
}
__global__ void k_edge2() {
    int e = blockIdx.x * blockDim.x + threadIdx.x;
    if (e >= E_TOT) return;
    int d = g_dst[e];
    float v = expf(leaky(g_als2[g_src[e]] + g_ald2[d]));
    g_e2[e] = v;
    atomicAdd(&g_den2[d], v);
}

// ---------------- aggregate x per head (input-space aggregation) ----------
// block 96 threads = one dst node; thread t owns input col t (t<74 valid)
__global__ __launch_bounds__(96) void k_aggx(const float* __restrict__ x) {
    int n = blockIdx.x, t = threadIdx.x;
    int start = g_rowptr[n], deg = g_rowptr[n + 1] - start;
    __shared__ float ash[64 * H1];
    __shared__ int   ssrc[64];

    const float4 den = *(const float4*)(g_den1 + n * 4);
    float4 inv;
    inv.x = 1.f / (den.x + 1e-16f);
    inv.y = 1.f / (den.y + 1e-16f);
    inv.z = 1.f / (den.z + 1e-16f);
    inv.w = 1.f / (den.w + 1e-16f);

    float a0 = 0.f, a1 = 0.f, a2 = 0.f, a3 = 0.f;
    for (int c0 = 0; c0 < deg; c0 += 64) {
        int cnt = min(64, deg - c0);
        if (t < cnt) {
            int e = g_elist[start + c0 + t];
            ssrc[t] = g_src[e];
            float4 ex = *(const float4*)(g_e1 + (size_t)e * 4);
            ash[t * 4 + 0] = ex.x * inv.x;
            ash[t * 4 + 1] = ex.y * inv.y;
            ash[t * 4 + 2] = ex.z * inv.z;
            ash[t * 4 + 3] = ex.w * inv.w;
        }
        __syncthreads();
        for (int j = 0; j < cnt; j++) {
            float xv = (t < F0) ? __ldg(&x[(size_t)ssrc[j] * F0 + t]) : 0.f;
            a0 = fmaf(xv, ash[j * 4 + 0], a0);
            a1 = fmaf(xv, ash[j * 4 + 1], a1);
            a2 = fmaf(xv, ash[j * 4 + 2], a2);
            a3 = fmaf(xv, ash[j * 4 + 3], a3);
        }
        __syncthreads();
    }
    __half* xa = (__half*)g_xagg + (size_t)n * (H1 * K1PAD);
    xa[t]           = __float2half_rn(a0);
    xa[K1PAD + t]   = __float2half_rn(a1);
    xa[2*K1PAD + t] = __float2half_rn(a2);
    xa[3*K1PAD + t] = __float2half_rn(a3);
}

// ---------------- GEMM ----------------
#define SMSTRIDE 80
#define TILE_B   (128 * SMSTRIDE)

// C = A[M,K] @ B[N,K]^T. AHEADS>1: A rows are [AHEADS][K], head chosen by n0.
// FUSE: v = relu(acc + bias[c]); store; als[r] += v.avs[c]; ald[r] += v.avd[c].
template <int KT, int LDC, int NB, int AHEADS, bool FUSE>
__global__ __launch_bounds__(256, 2) void k_mma(
    const uint4* __restrict__ A1,
    const uint4* __restrict__ B1, const uint4* __restrict__ B2,
    __half* __restrict__ C, int M,
    const float* __restrict__ bias,
    const float* __restrict__ avs, const float* __restrict__ avd,
    float* __restrict__ als, float* __restrict__ ald)
{
    extern __shared__ char smem[];
    const uint32_t sbase = smem_u32(smem);
    const int tid = threadIdx.x, lane = tid & 31, wid = tid >> 5;
    const int wm = wid & 1, wn = wid >> 1;
    const int m0 = blockIdx.y * 128, n0 = blockIdx.x * 128;
    const int KW = KT * 4;                       // uint4 per (head-)row
    const int AST = AHEADS * KW;                 // A row stride
    const int head = (AHEADS == 1) ? 0 : (n0 >> 8);
    constexpr int NT = 1 + NB;

    float acc[4][4][4];
#pragma unroll
    for (int a = 0; a < 4; a++)
#pragma unroll
        for (int b = 0; b < 4; b++)
#pragma unroll
            for (int c = 0; c < 4; c++) acc[a][b][c] = 0.f;

    auto load_stage = [&](int ki, int s) {
        uint32_t sb = sbase + s * (NT * TILE_B);
#pragma unroll
        for (int i = 0; i < 2; i++) {
            int idx = tid + i * 256;
            int row = idx >> 2, ch = idx & 3;
            uint32_t soff = row * SMSTRIDE + ch * 16;
            int ar = min(m0 + row, M - 1);
            size_t ga = (size_t)ar * AST + head * KW + ki * 4 + ch;
            size_t gb = (size_t)(n0 + row) * KW + ki * 4 + ch;
            CP_ASYNC16(sb + soff,          A1 + ga);
            CP_ASYNC16(sb + TILE_B + soff, B1 + gb);
            if (NB == 2) CP_ASYNC16(sb + 2 * TILE_B + soff, B2 + gb);
        }
        CP_COMMIT();
    };

    load_stage(0, 0);

    for (int ki = 0; ki < KT; ki++) {
        if (ki + 1 < KT) load_stage(ki + 1, (ki + 1) & 1);
        if (ki + 1 < KT) CP_WAIT1(); else CP_WAIT0();
        __syncthreads();

        uint32_t sb  = sbase + (ki & 1) * (NT * TILE_B);
        uint32_t a1b = sb, b1b = sb + TILE_B, b2b = sb + 2 * TILE_B;

#pragma unroll
        for (int k16 = 0; k16 < 2; k16++) {
            uint32_t bf1[8], bf2[8];
#pragma unroll
            for (int g = 0; g < 2; g++) {
                int nrow = wn * 32 + g * 16 + (lane & 7) + ((lane >> 4) << 3);
                int kb   = k16 * 32 + (((lane >> 3) & 1) << 4);
                uint32_t ao = nrow * SMSTRIDE + kb;
                LDSM_X4(&bf1[g * 4], b1b + ao);
                if (NB == 2) LDSM_X4(&bf2[g * 4], b2b + ao);
            }
#pragma unroll
            for (int mt = 0; mt < 4; mt++) {
                int arow = wm * 64 + mt * 16 + (lane & 7) + (((lane >> 3) & 1) << 3);
                int kb   = k16 * 32 + ((lane >> 4) << 4);
                uint32_t ao = arow * SMSTRIDE + kb;
                uint32_t af[4];
                LDSM_X4(af, a1b + ao);
#pragma unroll
                for (int nt = 0; nt < 4; nt++) MMA_FP16(acc[mt][nt], af, &bf1[nt * 2]);
                if (NB == 2) {
#pragma unroll
                    for (int nt = 0; nt < 4; nt++) MMA_FP16(acc[mt][nt], af, &bf2[nt * 2]);
                }
            }
        }
        __syncthreads();
    }

    // ---------------- epilogue ----------------
    if (FUSE) {
        float bv[4][2], av_s[4][2], av_d[4][2];
#pragma unroll
        for (int nt = 0; nt < 4; nt++) {
            int c = n0 + wn * 32 + nt * 8 + (lane & 3) * 2;
            bv[nt][0]   = bias[c]; bv[nt][1]   = bias[c + 1];
            av_s[nt][0] = avs[c];  av_s[nt][1] = avs[c + 1];
            av_d[nt][0] = avd[c];  av_d[nt][1] = avd[c + 1];
        }
#pragma unroll
        for (int mt = 0; mt < 4; mt++) {
            int r = m0 + wm * 64 + mt * 16 + (lane >> 2);
            float s0 = 0.f, s1 = 0.f, d0 = 0.f, d1 = 0.f;
#pragma unroll
            for (int nt = 0; nt < 4; nt++) {
                int c = n0 + wn * 32 + nt * 8 + (lane & 3) * 2;
                float v0 = fmaxf(acc[mt][nt][0] + bv[nt][0], 0.f);
                float v1 = fmaxf(acc[mt][nt][1] + bv[nt][1], 0.f);
                float v2 = fmaxf(acc[mt][nt][2] + bv[nt][0], 0.f);
                float v3 = fmaxf(acc[mt][nt][3] + bv[nt][1], 0.f);
                if (r < M)
                    *(__half2*)&C[(size_t)r * LDC + c] = __floats2half2_rn(v0, v1);
                if (r + 8 < M)
                    *(__half2*)&C[(size_t)(r + 8) * LDC + c] = __floats2half2_rn(v2, v3);
                s0 = fmaf(v0, av_s[nt][0], fmaf(v1, av_s[nt][1], s0));
                s1 = fmaf(v2, av_s[nt][0], fmaf(v3, av_s[nt][1], s1));
                d0 = fmaf(v0, av_d[nt][0], fmaf(v1, av_d[nt][1], d0));
                d1 = fmaf(v2, av_d[nt][0], fmaf(v3, av_d[nt][1], d1));
            }
            s0 += __shfl_xor_sync(0xffffffffu, s0, 1); s0 += __shfl_xor_sync(0xffffffffu, s0, 2);
            s1 += __shfl_xor_sync(0xffffffffu, s1, 1); s1 += __shfl_xor_sync(0xffffffffu, s1, 2);
            d0 += __shfl_xor_sync(0xffffffffu, d0, 1); d0 += __shfl_xor_sync(0xffffffffu, d0, 2);
            d1 += __shfl_xor_sync(0xffffffffu, d1, 1); d1 += __shfl_xor_sync(0xffffffffu, d1, 2);
            if ((lane & 3) == 0) {
                if (r < M)     { atomicAdd(&als[r], s0);     atomicAdd(&ald[r], d0); }
                if (r + 8 < M) { atomicAdd(&als[r + 8], s1); atomicAdd(&ald[r + 8], d1); }
            }
        }
    } else {
#pragma unroll
        for (int mt = 0; mt < 4; mt++) {
            int r = m0 + wm * 64 + mt * 16 + (lane >> 2);
#pragma unroll
            for (int nt = 0; nt < 4; nt++) {
                int c = n0 + wn * 32 + nt * 8 + (lane & 3) * 2;
                if (r < M)
                    *(__half2*)&C[(size_t)r * LDC + c] = __floats2half2_rn(acc[mt][nt][0], acc[mt][nt][1]);
                if (r + 8 < M)
                    *(__half2*)&C[(size_t)(r + 8) * LDC + c] = __floats2half2_rn(acc[mt][nt][2], acc[mt][nt][3]);
            }
        }
    }
}

// ---------------- aggregate layer 2 ----------------
__global__ __launch_bounds__(256) void k_agg2(const float* __restrict__ b2) {
    int n = blockIdx.x, t = threadIdx.x;
    int start = g_rowptr[n], deg = g_rowptr[n + 1] - start;
    __shared__ float ash[64];
    __shared__ int   ssrc[64];

    float inv = 1.f / (g_den2[n] + 1e-16f);

    float acc = 0.f;
    for (int c0 = 0; c0 < deg; c0 += 64) {
        int cnt = min(64, deg - c0);
        if (t < cnt) {
            int e = g_elist[start + c0 + t];
            ssrc[t] = g_src[e];
            ash[t] = g_e2[e] * inv;
        }
        __syncthreads();
#pragma unroll 2
        for (int j = 0; j < cnt; j++)
            acc = fmaf(__half2float(__ldg(g_h2 + (size_t)ssrc[j] * D2 + t)), ash[j], acc);
        __syncthreads();
    }
    g_out2[(size_t)n * D2 + t] = fmaxf(acc + b2[t], 0.f);
}

// ---------------- pool + FC ----------------
__device__ __forceinline__ int lower_bound_batch(const int* b32, int is64, int key) {
    int lo = 0, hi = N_NODES;
    while (lo < hi) {
        int mid = (lo + hi) >> 1;
        int v = is64 ? b32[2 * mid] : b32[mid];
        if (v < key) lo = mid + 1; else hi = mid;
    }
    return lo;
}
__global__ __launch_bounds__(256) void k_pool_fc(
    const int* __restrict__ batch32, const int* __restrict__ ei32,
    const float* __restrict__ fcW, const float* __restrict__ fcb,
    float* __restrict__ out)
{
    int g = blockIdx.x, t = threadIdx.x;
    __shared__ int s_lo, s_hi;
    __shared__ float pooled[D2];
    if (t == 0) {
        int is64 = detect_i64(ei32);
        s_lo = lower_bound_batch(batch32, is64, g);
        s_hi = lower_bound_batch(batch32, is64, g + 1);
    }
    __syncthreads();
    int lo = s_lo, hi = s_hi;
    float s = 0.f;
    for (int n = lo; n < hi; n++) s += g_out2[(size_t)n * D2 + t];
    float cnt = (float)(hi - lo);
    pooled[t] = s / fmaxf(cnt, 1.f);
    __syncthreads();
    if (t < OUT_DIM) {
        float acc = fcb[t];
        for (int d = 0; d < D2; d++) acc = fmaf(pooled[d], fcW[d * OUT_DIM + t], acc);
        out[g * OUT_DIM + t] = acc;
    }
}

// ---------------- launch ----------------
extern "C" void kernel_launch(void* const* d_in, const int* in_sizes, int n_in,
                              void* d_out, int out_size)
{
    const float* x      = (const float*)d_in[0];
    const int*   ei32   = (const int*)  d_in[1];
    const int*   bat32  = (const int*)  d_in[2];
    const float* W1     = (const float*)d_in[3];
    const float* a_src1 = (const float*)d_in[4];
    const float* a_dst1 = (const float*)d_in[5];
    const float* b1     = (const float*)d_in[6];
    const float* W2     = (const float*)d_in[7];
    const float* a_src2 = (const float*)d_in[8];
    const float* a_dst2 = (const float*)d_in[9];
    const float* b2     = (const float*)d_in[10];
    const float* fcW    = (const float*)d_in[11];
    const float* fcb    = (const float*)d_in[12];
    float* out = (float*)d_out;

    uint4 *xagg, *w1a, *w1b, *o1, *w2;
    __half *h2;
    float *als2, *ald2, *was2, *wad2;
    cudaGetSymbolAddress((void**)&xagg, g_xagg);
    cudaGetSymbolAddress((void**)&w1a,  g_w1a);
    cudaGetSymbolAddress((void**)&w1b,  g_w1b);
    cudaGetSymbolAddress((void**)&o1,   g_o1);
    cudaGetSymbolAddress((void**)&w2,   g_w2);
    cudaGetSymbolAddress((void**)&h2,   g_h2);
    cudaGetSymbolAddress((void**)&als2, g_als2);
    cudaGetSymbolAddress((void**)&ald2, g_ald2);
    cudaGetSymbolAddress((void**)&was2, g_was2);
    cudaGetSymbolAddress((void**)&wad2, g_wad2);

    const int SM1 = 2 * 3 * TILE_B;   // 61440
    const int SM2 = 2 * 2 * TILE_B;   // 40960
    cudaFuncSetAttribute((void*)k_mma<3, HD1, 2, H1, true>,  cudaFuncAttributeMaxDynamicSharedMemorySize, SM1);
    cudaFuncSetAttribute((void*)k_mma<32, D2, 1, 1, false>,  cudaFuncAttributeMaxDynamicSharedMemorySize, SM2);

    const int MT = (N_NODES + 127) / 128;   // 391

    k_zero    <<<(N_NODES * H1 + 255) / 256, 256>>>();
    k_prep_w1 <<<(HD1 * K1PAD + 255) / 256, 256>>>(W1);
    k_prep_w2 <<<(D2 * HD1 + 255) / 256, 256>>>(W2);
    k_prep_av1<<<(F0 * H1 * 32 + 255) / 256, 256>>>(W1, a_src1, a_dst1);
    k_prep_av2<<<(HD1 * 32 + 255) / 256, 256>>>(W2, a_src2, a_dst2);
    k_logit1  <<<(N_NODES * 32 + 255) / 256, 256>>>(x);

    // CSR
    k_prep_edges <<<(E_TOT + 255) / 256, 256>>>(ei32);
    k_scan       <<<1, 1024>>>();
    k_init_cursor<<<(N_NODES + 255) / 256, 256>>>();
    k_scatter    <<<(E_TOT + 255) / 256, 256>>>();

    k_edge1<<<(E_TOT + 255) / 256, 256>>>();
    k_aggx <<<N_NODES, 96>>>(x);

    // GEMM1': out1 = relu(xagg @ W1split + b1); fused als2/ald2
    k_mma<3, HD1, 2, H1, true><<<dim3(HD1 / 128, MT), 256, SM1>>>(
        xagg, w1a, w1b, (__half*)o1, N_NODES, b1, was2, wad2, als2, ald2);

    k_edge2<<<(E_TOT + 255) / 256, 256>>>();

    // GEMM2: h2 = out1 @ W2 (plain)
    k_mma<32, D2, 1, 1, false><<<dim3(D2 / 128, MT), 256, SM2>>>(
        o1, w2, w2, h2, N_NODES, b2, was2, wad2, als2, ald2);

    k_agg2<<<N_NODES, 256>>>(b2);

    k_pool_fc<<<N_GRAPHS, 256>>>(bat32, ei32, fcW, fcb, out);
}

// round 8
// speedup vs baseline: 4.2623x; 1.1959x over previous
#include <cuda_runtime.h>
#include <cuda_fp16.h>
#include <math.h>
#include <stdint.h>

// ---------------- problem constants ----------------
#define N_NODES 50000
#define N_EDGES 200000
#define E_TOT   (N_EDGES + N_NODES)   // 250000
#define F0      74
#define K1PAD   96
#define H1      4
#define D1      256
#define HD1     (H1 * D1)             // 1024
#define D2      256
#define N_GRAPHS 256
#define OUT_DIM 12
#define NEG_SLOPE 0.2f

// ---------------- scratch ----------------
__device__ __half g_h2 [(size_t)N_NODES * D2];
__device__ float  g_out2[(size_t)N_NODES * D2];
__device__ float g_als1[N_NODES * H1];
__device__ float g_ald1[N_NODES * H1];
__device__ float g_als2[N_NODES];
__device__ float g_ald2[N_NODES];
__device__ int   g_deg[N_NODES];
__device__ int   g_rowptr[N_NODES + 1];
__device__ int   g_cursor[N_NODES];
__device__ int   g_elist[E_TOT];
__device__ int   g_src[E_TOT];
__device__ int   g_dst[E_TOT];

// attention projection vectors
__device__ float g_was1[K1PAD * H1];
__device__ float g_wad1[K1PAD * H1];
__device__ float g_was2[HD1];
__device__ float g_wad2[HD1];

// GEMM operands (fp16, K-major, 16B-aligned)
__device__ uint4 g_xagg[(size_t)N_NODES * H1 * K1PAD / 8];
__device__ uint4 g_w1a [(size_t)HD1 * K1PAD / 8];
__device__ uint4 g_w1b [(size_t)HD1 * K1PAD / 8];
__device__ uint4 g_o1  [(size_t)N_NODES * HD1 / 8];
__device__ uint4 g_w2  [(size_t)D2 * HD1 / 8];

// ---------------- PTX helpers ----------------
__device__ __forceinline__ uint32_t smem_u32(const void* p) {
    uint32_t a;
    asm("{ .reg .u64 t; cvta.to.shared.u64 t, %1; cvt.u32.u64 %0, t; }" : "=r"(a) : "l"(p));
    return a;
}
#define CP_ASYNC16(dst, src) \
    asm volatile("cp.async.cg.shared.global [%0], [%1], 16;" :: "r"(dst), "l"(src))
#define CP_COMMIT() asm volatile("cp.async.commit_group;" ::: "memory")
#define CP_WAIT0()  asm volatile("cp.async.wait_group 0;" ::: "memory")
#define CP_WAIT1()  asm volatile("cp.async.wait_group 1;" ::: "memory")

#define LDSM_X4(r, addr) \
    asm volatile("ldmatrix.sync.aligned.m8n8.x4.shared.b16 {%0,%1,%2,%3}, [%4];" \
        : "=r"((r)[0]), "=r"((r)[1]), "=r"((r)[2]), "=r"((r)[3]) : "r"(addr))

#define MMA_FP16(d, a, b) \
    asm volatile("mma.sync.aligned.m16n8k16.row.col.f32.f16.f16.f32 " \
        "{%0,%1,%2,%3}, {%4,%5,%6,%7}, {%8,%9}, {%0,%1,%2,%3};" \
        : "+f"((d)[0]), "+f"((d)[1]), "+f"((d)[2]), "+f"((d)[3]) \
        : "r"((a)[0]), "r"((a)[1]), "r"((a)[2]), "r"((a)[3]), "r"((b)[0]), "r"((b)[1]))

// ---------------- misc ----------------
__device__ __forceinline__ int detect_i64(const int* p) {
    return (p[1] | p[3] | p[5] | p[7]) == 0;
}
__device__ __forceinline__ float leaky(float v) { return v >= 0.f ? v : NEG_SLOPE * v; }

// ---------------- fused setup: weight preps + attvecs + zero ----------------
#define PW1_B 384     // prep_w1: 98304 elems
#define PW2_B 1024    // prep_w2: 262144 elems
#define AV1_B 37      // prep_av1: 296 warps
#define AV2_B 128     // prep_av2: 1024 warps
#define ZR_B  196     // zero: 50000
#define SETUP_GRID (PW1_B + PW2_B + AV1_B + AV2_B + ZR_B)

__global__ __launch_bounds__(256) void k_setup(
    const float* __restrict__ W1, const float* __restrict__ W2,
    const float* __restrict__ as1, const float* __restrict__ ad1,
    const float* __restrict__ as2, const float* __restrict__ ad2)
{
    int b = blockIdx.x, t = threadIdx.x, lane = t & 31;
    if (b < PW1_B) {
        int i = b * 256 + t;                       // [1024 n][96 k]
        if (i < HD1 * K1PAD) {
            int n = i / K1PAD, k = i - n * K1PAD;
            float v = (k < F0) ? W1[(size_t)k * HD1 + n] : 0.f;
            __half hi = __float2half_rn(v);
            ((__half*)g_w1a)[i] = hi;
            ((__half*)g_w1b)[i] = __float2half_rn(v - __half2float(hi));
        }
    } else if (b < PW1_B + PW2_B) {
        int i = (b - PW1_B) * 256 + t;             // [256 n][1024 k]
        if (i < D2 * HD1) {
            int n = i >> 10, k = i & 1023;
            ((__half*)g_w2)[i] = __float2half_rn(W2[(size_t)k * D2 + n]);
        }
    } else if (b < PW1_B + PW2_B + AV1_B) {
        int w = ((b - PW1_B - PW2_B) * 256 + t) >> 5;
        if (w < F0 * H1) {
            int k = w >> 2, h = w & 3;
            float s = 0.f, d = 0.f;
            for (int j = lane; j < D1; j += 32) {
                float wv = W1[(size_t)k * HD1 + h * D1 + j];
                s = fmaf(wv, as1[h * D1 + j], s);
                d = fmaf(wv, ad1[h * D1 + j], d);
            }
#pragma unroll
            for (int o = 16; o; o >>= 1) {
                s += __shfl_xor_sync(0xffffffffu, s, o);
                d += __shfl_xor_sync(0xffffffffu, d, o);
            }
            if (lane == 0) { g_was1[k * 4 + h] = s; g_wad1[k * 4 + h] = d; }
        }
    } else if (b < PW1_B + PW2_B + AV1_B + AV2_B) {
        int w = ((b - PW1_B - PW2_B - AV1_B) * 256 + t) >> 5;
        if (w < HD1) {
            float s = 0.f, d = 0.f;
            for (int j = lane; j < D2; j += 32) {
                float wv = W2[(size_t)w * D2 + j];
                s = fmaf(wv, as2[j], s);
                d = fmaf(wv, ad2[j], d);
            }
#pragma unroll
            for (int o = 16; o; o >>= 1) {
                s += __shfl_xor_sync(0xffffffffu, s, o);
                d += __shfl_xor_sync(0xffffffffu, d, o);
            }
            if (lane == 0) { g_was2[w] = s; g_wad2[w] = d; }
        }
    } else {
        int i = (b - PW1_B - PW2_B - AV1_B - AV2_B) * 256 + t;
        if (i < N_NODES) {
            g_deg[i] = 0;
            g_als2[i] = 0.f;
            g_ald2[i] = 0.f;
        }
    }
}

// ---------------- stage2: layer-1 logits (warp/node) + edge decode ---------
#define LG_B 6250     // 50000 warps
#define PE_B ((E_TOT + 255) / 256)
#define STAGE2_GRID (LG_B + PE_B)

__global__ __launch_bounds__(256) void k_stage2(const float* __restrict__ x,
                                                const int* __restrict__ ei32) {
    int b = blockIdx.x, t = threadIdx.x;
    if (b < LG_B) {
        int n = (b * 256 + t) >> 5;
        int lane = t & 31;
        if (n >= N_NODES) return;
        float4 s = make_float4(0, 0, 0, 0), d = make_float4(0, 0, 0, 0);
        for (int k = lane; k < F0; k += 32) {
            float xv = __ldg(&x[(size_t)n * F0 + k]);
            float4 a = *(const float4*)(g_was1 + k * 4);
            float4 bb = *(const float4*)(g_wad1 + k * 4);
            s.x = fmaf(xv, a.x, s.x);  s.y = fmaf(xv, a.y, s.y);
            s.z = fmaf(xv, a.z, s.z);  s.w = fmaf(xv, a.w, s.w);
            d.x = fmaf(xv, bb.x, d.x); d.y = fmaf(xv, bb.y, d.y);
            d.z = fmaf(xv, bb.z, d.z); d.w = fmaf(xv, bb.w, d.w);
        }
#pragma unroll
        for (int o = 16; o; o >>= 1) {
            s.x += __shfl_xor_sync(0xffffffffu, s.x, o);
            s.y += __shfl_xor_sync(0xffffffffu, s.y, o);
            s.z += __shfl_xor_sync(0xffffffffu, s.z, o);
            s.w += __shfl_xor_sync(0xffffffffu, s.w, o);
            d.x += __shfl_xor_sync(0xffffffffu, d.x, o);
            d.y += __shfl_xor_sync(0xffffffffu, d.y, o);
            d.z += __shfl_xor_sync(0xffffffffu, d.z, o);
            d.w += __shfl_xor_sync(0xffffffffu, d.w, o);
        }
        if (lane == 0) {
            *(float4*)(g_als1 + n * 4) = s;
            *(float4*)(g_ald1 + n * 4) = d;
        }
    } else {
        int e = (b - LG_B) * 256 + t;
        if (e >= E_TOT) return;
        int is64 = detect_i64(ei32);
        int s, d;
        if (e < N_EDGES) {
            s = is64 ? ei32[2 * (size_t)e]             : ei32[e];
            d = is64 ? ei32[2 * ((size_t)N_EDGES + e)] : ei32[N_EDGES + e];
        } else {
            s = d = e - N_EDGES;
        }
        g_src[e] = s;
        g_dst[e] = d;
        atomicAdd(&g_deg[d], 1);
    }
}

// ---------------- CSR scan (+ cursor init) ----------------
__global__ void k_scan() {
    __shared__ int sums[1024];
    int t = threadIdx.x;
    const int CH = (N_NODES + 1023) / 1024;
    int b = t * CH, e = min(b + CH, N_NODES);
    int s = 0;
    for (int i = b; i < e; i++) s += g_deg[i];
    sums[t] = s;
    __syncthreads();
    for (int off = 1; off < 1024; off <<= 1) {
        int v = (t >= off) ? sums[t - off] : 0;
        __syncthreads();
        sums[t] += v;
        __syncthreads();
    }
    int run = sums[t] - s;
    for (int i = b; i < e; i++) {
        g_rowptr[i] = run;
        g_cursor[i] = run;
        run += g_deg[i];
    }
    if (t == 1023) g_rowptr[N_NODES] = sums[1023];
}
__global__ void k_scatter() {
    int e = blockIdx.x * blockDim.x + threadIdx.x;
    if (e >= E_TOT) return;
    int p = atomicAdd(&g_cursor[g_dst[e]], 1);
    g_elist[p] = e;
}

// ---------------- layer-1 aggregate (warp/node, fused softmax) -------------
__global__ __launch_bounds__(256) void k_aggx(const float* __restrict__ x) {
    int n = (blockIdx.x * blockDim.x + threadIdx.x) >> 5;
    int lane = threadIdx.x & 31;
    if (n >= N_NODES) return;
    int start = g_rowptr[n], deg = g_rowptr[n + 1] - start;
    const float4 adn = *(const float4*)(g_ald1 + n * 4);

    float a[3][4];
#pragma unroll
    for (int g = 0; g < 3; g++)
#pragma unroll
        for (int h = 0; h < 4; h++) a[g][h] = 0.f;
    float4 den = make_float4(0, 0, 0, 0);

    for (int c0 = 0; c0 < deg; c0 += 32) {
        int j = c0 + lane;
        int srcj = 0;
        float4 e = make_float4(0, 0, 0, 0);
        if (j < deg) {
            int ed = g_elist[start + j];
            srcj = g_src[ed];
            float4 as = *(const float4*)(g_als1 + srcj * 4);
            e.x = expf(leaky(as.x + adn.x));
            e.y = expf(leaky(as.y + adn.y));
            e.z = expf(leaky(as.z + adn.z));
            e.w = expf(leaky(as.w + adn.w));
            den.x += e.x; den.y += e.y; den.z += e.z; den.w += e.w;
        }
        int cnt = min(32, deg - c0);
        for (int jj = 0; jj < cnt; jj++) {
            int s  = __shfl_sync(0xffffffffu, srcj, jj);
            float e0 = __shfl_sync(0xffffffffu, e.x, jj);
            float e1 = __shfl_sync(0xffffffffu, e.y, jj);
            float e2 = __shfl_sync(0xffffffffu, e.z, jj);
            float e3 = __shfl_sync(0xffffffffu, e.w, jj);
            const float* xr = x + (size_t)s * F0;
            float x0 = __ldg(xr + lane);
            float x1 = __ldg(xr + lane + 32);
            float x2 = (lane + 64 < F0) ? __ldg(xr + lane + 64) : 0.f;
            a[0][0] = fmaf(x0, e0, a[0][0]); a[0][1] = fmaf(x0, e1, a[0][1]);
            a[0][2] = fmaf(x0, e2, a[0][2]); a[0][3] = fmaf(x0, e3, a[0][3]);
            a[1][0] = fmaf(x1, e0, a[1][0]); a[1][1] = fmaf(x1, e1, a[1][1]);
            a[1][2] = fmaf(x1, e2, a[1][2]); a[1][3] = fmaf(x1, e3, a[1][3]);
            a[2][0] = fmaf(x2, e0, a[2][0]); a[2][1] = fmaf(x2, e1, a[2][1]);
            a[2][2] = fmaf(x2, e2, a[2][2]); a[2][3] = fmaf(x2, e3, a[2][3]);
        }
    }
#pragma unroll
    for (int o = 16; o; o >>= 1) {
        den.x += __shfl_xor_sync(0xffffffffu, den.x, o);
        den.y += __shfl_xor_sync(0xffffffffu, den.y, o);
        den.z += __shfl_xor_sync(0xffffffffu, den.z, o);
        den.w += __shfl_xor_sync(0xffffffffu, den.w, o);
    }
    float inv[4];
    inv[0] = 1.f / (den.x + 1e-16f);
    inv[1] = 1.f / (den.y + 1e-16f);
    inv[2] = 1.f / (den.z + 1e-16f);
    inv[3] = 1.f / (den.w + 1e-16f);

    __half* xa = (__half*)g_xagg + (size_t)n * (H1 * K1PAD);
#pragma unroll
    for (int g = 0; g < 3; g++) {
        int col = lane + 32 * g;
#pragma unroll
        for (int h = 0; h < 4; h++)
            xa[h * K1PAD + col] = __float2half_rn(a[g][h] * inv[h]);
    }
}

// ---------------- layer-2 aggregate (warp/node, fused softmax) -------------
__global__ __launch_bounds__(256) void k_agg2(const float* __restrict__ b2) {
    int n = (blockIdx.x * blockDim.x + threadIdx.x) >> 5;
    int lane = threadIdx.x & 31;
    if (n >= N_NODES) return;
    int start = g_rowptr[n], deg = g_rowptr[n + 1] - start;
    const float adn = g_ald2[n];

    float2 acc[4];
#pragma unroll
    for (int q = 0; q < 4; q++) acc[q] = make_float2(0.f, 0.f);
    float den = 0.f;

    for (int c0 = 0; c0 < deg; c0 += 32) {
        int j = c0 + lane;
        int srcj = 0;
        float e = 0.f;
        if (j < deg) {
            int ed = g_elist[start + j];
            srcj = g_src[ed];
            e = expf(leaky(g_als2[srcj] + adn));
            den += e;
        }
        int cnt = min(32, deg - c0);
        for (int jj = 0; jj < cnt; jj++) {
            int s   = __shfl_sync(0xffffffffu, srcj, jj);
            float ev = __shfl_sync(0xffffffffu, e, jj);
            const __half2* hr = (const __half2*)(g_h2 + (size_t)s * D2);
#pragma unroll
            for (int q = 0; q < 4; q++) {
                float2 v = __half22float2(__ldg(hr + lane + 32 * q));
                acc[q].x = fmaf(v.x, ev, acc[q].x);
                acc[q].y = fmaf(v.y, ev, acc[q].y);
            }
        }
    }
#pragma unroll
    for (int o = 16; o; o >>= 1) den += __shfl_xor_sync(0xffffffffu, den, o);
    float inv = 1.f / (den + 1e-16f);

#pragma unroll
    for (int q = 0; q < 4; q++) {
        int c = 2 * (lane + 32 * q);
        float2 o;
        o.x = fmaxf(fmaf(acc[q].x, inv, 0.f) + __ldg(b2 + c),     0.f);
        o.y = fmaxf(fmaf(acc[q].y, inv, 0.f) + __ldg(b2 + c + 1), 0.f);
        *(float2*)&g_out2[(size_t)n * D2 + c] = o;
    }
}

// ---------------- GEMM ----------------
#define SMSTRIDE 80
#define TILE_B   (128 * SMSTRIDE)

template <int KT, int LDC, int NB, int AHEADS, bool FUSE>
__global__ __launch_bounds__(256, 2) void k_mma(
    const uint4* __restrict__ A1,
    const uint4* __restrict__ B1, const uint4* __restrict__ B2,
    __half* __restrict__ C, int M,
    const float* __restrict__ bias,
    const float* __restrict__ avs, const float* __restrict__ avd,
    float* __restrict__ als, float* __restrict__ ald)
{
    extern __shared__ char smem[];
    const uint32_t sbase = smem_u32(smem);
    const int tid = threadIdx.x, lane = tid & 31, wid = tid >> 5;
    const int wm = wid & 1, wn = wid >> 1;
    const int m0 = blockIdx.y * 128, n0 = blockIdx.x * 128;
    const int KW = KT * 4;
    const int AST = AHEADS * KW;
    const int head = (AHEADS == 1) ? 0 : (n0 >> 8);
    constexpr int NT = 1 + NB;

    float acc[4][4][4];
#pragma unroll
    for (int a = 0; a < 4; a++)
#pragma unroll
        for (int b = 0; b < 4; b++)
#pragma unroll
            for (int c = 0; c < 4; c++) acc[a][b][c] = 0.f;

    auto load_stage = [&](int ki, int s) {
        uint32_t sb = sbase + s * (NT * TILE_B);
#pragma unroll
        for (int i = 0; i < 2; i++) {
            int idx = tid + i * 256;
            int row = idx >> 2, ch = idx & 3;
            uint32_t soff = row * SMSTRIDE + ch * 16;
            int ar = min(m0 + row, M - 1);
            size_t ga = (size_t)ar * AST + head * KW + ki * 4 + ch;
            size_t gb = (size_t)(n0 + row) * KW + ki * 4 + ch;
            CP_ASYNC16(sb + soff,          A1 + ga);
            CP_ASYNC16(sb + TILE_B + soff, B1 + gb);
            if (NB == 2) CP_ASYNC16(sb + 2 * TILE_B + soff, B2 + gb);
        }
        CP_COMMIT();
    };

    load_stage(0, 0);

    for (int ki = 0; ki < KT; ki++) {
        if (ki + 1 < KT) load_stage(ki + 1, (ki + 1) & 1);
        if (ki + 1 < KT) CP_WAIT1(); else CP_WAIT0();
        __syncthreads();

        uint32_t sb  = sbase + (ki & 1) * (NT * TILE_B);
        uint32_t a1b = sb, b1b = sb + TILE_B, b2b = sb + 2 * TILE_B;

#pragma unroll
        for (int k16 = 0; k16 < 2; k16++) {
            uint32_t bf1[8], bf2[8];
#pragma unroll
            for (int g = 0; g < 2; g++) {
                int nrow = wn * 32 + g * 16 + (lane & 7) + ((lane >> 4) << 3);
                int kb   = k16 * 32 + (((lane >> 3) & 1) << 4);
                uint32_t ao = nrow * SMSTRIDE + kb;
                LDSM_X4(&bf1[g * 4], b1b + ao);
                if (NB == 2) LDSM_X4(&bf2[g * 4], b2b + ao);
            }
#pragma unroll
            for (int mt = 0; mt < 4; mt++) {
                int arow = wm * 64 + mt * 16 + (lane & 7) + (((lane >> 3) & 1) << 3);
                int kb   = k16 * 32 + ((lane >> 4) << 4);
                uint32_t ao = arow * SMSTRIDE + kb;
                uint32_t af[4];
                LDSM_X4(af, a1b + ao);
#pragma unroll
                for (int nt = 0; nt < 4; nt++) MMA_FP16(acc[mt][nt], af, &bf1[nt * 2]);
                if (NB == 2) {
#pragma unroll
                    for (int nt = 0; nt < 4; nt++) MMA_FP16(acc[mt][nt], af, &bf2[nt * 2]);
                }
            }
        }
        __syncthreads();
    }

    if (FUSE) {
        float bv[4][2], av_s[4][2], av_d[4][2];
#pragma unroll
        for (int nt = 0; nt < 4; nt++) {
            int c = n0 + wn * 32 + nt * 8 + (lane & 3) * 2;
            bv[nt][0]   = bias[c]; bv[nt][1]   = bias[c + 1];
            av_s[nt][0] = avs[c];  av_s[nt][1] = avs[c + 1];
            av_d[nt][0] = avd[c];  av_d[nt][1] = avd[c + 1];
        }
#pragma unroll
        for (int mt = 0; mt < 4; mt++) {
            int r = m0 + wm * 64 + mt * 16 + (lane >> 2);
            float s0 = 0.f, s1 = 0.f, d0 = 0.f, d1 = 0.f;
#pragma unroll
            for (int nt = 0; nt < 4; nt++) {
                int c = n0 + wn * 32 + nt * 8 + (lane & 3) * 2;
                float v0 = fmaxf(acc[mt][nt][0] + bv[nt][0], 0.f);
                float v1 = fmaxf(acc[mt][nt][1] + bv[nt][1], 0.f);
                float v2 = fmaxf(acc[mt][nt][2] + bv[nt][0], 0.f);
                float v3 = fmaxf(acc[mt][nt][3] + bv[nt][1], 0.f);
                if (r < M)
                    *(__half2*)&C[(size_t)r * LDC + c] = __floats2half2_rn(v0, v1);
                if (r + 8 < M)
                    *(__half2*)&C[(size_t)(r + 8) * LDC + c] = __floats2half2_rn(v2, v3);
                s0 = fmaf(v0, av_s[nt][0], fmaf(v1, av_s[nt][1], s0));
                s1 = fmaf(v2, av_s[nt][0], fmaf(v3, av_s[nt][1], s1));
                d0 = fmaf(v0, av_d[nt][0], fmaf(v1, av_d[nt][1], d0));
                d1 = fmaf(v2, av_d[nt][0], fmaf(v3, av_d[nt][1], d1));
            }
            s0 += __shfl_xor_sync(0xffffffffu, s0, 1); s0 += __shfl_xor_sync(0xffffffffu, s0, 2);
            s1 += __shfl_xor_sync(0xffffffffu, s1, 1); s1 += __shfl_xor_sync(0xffffffffu, s1, 2);
            d0 += __shfl_xor_sync(0xffffffffu, d0, 1); d0 += __shfl_xor_sync(0xffffffffu, d0, 2);
            d1 += __shfl_xor_sync(0xffffffffu, d1, 1); d1 += __shfl_xor_sync(0xffffffffu, d1, 2);
            if ((lane & 3) == 0) {
                if (r < M)     { atomicAdd(&als[r], s0);     atomicAdd(&ald[r], d0); }
                if (r + 8 < M) { atomicAdd(&als[r + 8], s1); atomicAdd(&ald[r + 8], d1); }
            }
        }
    } else {
#pragma unroll
        for (int mt = 0; mt < 4; mt++) {
            int r = m0 + wm * 64 + mt * 16 + (lane >> 2);
#pragma unroll
            for (int nt = 0; nt < 4; nt++) {
                int c = n0 + wn * 32 + nt * 8 + (lane & 3) * 2;
                if (r < M)
                    *(__half2*)&C[(size_t)r * LDC + c] = __floats2half2_rn(acc[mt][nt][0], acc[mt][nt][1]);
                if (r + 8 < M)
                    *(__half2*)&C[(size_t)(r + 8) * LDC + c] = __floats2half2_rn(acc[mt][nt][2], acc[mt][nt][3]);
            }
        }
    }
}

// ---------------- pool + FC ----------------
__device__ __forceinline__ int lower_bound_batch(const int* b32, int is64, int key) {
    int lo = 0, hi = N_NODES;
    while (lo < hi) {
        int mid = (lo + hi) >> 1;
        int v = is64 ? b32[2 * mid] : b32[mid];
        if (v < key) lo = mid + 1; else hi = mid;
    }
    return lo;
}
__global__ __launch_bounds__(256) void k_pool_fc(
    const int* __restrict__ batch32, const int* __restrict__ ei32,
    const float* __restrict__ fcW, const float* __restrict__ fcb,
    float* __restrict__ out)
{
    int g = blockIdx.x, t = threadIdx.x;
    __shared__ int s_lo, s_hi;
    __shared__ float pooled[D2];
    if (t == 0) {
        int is64 = detect_i64(ei32);
        s_lo = lower_bound_batch(batch32, is64, g);
        s_hi = lower_bound_batch(batch32, is64, g + 1);
    }
    __syncthreads();
    int lo = s_lo, hi = s_hi;
    float s = 0.f;
    for (int n = lo; n < hi; n++) s += g_out2[(size_t)n * D2 + t];
    float cnt = (float)(hi - lo);
    pooled[t] = s / fmaxf(cnt, 1.f);
    __syncthreads();
    if (t < OUT_DIM) {
        float acc = fcb[t];
        for (int d = 0; d < D2; d++) acc = fmaf(pooled[d], fcW[d * OUT_DIM + t], acc);
        out[g * OUT_DIM + t] = acc;
    }
}

// ---------------- launch ----------------
extern "C" void kernel_launch(void* const* d_in, const int* in_sizes, int n_in,
                              void* d_out, int out_size)
{
    const float* x      = (const float*)d_in[0];
    const int*   ei32   = (const int*)  d_in[1];
    const int*   bat32  = (const int*)  d_in[2];
    const float* W1     = (const float*)d_in[3];
    const float* a_src1 = (const float*)d_in[4];
    const float* a_dst1 = (const float*)d_in[5];
    const float* b1     = (const float*)d_in[6];
    const float* W2     = (const float*)d_in[7];
    const float* a_src2 = (const float*)d_in[8];
    const float* a_dst2 = (const float*)d_in[9];
    const float* b2     = (const float*)d_in[10];
    const float* fcW    = (const float*)d_in[11];
    const float* fcb    = (const float*)d_in[12];
    float* out = (float*)d_out;

    uint4 *xagg, *w1a, *w1b, *o1, *w2;
    __half *h2;
    float *als2, *ald2, *was2, *wad2;
    cudaGetSymbolAddress((void**)&xagg, g_xagg);
    cudaGetSymbolAddress((void**)&w1a,  g_w1a);
    cudaGetSymbolAddress((void**)&w1b,  g_w1b);
    cudaGetSymbolAddress((void**)&o1,   g_o1);
    cudaGetSymbolAddress((void**)&w2,   g_w2);
    cudaGetSymbolAddress((void**)&h2,   g_h2);
    cudaGetSymbolAddress((void**)&als2, g_als2);
    cudaGetSymbolAddress((void**)&ald2, g_ald2);
    cudaGetSymbolAddress((void**)&was2, g_was2);
    cudaGetSymbolAddress((void**)&wad2, g_wad2);

    const int SM1 = 2 * 3 * TILE_B;   // 61440
    const int SM2 = 2 * 2 * TILE_B;   // 40960
    cudaFuncSetAttribute((void*)k_mma<3, HD1, 2, H1, true>, cudaFuncAttributeMaxDynamicSharedMemorySize, SM1);
    cudaFuncSetAttribute((void*)k_mma<32, D2, 1, 1, false>, cudaFuncAttributeMaxDynamicSharedMemorySize, SM2);

    const int MT = (N_NODES + 127) / 128;   // 391

    k_setup  <<<SETUP_GRID, 256>>>(W1, W2, a_src1, a_dst1, a_src2, a_dst2);
    k_stage2 <<<STAGE2_GRID, 256>>>(x, ei32);
    k_scan   <<<1, 1024>>>();
    k_scatter<<<(E_TOT + 255) / 256, 256>>>();
    k_aggx   <<<(N_NODES * 32 + 255) / 256, 256>>>(x);

    // GEMM1': out1 = relu(xagg @ W1split + b1); fused als2/ald2
    k_mma<3, HD1, 2, H1, true><<<dim3(HD1 / 128, MT), 256, SM1>>>(
        xagg, w1a, w1b, (__half*)o1, N_NODES, b1, was2, wad2, als2, ald2);

    // GEMM2: h2 = out1 @ W2 (plain)
    k_mma<32, D2, 1, 1, false><<<dim3(D2 / 128, MT), 256, SM2>>>(
        o1, w2, w2, h2, N_NODES, b2, was2, wad2, als2, ald2);

    k_agg2<<<(N_NODES * 32 + 255) / 256, 256>>>(b2);

    k_pool_fc<<<N_GRAPHS, 256>>>(bat32, ei32, fcW, fcb, out);
}

// round 9
// speedup vs baseline: 4.3973x; 1.0317x over previous
#include <cuda_runtime.h>
#include <cuda_fp16.h>
#include <math.h>
#include <stdint.h>

// ---------------- problem constants ----------------
#define N_NODES 50000
#define N_EDGES 200000
#define E_TOT   (N_EDGES + N_NODES)   // 250000
#define F0      74
#define K1PAD   96
#define H1      4
#define D1      256
#define HD1     (H1 * D1)             // 1024
#define D2      256
#define N_GRAPHS 256
#define OUT_DIM 12
#define NEG_SLOPE 0.2f

// ---------------- scratch ----------------
__device__ __half g_h2 [(size_t)N_NODES * D2];
__device__ float  g_out2[(size_t)N_NODES * D2];
__device__ float g_als1[N_NODES * H1];
__device__ float g_ald1[N_NODES * H1];
__device__ float g_als2[N_NODES];
__device__ float g_ald2[N_NODES];
__device__ int   g_deg[N_NODES];
__device__ int   g_rowptr[N_NODES + 1];
__device__ int   g_cursor[N_NODES];
__device__ int   g_elist[E_TOT];
__device__ int   g_src[E_TOT];
__device__ int   g_dst[E_TOT];

// attention projection vectors
__device__ float g_was1[K1PAD * H1];
__device__ float g_wad1[K1PAD * H1];
__device__ float g_was2[HD1];
__device__ float g_wad2[HD1];

// GEMM operands (fp16, K-major, 16B-aligned)
__device__ uint4 g_xagg[(size_t)N_NODES * H1 * K1PAD / 8];
__device__ uint4 g_w1  [(size_t)HD1 * K1PAD / 8];
__device__ uint4 g_o1  [(size_t)N_NODES * HD1 / 8];
__device__ uint4 g_w2  [(size_t)D2 * HD1 / 8];

// ---------------- PTX helpers ----------------
__device__ __forceinline__ uint32_t smem_u32(const void* p) {
    uint32_t a;
    asm("{ .reg .u64 t; cvta.to.shared.u64 t, %1; cvt.u32.u64 %0, t; }" : "=r"(a) : "l"(p));
    return a;
}
#define CP_ASYNC16(dst, src) \
    asm volatile("cp.async.cg.shared.global [%0], [%1], 16;" :: "r"(dst), "l"(src))
#define CP_COMMIT() asm volatile("cp.async.commit_group;" ::: "memory")
#define CP_WAIT2()  asm volatile("cp.async.wait_group 2;" ::: "memory")

#define LDSM_X4(r, addr) \
    asm volatile("ldmatrix.sync.aligned.m8n8.x4.shared.b16 {%0,%1,%2,%3}, [%4];" \
        : "=r"((r)[0]), "=r"((r)[1]), "=r"((r)[2]), "=r"((r)[3]) : "r"(addr))

#define MMA_FP16(d, a, b) \
    asm volatile("mma.sync.aligned.m16n8k16.row.col.f32.f16.f16.f32 " \
        "{%0,%1,%2,%3}, {%4,%5,%6,%7}, {%8,%9}, {%0,%1,%2,%3};" \
        : "+f"((d)[0]), "+f"((d)[1]), "+f"((d)[2]), "+f"((d)[3]) \
        : "r"((a)[0]), "r"((a)[1]), "r"((a)[2]), "r"((a)[3]), "r"((b)[0]), "r"((b)[1]))

// ---------------- misc ----------------
__device__ __forceinline__ int detect_i64(const int* p) {
    return (p[1] | p[3] | p[5] | p[7]) == 0;
}
__device__ __forceinline__ float leaky(float v) { return v >= 0.f ? v : NEG_SLOPE * v; }

// ---------------- fused setup ----------------
#define PW1_B 384
#define PW2_B 1024
#define AV1_B 37
#define AV2_B 128
#define ZR_B  196
#define SETUP_GRID (PW1_B + PW2_B + AV1_B + AV2_B + ZR_B)

__global__ __launch_bounds__(256) void k_setup(
    const float* __restrict__ W1, const float* __restrict__ W2,
    const float* __restrict__ as1, const float* __restrict__ ad1,
    const float* __restrict__ as2, const float* __restrict__ ad2)
{
    int b = blockIdx.x, t = threadIdx.x, lane = t & 31;
    if (b < PW1_B) {
        int i = b * 256 + t;                       // [1024 n][96 k]
        if (i < HD1 * K1PAD) {
            int n = i / K1PAD, k = i - n * K1PAD;
            float v = (k < F0) ? W1[(size_t)k * HD1 + n] : 0.f;
            ((__half*)g_w1)[i] = __float2half_rn(v);
        }
    } else if (b < PW1_B + PW2_B) {
        int i = (b - PW1_B) * 256 + t;             // [256 n][1024 k]
        if (i < D2 * HD1) {
            int n = i >> 10, k = i & 1023;
            ((__half*)g_w2)[i] = __float2half_rn(W2[(size_t)k * D2 + n]);
        }
    } else if (b < PW1_B + PW2_B + AV1_B) {
        int w = ((b - PW1_B - PW2_B) * 256 + t) >> 5;
        if (w < F0 * H1) {
            int k = w >> 2, h = w & 3;
            float s = 0.f, d = 0.f;
            for (int j = lane; j < D1; j += 32) {
                float wv = W1[(size_t)k * HD1 + h * D1 + j];
                s = fmaf(wv, as1[h * D1 + j], s);
                d = fmaf(wv, ad1[h * D1 + j], d);
            }
#pragma unroll
            for (int o = 16; o; o >>= 1) {
                s += __shfl_xor_sync(0xffffffffu, s, o);
                d += __shfl_xor_sync(0xffffffffu, d, o);
            }
            if (lane == 0) { g_was1[k * 4 + h] = s; g_wad1[k * 4 + h] = d; }
        }
    } else if (b < PW1_B + PW2_B + AV1_B + AV2_B) {
        int w = ((b - PW1_B - PW2_B - AV1_B) * 256 + t) >> 5;
        if (w < HD1) {
            float s = 0.f, d = 0.f;
            for (int j = lane; j < D2; j += 32) {
                float wv = W2[(size_t)w * D2 + j];
                s = fmaf(wv, as2[j], s);
                d = fmaf(wv, ad2[j], d);
            }
#pragma unroll
            for (int o = 16; o; o >>= 1) {
                s += __shfl_xor_sync(0xffffffffu, s, o);
                d += __shfl_xor_sync(0xffffffffu, d, o);
            }
            if (lane == 0) { g_was2[w] = s; g_wad2[w] = d; }
        }
    } else {
        int i = (b - PW1_B - PW2_B - AV1_B - AV2_B) * 256 + t;
        if (i < N_NODES) {
            g_deg[i] = 0;
            g_als2[i] = 0.f;
            g_ald2[i] = 0.f;
        }
    }
}

// ---------------- stage2: layer-1 logits + edge decode ----------------
#define LG_B 6250
#define PE_B ((E_TOT + 255) / 256)
#define STAGE2_GRID (LG_B + PE_B)

__global__ __launch_bounds__(256) void k_stage2(const float* __restrict__ x,
                                                const int* __restrict__ ei32) {
    int b = blockIdx.x, t = threadIdx.x;
    if (b < LG_B) {
        int n = (b * 256 + t) >> 5;
        int lane = t & 31;
        if (n >= N_NODES) return;
        float4 s = make_float4(0, 0, 0, 0), d = make_float4(0, 0, 0, 0);
        for (int k = lane; k < F0; k += 32) {
            float xv = __ldg(&x[(size_t)n * F0 + k]);
            float4 a = *(const float4*)(g_was1 + k * 4);
            float4 bb = *(const float4*)(g_wad1 + k * 4);
            s.x = fmaf(xv, a.x, s.x);  s.y = fmaf(xv, a.y, s.y);
            s.z = fmaf(xv, a.z, s.z);  s.w = fmaf(xv, a.w, s.w);
            d.x = fmaf(xv, bb.x, d.x); d.y = fmaf(xv, bb.y, d.y);
            d.z = fmaf(xv, bb.z, d.z); d.w = fmaf(xv, bb.w, d.w);
        }
#pragma unroll
        for (int o = 16; o; o >>= 1) {
            s.x += __shfl_xor_sync(0xffffffffu, s.x, o);
            s.y += __shfl_xor_sync(0xffffffffu, s.y, o);
            s.z += __shfl_xor_sync(0xffffffffu, s.z, o);
            s.w += __shfl_xor_sync(0xffffffffu, s.w, o);
            d.x += __shfl_xor_sync(0xffffffffu, d.x, o);
            d.y += __shfl_xor_sync(0xffffffffu, d.y, o);
            d.z += __shfl_xor_sync(0xffffffffu, d.z, o);
            d.w += __shfl_xor_sync(0xffffffffu, d.w, o);
        }
        if (lane == 0) {
            *(float4*)(g_als1 + n * 4) = s;
            *(float4*)(g_ald1 + n * 4) = d;
        }
    } else {
        int e = (b - LG_B) * 256 + t;
        if (e >= E_TOT) return;
        int is64 = detect_i64(ei32);
        int s, d;
        if (e < N_EDGES) {
            s = is64 ? ei32[2 * (size_t)e]             : ei32[e];
            d = is64 ? ei32[2 * ((size_t)N_EDGES + e)] : ei32[N_EDGES + e];
        } else {
            s = d = e - N_EDGES;
        }
        g_src[e] = s;
        g_dst[e] = d;
        atomicAdd(&g_deg[d], 1);
    }
}

// ---------------- CSR scan (+ cursor init) ----------------
__global__ void k_scan() {
    __shared__ int sums[1024];
    int t = threadIdx.x;
    const int CH = (N_NODES + 1023) / 1024;
    int b = t * CH, e = min(b + CH, N_NODES);
    int s = 0;
    for (int i = b; i < e; i++) s += g_deg[i];
    sums[t] = s;
    __syncthreads();
    for (int off = 1; off < 1024; off <<= 1) {
        int v = (t >= off) ? sums[t - off] : 0;
        __syncthreads();
        sums[t] += v;
        __syncthreads();
    }
    int run = sums[t] - s;
    for (int i = b; i < e; i++) {
        g_rowptr[i] = run;
        g_cursor[i] = run;
        run += g_deg[i];
    }
    if (t == 1023) g_rowptr[N_NODES] = sums[1023];
}
__global__ void k_scatter() {
    int e = blockIdx.x * blockDim.x + threadIdx.x;
    if (e >= E_TOT) return;
    int p = atomicAdd(&g_cursor[g_dst[e]], 1);
    g_elist[p] = e;
}

// ---------------- layer-1 aggregate (warp/node, fused softmax) -------------
__global__ __launch_bounds__(256) void k_aggx(const float* __restrict__ x) {
    int n = (blockIdx.x * blockDim.x + threadIdx.x) >> 5;
    int lane = threadIdx.x & 31;
    if (n >= N_NODES) return;
    int start = g_rowptr[n], deg = g_rowptr[n + 1] - start;
    const float4 adn = *(const float4*)(g_ald1 + n * 4);

    float a[3][4];
#pragma unroll
    for (int g = 0; g < 3; g++)
#pragma unroll
        for (int h = 0; h < 4; h++) a[g][h] = 0.f;
    float4 den = make_float4(0, 0, 0, 0);

    for (int c0 = 0; c0 < deg; c0 += 32) {
        int j = c0 + lane;
        int srcj = 0;
        float4 e = make_float4(0, 0, 0, 0);
        if (j < deg) {
            int ed = g_elist[start + j];
            srcj = g_src[ed];
            float4 as = *(const float4*)(g_als1 + srcj * 4);
            e.x = expf(leaky(as.x + adn.x));
            e.y = expf(leaky(as.y + adn.y));
            e.z = expf(leaky(as.z + adn.z));
            e.w = expf(leaky(as.w + adn.w));
            den.x += e.x; den.y += e.y; den.z += e.z; den.w += e.w;
        }
        int cnt = min(32, deg - c0);
        for (int jj = 0; jj < cnt; jj++) {
            int s  = __shfl_sync(0xffffffffu, srcj, jj);
            float e0 = __shfl_sync(0xffffffffu, e.x, jj);
            float e1 = __shfl_sync(0xffffffffu, e.y, jj);
            float e2 = __shfl_sync(0xffffffffu, e.z, jj);
            float e3 = __shfl_sync(0xffffffffu, e.w, jj);
            const float* xr = x + (size_t)s * F0;
            float x0 = __ldg(xr + lane);
            float x1 = __ldg(xr + lane + 32);
            float x2 = (lane + 64 < F0) ? __ldg(xr + lane + 64) : 0.f;
            a[0][0] = fmaf(x0, e0, a[0][0]); a[0][1] = fmaf(x0, e1, a[0][1]);
            a[0][2] = fmaf(x0, e2, a[0][2]); a[0][3] = fmaf(x0, e3, a[0][3]);
            a[1][0] = fmaf(x1, e0, a[1][0]); a[1][1] = fmaf(x1, e1, a[1][1]);
            a[1][2] = fmaf(x1, e2, a[1][2]); a[1][3] = fmaf(x1, e3, a[1][3]);
            a[2][0] = fmaf(x2, e0, a[2][0]); a[2][1] = fmaf(x2, e1, a[2][1]);
            a[2][2] = fmaf(x2, e2, a[2][2]); a[2][3] = fmaf(x2, e3, a[2][3]);
        }
    }
#pragma unroll
    for (int o = 16; o; o >>= 1) {
        den.x += __shfl_xor_sync(0xffffffffu, den.x, o);
        den.y += __shfl_xor_sync(0xffffffffu, den.y, o);
        den.z += __shfl_xor_sync(0xffffffffu, den.z, o);
        den.w += __shfl_xor_sync(0xffffffffu, den.w, o);
    }
    float inv[4];
    inv[0] = 1.f / (den.x + 1e-16f);
    inv[1] = 1.f / (den.y + 1e-16f);
    inv[2] = 1.f / (den.z + 1e-16f);
    inv[3] = 1.f / (den.w + 1e-16f);

    __half* xa = (__half*)g_xagg + (size_t)n * (H1 * K1PAD);
#pragma unroll
    for (int g = 0; g < 3; g++) {
        int col = lane + 32 * g;
#pragma unroll
        for (int h = 0; h < 4; h++)
            xa[h * K1PAD + col] = __float2half_rn(a[g][h] * inv[h]);
    }
}

// ---------------- layer-2 aggregate (warp/node, fused softmax) -------------
__global__ __launch_bounds__(256) void k_agg2(const float* __restrict__ b2) {
    int n = (blockIdx.x * blockDim.x + threadIdx.x) >> 5;
    int lane = threadIdx.x & 31;
    if (n >= N_NODES) return;
    int start = g_rowptr[n], deg = g_rowptr[n + 1] - start;
    const float adn = g_ald2[n];

    float2 acc[4];
#pragma unroll
    for (int q = 0; q < 4; q++) acc[q] = make_float2(0.f, 0.f);
    float den = 0.f;

    for (int c0 = 0; c0 < deg; c0 += 32) {
        int j = c0 + lane;
        int srcj = 0;
        float e = 0.f;
        if (j < deg) {
            int ed = g_elist[start + j];
            srcj = g_src[ed];
            e = expf(leaky(g_als2[srcj] + adn));
            den += e;
        }
        int cnt = min(32, deg - c0);
        for (int jj = 0; jj < cnt; jj++) {
            int s   = __shfl_sync(0xffffffffu, srcj, jj);
            float ev = __shfl_sync(0xffffffffu, e, jj);
            const __half2* hr = (const __half2*)(g_h2 + (size_t)s * D2);
#pragma unroll
            for (int q = 0; q < 4; q++) {
                float2 v = __half22float2(__ldg(hr + lane + 32 * q));
                acc[q].x = fmaf(v.x, ev, acc[q].x);
                acc[q].y = fmaf(v.y, ev, acc[q].y);
            }
        }
    }
#pragma unroll
    for (int o = 16; o; o >>= 1) den += __shfl_xor_sync(0xffffffffu, den, o);
    float inv = 1.f / (den + 1e-16f);

#pragma unroll
    for (int q = 0; q < 4; q++) {
        int c = 2 * (lane + 32 * q);
        float2 o;
        o.x = fmaxf(fmaf(acc[q].x, inv, 0.f) + __ldg(b2 + c),     0.f);
        o.y = fmaxf(fmaf(acc[q].y, inv, 0.f) + __ldg(b2 + c + 1), 0.f);
        *(float2*)&g_out2[(size_t)n * D2 + c] = o;
    }
}

// ---------------- GEMM: fp16 single-term, 3-stage cp.async ----------------
#define SMSTRIDE 80
#define TILE_B   (128 * SMSTRIDE)
#define GM_SMEM  (3 * 2 * TILE_B)     // 61440 B

template <int KT, int LDC, int AHEADS, bool FUSE>
__global__ __launch_bounds__(256, 2) void k_mma(
    const uint4* __restrict__ A1, const uint4* __restrict__ B1,
    __half* __restrict__ C, int M,
    const float* __restrict__ bias,
    const float* __restrict__ avs, const float* __restrict__ avd,
    float* __restrict__ als, float* __restrict__ ald)
{
    extern __shared__ char smem[];
    const uint32_t sbase = smem_u32(smem);
    const int tid = threadIdx.x, lane = tid & 31, wid = tid >> 5;
    const int wm = wid & 1, wn = wid >> 1;
    const int m0 = blockIdx.y * 128, n0 = blockIdx.x * 128;
    const int KW = KT * 4;
    const int AST = AHEADS * KW;
    const int head = (AHEADS == 1) ? 0 : (n0 >> 8);

    float acc[4][4][4];
#pragma unroll
    for (int a = 0; a < 4; a++)
#pragma unroll
        for (int b = 0; b < 4; b++)
#pragma unroll
            for (int c = 0; c < 4; c++) acc[a][b][c] = 0.f;

    auto load_stage = [&](int ki, int s) {
        uint32_t sb = sbase + s * (2 * TILE_B);
#pragma unroll
        for (int i = 0; i < 2; i++) {
            int idx = tid + i * 256;
            int row = idx >> 2, ch = idx & 3;
            uint32_t soff = row * SMSTRIDE + ch * 16;
            int ar = min(m0 + row, M - 1);
            size_t ga = (size_t)ar * AST + head * KW + ki * 4 + ch;
            size_t gb = (size_t)(n0 + row) * KW + ki * 4 + ch;
            CP_ASYNC16(sb + soff,          A1 + ga);
            CP_ASYNC16(sb + TILE_B + soff, B1 + gb);
        }
    };

    load_stage(0, 0); CP_COMMIT();
    if (KT > 1) load_stage(1, 1);
    CP_COMMIT();

    for (int ki = 0; ki < KT; ki++) {
        if (ki + 2 < KT) load_stage(ki + 2, (ki + 2) % 3);
        CP_COMMIT();
        CP_WAIT2();
        __syncthreads();

        uint32_t sb  = sbase + (ki % 3) * (2 * TILE_B);
        uint32_t a1b = sb, b1b = sb + TILE_B;

#pragma unroll
        for (int k16 = 0; k16 < 2; k16++) {
            uint32_t bf1[8];
#pragma unroll
            for (int g = 0; g < 2; g++) {
                int nrow = wn * 32 + g * 16 + (lane & 7) + ((lane >> 4) << 3);
                int kb   = k16 * 32 + (((lane >> 3) & 1) << 4);
                LDSM_X4(&bf1[g * 4], b1b + nrow * SMSTRIDE + kb);
            }
#pragma unroll
            for (int mt = 0; mt < 4; mt++) {
                int arow = wm * 64 + mt * 16 + (lane & 7) + (((lane >> 3) & 1) << 3);
                int kb   = k16 * 32 + ((lane >> 4) << 4);
                uint32_t af[4];
                LDSM_X4(af, a1b + arow * SMSTRIDE + kb);
#pragma unroll
                for (int nt = 0; nt < 4; nt++) MMA_FP16(acc[mt][nt], af, &bf1[nt * 2]);
            }
        }
        __syncthreads();
    }

    if (FUSE) {
        float bv[4][2], av_s[4][2], av_d[4][2];
#pragma unroll
        for (int nt = 0; nt < 4; nt++) {
            int c = n0 + wn * 32 + nt * 8 + (lane & 3) * 2;
            bv[nt][0]   = bias[c]; bv[nt][1]   = bias[c + 1];
            av_s[nt][0] = avs[c];  av_s[nt][1] = avs[c + 1];
            av_d[nt][0] = avd[c];  av_d[nt][1] = avd[c + 1];
        }
#pragma unroll
        for (int mt = 0; mt < 4; mt++) {
            int r = m0 + wm * 64 + mt * 16 + (lane >> 2);
            float s0 = 0.f, s1 = 0.f, d0 = 0.f, d1 = 0.f;
#pragma unroll
            for (int nt = 0; nt < 4; nt++) {
                int c = n0 + wn * 32 + nt * 8 + (lane & 3) * 2;
                float v0 = fmaxf(acc[mt][nt][0] + bv[nt][0], 0.f);
                float v1 = fmaxf(acc[mt][nt][1] + bv[nt][1], 0.f);
                float v2 = fmaxf(acc[mt][nt][2] + bv[nt][0], 0.f);
                float v3 = fmaxf(acc[mt][nt][3] + bv[nt][1], 0.f);
                if (r < M)
                    *(__half2*)&C[(size_t)r * LDC + c] = __floats2half2_rn(v0, v1);
                if (r + 8 < M)
                    *(__half2*)&C[(size_t)(r + 8) * LDC + c] = __floats2half2_rn(v2, v3);
                s0 = fmaf(v0, av_s[nt][0], fmaf(v1, av_s[nt][1], s0));
                s1 = fmaf(v2, av_s[nt][0], fmaf(v3, av_s[nt][1], s1));
                d0 = fmaf(v0, av_d[nt][0], fmaf(v1, av_d[nt][1], d0));
                d1 = fmaf(v2, av_d[nt][0], fmaf(v3, av_d[nt][1], d1));
            }
            s0 += __shfl_xor_sync(0xffffffffu, s0, 1); s0 += __shfl_xor_sync(0xffffffffu, s0, 2);
            s1 += __shfl_xor_sync(0xffffffffu, s1, 1); s1 += __shfl_xor_sync(0xffffffffu, s1, 2);
            d0 += __shfl_xor_sync(0xffffffffu, d0, 1); d0 += __shfl_xor_sync(0xffffffffu, d0, 2);
            d1 += __shfl_xor_sync(0xffffffffu, d1, 1); d1 += __shfl_xor_sync(0xffffffffu, d1, 2);
            if ((lane & 3) == 0) {
                if (r < M)     { atomicAdd(&als[r], s0);     atomicAdd(&ald[r], d0); }
                if (r + 8 < M) { atomicAdd(&als[r + 8], s1); atomicAdd(&ald[r + 8], d1); }
            }
        }
    } else {
#pragma unroll
        for (int mt = 0; mt < 4; mt++) {
            int r = m0 + wm * 64 + mt * 16 + (lane >> 2);
#pragma unroll
            for (int nt = 0; nt < 4; nt++) {
                int c = n0 + wn * 32 + nt * 8 + (lane & 3) * 2;
                if (r < M)
                    *(__half2*)&C[(size_t)r * LDC + c] = __floats2half2_rn(acc[mt][nt][0], acc[mt][nt][1]);
                if (r + 8 < M)
                    *(__half2*)&C[(size_t)(r + 8) * LDC + c] = __floats2half2_rn(acc[mt][nt][2], acc[mt][nt][3]);
            }
        }
    }
}

// ---------------- pool + FC ----------------
__device__ __forceinline__ int lower_bound_batch(const int* b32, int is64, int key) {
    int lo = 0, hi = N_NODES;
    while (lo < hi) {
        int mid = (lo + hi) >> 1;
        int v = is64 ? b32[2 * mid] : b32[mid];
        if (v < key) lo = mid + 1; else hi = mid;
    }
    return lo;
}
__global__ __launch_bounds__(256) void k_pool_fc(
    const int* __restrict__ batch32, const int* __restrict__ ei32,
    const float* __restrict__ fcW, const float* __restrict__ fcb,
    float* __restrict__ out)
{
    int g = blockIdx.x, t = threadIdx.x;
    __shared__ int s_lo, s_hi;
    __shared__ float pooled[D2];
    if (t == 0) {
        int is64 = detect_i64(ei32);
        s_lo = lower_bound_batch(batch32, is64, g);
        s_hi = lower_bound_batch(batch32, is64, g + 1);
    }
    __syncthreads();
    int lo = s_lo, hi = s_hi;
    float s = 0.f;
    for (int n = lo; n < hi; n++) s += g_out2[(size_t)n * D2 + t];
    float cnt = (float)(hi - lo);
    pooled[t] = s / fmaxf(cnt, 1.f);
    __syncthreads();
    if (t < OUT_DIM) {
        float acc = fcb[t];
        for (int d = 0; d < D2; d++) acc = fmaf(pooled[d], fcW[d * OUT_DIM + t], acc);
        out[g * OUT_DIM + t] = acc;
    }
}

// ---------------- launch ----------------
extern "C" void kernel_launch(void* const* d_in, const int* in_sizes, int n_in,
                              void* d_out, int out_size)
{
    const float* x      = (const float*)d_in[0];
    const int*   ei32   = (const int*)  d_in[1];
    const int*   bat32  = (const int*)  d_in[2];
    const float* W1     = (const float*)d_in[3];
    const float* a_src1 = (const float*)d_in[4];
    const float* a_dst1 = (const float*)d_in[5];
    const float* b1     = (const float*)d_in[6];
    const float* W2     = (const float*)d_in[7];
    const float* a_src2 = (const float*)d_in[8];
    const float* a_dst2 = (const float*)d_in[9];
    const float* b2     = (const float*)d_in[10];
    const float* fcW    = (const float*)d_in[11];
    const float* fcb    = (const float*)d_in[12];
    float* out = (float*)d_out;

    uint4 *xagg, *w1, *o1, *w2;
    __half *h2;
    float *als2, *ald2, *was2, *wad2;
    cudaGetSymbolAddress((void**)&xagg, g_xagg);
    cudaGetSymbolAddress((void**)&w1,   g_w1);
    cudaGetSymbolAddress((void**)&o1,   g_o1);
    cudaGetSymbolAddress((void**)&w2,   g_w2);
    cudaGetSymbolAddress((void**)&h2,   g_h2);
    cudaGetSymbolAddress((void**)&als2, g_als2);
    cudaGetSymbolAddress((void**)&ald2, g_ald2);
    cudaGetSymbolAddress((void**)&was2, g_was2);
    cudaGetSymbolAddress((void**)&wad2, g_wad2);

    cudaFuncSetAttribute((void*)k_mma<3, HD1, H1, true>, cudaFuncAttributeMaxDynamicSharedMemorySize, GM_SMEM);
    cudaFuncSetAttribute((void*)k_mma<32, D2, 1, false>, cudaFuncAttributeMaxDynamicSharedMemorySize, GM_SMEM);

    const int MT = (N_NODES + 127) / 128;   // 391

    k_setup  <<<SETUP_GRID, 256>>>(W1, W2, a_src1, a_dst1, a_src2, a_dst2);
    k_stage2 <<<STAGE2_GRID, 256>>>(x, ei32);
    k_scan   <<<1, 1024>>>();
    k_scatter<<<(E_TOT + 255) / 256, 256>>>();
    k_aggx   <<<(N_NODES * 32 + 255) / 256, 256>>>(x);

    // GEMM1': out1 = relu(xagg @ W1 + b1); fused als2/ald2
    k_mma<3, HD1, H1, true><<<dim3(HD1 / 128, MT), 256, GM_SMEM>>>(
        xagg, w1, (__half*)o1, N_NODES, b1, was2, wad2, als2, ald2);

    // GEMM2: h2 = out1 @ W2
    k_mma<32, D2, 1, false><<<dim3(D2 / 128, MT), 256, GM_SMEM>>>(
        o1, w2, h2, N_NODES, b2, was2, wad2, als2, ald2);

    k_agg2<<<(N_NODES * 32 + 255) / 256, 256>>>(b2);

    k_pool_fc<<<N_GRAPHS, 256>>>(bat32, ei32, fcW, fcb, out);
}

// round 10
// speedup vs baseline: 4.4943x; 1.0221x over previous
#include <cuda_runtime.h>
#include <cuda_fp16.h>
#include <math.h>
#include <stdint.h>

// ---------------- problem constants ----------------
#define N_NODES 50000
#define N_EDGES 200000
#define E_TOT   (N_EDGES + N_NODES)   // 250000
#define F0      74
#define K1PAD   96
#define H1      4
#define D1      256
#define HD1     (H1 * D1)             // 1024
#define D2      256
#define N_GRAPHS 256
#define OUT_DIM 12
#define NEG_SLOPE 0.2f

// ---------------- scratch ----------------
__device__ __half g_h2 [(size_t)N_NODES * D2];
__device__ float  g_out2[(size_t)N_NODES * D2];
__device__ float g_als1[N_NODES * H1];
__device__ float g_ald1[N_NODES * H1];
__device__ float g_als2[N_NODES];
__device__ float g_ald2[N_NODES];
__device__ int   g_deg[N_NODES];
__device__ int   g_rowptr[N_NODES + 1];
__device__ int   g_cursor[N_NODES];
__device__ int   g_elist[E_TOT];
__device__ int   g_src[E_TOT];
__device__ int   g_dst[E_TOT];

// attention projection vectors
__device__ float g_was1[K1PAD * H1];
__device__ float g_wad1[K1PAD * H1];
__device__ float g_was2[HD1];
__device__ float g_wad2[HD1];

// GEMM operands (fp16, K-major, 16B-aligned)
__device__ uint4 g_xagg[(size_t)N_NODES * H1 * K1PAD / 8];
__device__ uint4 g_w1  [(size_t)HD1 * K1PAD / 8];
__device__ uint4 g_o1  [(size_t)N_NODES * HD1 / 8];
__device__ uint4 g_w2  [(size_t)D2 * HD1 / 8];

// ---------------- PTX helpers ----------------
__device__ __forceinline__ uint32_t smem_u32(const void* p) {
    uint32_t a;
    asm("{ .reg .u64 t; cvta.to.shared.u64 t, %1; cvt.u32.u64 %0, t; }" : "=r"(a) : "l"(p));
    return a;
}
#define CP_ASYNC16(dst, src) \
    asm volatile("cp.async.cg.shared.global [%0], [%1], 16;" :: "r"(dst), "l"(src))
#define CP_COMMIT() asm volatile("cp.async.commit_group;" ::: "memory")
#define CP_WAIT1()  asm volatile("cp.async.wait_group 1;" ::: "memory")
#define CP_WAIT3()  asm volatile("cp.async.wait_group 3;" ::: "memory")

#define LDSM_X4(r, addr) \
    asm volatile("ldmatrix.sync.aligned.m8n8.x4.shared.b16 {%0,%1,%2,%3}, [%4];" \
        : "=r"((r)[0]), "=r"((r)[1]), "=r"((r)[2]), "=r"((r)[3]) : "r"(addr))

#define MMA_FP16(d, a, b) \
    asm volatile("mma.sync.aligned.m16n8k16.row.col.f32.f16.f16.f32 " \
        "{%0,%1,%2,%3}, {%4,%5,%6,%7}, {%8,%9}, {%0,%1,%2,%3};" \
        : "+f"((d)[0]), "+f"((d)[1]), "+f"((d)[2]), "+f"((d)[3]) \
        : "r"((a)[0]), "r"((a)[1]), "r"((a)[2]), "r"((a)[3]), "r"((b)[0]), "r"((b)[1]))

// ---------------- misc ----------------
__device__ __forceinline__ int detect_i64(const int* p) {
    return (p[1] | p[3] | p[5] | p[7]) == 0;
}
__device__ __forceinline__ float leaky(float v) { return v >= 0.f ? v : NEG_SLOPE * v; }

// ---------------- fused setup ----------------
#define PW1_B 384
#define PW2_B 1024
#define AV1_B 37
#define AV2_B 128
#define ZR_B  196
#define SETUP_GRID (PW1_B + PW2_B + AV1_B + AV2_B + ZR_B)

__global__ __launch_bounds__(256) void k_setup(
    const float* __restrict__ W1, const float* __restrict__ W2,
    const float* __restrict__ as1, const float* __restrict__ ad1,
    const float* __restrict__ as2, const float* __restrict__ ad2)
{
    int b = blockIdx.x, t = threadIdx.x, lane = t & 31;
    if (b < PW1_B) {
        int i = b * 256 + t;
        if (i < HD1 * K1PAD) {
            int n = i / K1PAD, k = i - n * K1PAD;
            float v = (k < F0) ? W1[(size_t)k * HD1 + n] : 0.f;
            ((__half*)g_w1)[i] = __float2half_rn(v);
        }
    } else if (b < PW1_B + PW2_B) {
        int i = (b - PW1_B) * 256 + t;
        if (i < D2 * HD1) {
            int n = i >> 10, k = i & 1023;
            ((__half*)g_w2)[i] = __float2half_rn(W2[(size_t)k * D2 + n]);
        }
    } else if (b < PW1_B + PW2_B + AV1_B) {
        int w = ((b - PW1_B - PW2_B) * 256 + t) >> 5;
        if (w < F0 * H1) {
            int k = w >> 2, h = w & 3;
            float s = 0.f, d = 0.f;
            for (int j = lane; j < D1; j += 32) {
                float wv = W1[(size_t)k * HD1 + h * D1 + j];
                s = fmaf(wv, as1[h * D1 + j], s);
                d = fmaf(wv, ad1[h * D1 + j], d);
            }
#pragma unroll
            for (int o = 16; o; o >>= 1) {
                s += __shfl_xor_sync(0xffffffffu, s, o);
                d += __shfl_xor_sync(0xffffffffu, d, o);
            }
            if (lane == 0) { g_was1[k * 4 + h] = s; g_wad1[k * 4 + h] = d; }
        }
    } else if (b < PW1_B + PW2_B + AV1_B + AV2_B) {
        int w = ((b - PW1_B - PW2_B - AV1_B) * 256 + t) >> 5;
        if (w < HD1) {
            float s = 0.f, d = 0.f;
            for (int j = lane; j < D2; j += 32) {
                float wv = W2[(size_t)w * D2 + j];
                s = fmaf(wv, as2[j], s);
                d = fmaf(wv, ad2[j], d);
            }
#pragma unroll
            for (int o = 16; o; o >>= 1) {
                s += __shfl_xor_sync(0xffffffffu, s, o);
                d += __shfl_xor_sync(0xffffffffu, d, o);
            }
            if (lane == 0) { g_was2[w] = s; g_wad2[w] = d; }
        }
    } else {
        int i = (b - PW1_B - PW2_B - AV1_B - AV2_B) * 256 + t;
        if (i < N_NODES) {
            g_deg[i] = 0;
            g_als2[i] = 0.f;
            g_ald2[i] = 0.f;
        }
    }
}

// ---------------- stage2: layer-1 logits + edge decode ----------------
#define LG_B 6250
#define PE_B ((E_TOT + 255) / 256)
#define STAGE2_GRID (LG_B + PE_B)

__global__ __launch_bounds__(256) void k_stage2(const float* __restrict__ x,
                                                const int* __restrict__ ei32) {
    int b = blockIdx.x, t = threadIdx.x;
    if (b < LG_B) {
        int n = (b * 256 + t) >> 5;
        int lane = t & 31;
        if (n >= N_NODES) return;
        float4 s = make_float4(0, 0, 0, 0), d = make_float4(0, 0, 0, 0);
        for (int k = lane; k < F0; k += 32) {
            float xv = __ldg(&x[(size_t)n * F0 + k]);
            float4 a = *(const float4*)(g_was1 + k * 4);
            float4 bb = *(const float4*)(g_wad1 + k * 4);
            s.x = fmaf(xv, a.x, s.x);  s.y = fmaf(xv, a.y, s.y);
            s.z = fmaf(xv, a.z, s.z);  s.w = fmaf(xv, a.w, s.w);
            d.x = fmaf(xv, bb.x, d.x); d.y = fmaf(xv, bb.y, d.y);
            d.z = fmaf(xv, bb.z, d.z); d.w = fmaf(xv, bb.w, d.w);
        }
#pragma unroll
        for (int o = 16; o; o >>= 1) {
            s.x += __shfl_xor_sync(0xffffffffu, s.x, o);
            s.y += __shfl_xor_sync(0xffffffffu, s.y, o);
            s.z += __shfl_xor_sync(0xffffffffu, s.z, o);
            s.w += __shfl_xor_sync(0xffffffffu, s.w, o);
            d.x += __shfl_xor_sync(0xffffffffu, d.x, o);
            d.y += __shfl_xor_sync(0xffffffffu, d.y, o);
            d.z += __shfl_xor_sync(0xffffffffu, d.z, o);
            d.w += __shfl_xor_sync(0xffffffffu, d.w, o);
        }
        if (lane == 0) {
            *(float4*)(g_als1 + n * 4) = s;
            *(float4*)(g_ald1 + n * 4) = d;
        }
    } else {
        int e = (b - LG_B) * 256 + t;
        if (e >= E_TOT) return;
        int is64 = detect_i64(ei32);
        int s, d;
        if (e < N_EDGES) {
            s = is64 ? ei32[2 * (size_t)e]             : ei32[e];
            d = is64 ? ei32[2 * ((size_t)N_EDGES + e)] : ei32[N_EDGES + e];
        } else {
            s = d = e - N_EDGES;
        }
        g_src[e] = s;
        g_dst[e] = d;
        atomicAdd(&g_deg[d], 1);
    }
}

// ---------------- CSR scan (+ cursor init) ----------------
__global__ void k_scan() {
    __shared__ int sums[1024];
    int t = threadIdx.x;
    const int CH = (N_NODES + 1023) / 1024;
    int b = t * CH, e = min(b + CH, N_NODES);
    int s = 0;
    for (int i = b; i < e; i++) s += g_deg[i];
    sums[t] = s;
    __syncthreads();
    for (int off = 1; off < 1024; off <<= 1) {
        int v = (t >= off) ? sums[t - off] : 0;
        __syncthreads();
        sums[t] += v;
        __syncthreads();
    }
    int run = sums[t] - s;
    for (int i = b; i < e; i++) {
        g_rowptr[i] = run;
        g_cursor[i] = run;
        run += g_deg[i];
    }
    if (t == 1023) g_rowptr[N_NODES] = sums[1023];
}
__global__ void k_scatter() {
    int e = blockIdx.x * blockDim.x + threadIdx.x;
    if (e >= E_TOT) return;
    int p = atomicAdd(&g_cursor[g_dst[e]], 1);
    g_elist[p] = e;
}

// ---------------- layer-1 aggregate (warp/node, fused softmax) -------------
__global__ __launch_bounds__(256) void k_aggx(const float* __restrict__ x) {
    int n = (blockIdx.x * blockDim.x + threadIdx.x) >> 5;
    int lane = threadIdx.x & 31;
    if (n >= N_NODES) return;
    int start = g_rowptr[n], deg = g_rowptr[n + 1] - start;
    const float4 adn = *(const float4*)(g_ald1 + n * 4);

    float a[3][4];
#pragma unroll
    for (int g = 0; g < 3; g++)
#pragma unroll
        for (int h = 0; h < 4; h++) a[g][h] = 0.f;
    float4 den = make_float4(0, 0, 0, 0);

    for (int c0 = 0; c0 < deg; c0 += 32) {
        int j = c0 + lane;
        int srcj = 0;
        float4 e = make_float4(0, 0, 0, 0);
        if (j < deg) {
            int ed = g_elist[start + j];
            srcj = g_src[ed];
            float4 as = *(const float4*)(g_als1 + srcj * 4);
            e.x = expf(leaky(as.x + adn.x));
            e.y = expf(leaky(as.y + adn.y));
            e.z = expf(leaky(as.z + adn.z));
            e.w = expf(leaky(as.w + adn.w));
            den.x += e.x; den.y += e.y; den.z += e.z; den.w += e.w;
        }
        int cnt = min(32, deg - c0);
        for (int jj = 0; jj < cnt; jj++) {
            int s  = __shfl_sync(0xffffffffu, srcj, jj);
            float e0 = __shfl_sync(0xffffffffu, e.x, jj);
            float e1 = __shfl_sync(0xffffffffu, e.y, jj);
            float e2 = __shfl_sync(0xffffffffu, e.z, jj);
            float e3 = __shfl_sync(0xffffffffu, e.w, jj);
            const float* xr = x + (size_t)s * F0;
            float x0 = __ldg(xr + lane);
            float x1 = __ldg(xr + lane + 32);
            float x2 = (lane + 64 < F0) ? __ldg(xr + lane + 64) : 0.f;
            a[0][0] = fmaf(x0, e0, a[0][0]); a[0][1] = fmaf(x0, e1, a[0][1]);
            a[0][2] = fmaf(x0, e2, a[0][2]); a[0][3] = fmaf(x0, e3, a[0][3]);
            a[1][0] = fmaf(x1, e0, a[1][0]); a[1][1] = fmaf(x1, e1, a[1][1]);
            a[1][2] = fmaf(x1, e2, a[1][2]); a[1][3] = fmaf(x1, e3, a[1][3]);
            a[2][0] = fmaf(x2, e0, a[2][0]); a[2][1] = fmaf(x2, e1, a[2][1]);
            a[2][2] = fmaf(x2, e2, a[2][2]); a[2][3] = fmaf(x2, e3, a[2][3]);
        }
    }
#pragma unroll
    for (int o = 16; o; o >>= 1) {
        den.x += __shfl_xor_sync(0xffffffffu, den.x, o);
        den.y += __shfl_xor_sync(0xffffffffu, den.y, o);
        den.z += __shfl_xor_sync(0xffffffffu, den.z, o);
        den.w += __shfl_xor_sync(0xffffffffu, den.w, o);
    }
    float inv[4];
    inv[0] = 1.f / (den.x + 1e-16f);
    inv[1] = 1.f / (den.y + 1e-16f);
    inv[2] = 1.f / (den.z + 1e-16f);
    inv[3] = 1.f / (den.w + 1e-16f);

    __half* xa = (__half*)g_xagg + (size_t)n * (H1 * K1PAD);
#pragma unroll
    for (int g = 0; g < 3; g++) {
        int col = lane + 32 * g;
#pragma unroll
        for (int h = 0; h < 4; h++)
            xa[h * K1PAD + col] = __float2half_rn(a[g][h] * inv[h]);
    }
}

// ---------------- layer-2 aggregate (warp/node, fused softmax) -------------
__global__ __launch_bounds__(256) void k_agg2(const float* __restrict__ b2) {
    int n = (blockIdx.x * blockDim.x + threadIdx.x) >> 5;
    int lane = threadIdx.x & 31;
    if (n >= N_NODES) return;
    int start = g_rowptr[n], deg = g_rowptr[n + 1] - start;
    const float adn = g_ald2[n];

    float2 acc[4];
#pragma unroll
    for (int q = 0; q < 4; q++) acc[q] = make_float2(0.f, 0.f);
    float den = 0.f;

    for (int c0 = 0; c0 < deg; c0 += 32) {
        int j = c0 + lane;
        int srcj = 0;
        float e = 0.f;
        if (j < deg) {
            int ed = g_elist[start + j];
            srcj = g_src[ed];
            e = expf(leaky(g_als2[srcj] + adn));
            den += e;
        }
        int cnt = min(32, deg - c0);
        for (int jj = 0; jj < cnt; jj++) {
            int s   = __shfl_sync(0xffffffffu, srcj, jj);
            float ev = __shfl_sync(0xffffffffu, e, jj);
            const __half2* hr = (const __half2*)(g_h2 + (size_t)s * D2);
#pragma unroll
            for (int q = 0; q < 4; q++) {
                float2 v = __half22float2(__ldg(hr + lane + 32 * q));
                acc[q].x = fmaf(v.x, ev, acc[q].x);
                acc[q].y = fmaf(v.y, ev, acc[q].y);
            }
        }
    }
#pragma unroll
    for (int o = 16; o; o >>= 1) den += __shfl_xor_sync(0xffffffffu, den, o);
    float inv = 1.f / (den + 1e-16f);

#pragma unroll
    for (int q = 0; q < 4; q++) {
        int c = 2 * (lane + 32 * q);
        float2 o;
        o.x = fmaxf(fmaf(acc[q].x, inv, 0.f) + __ldg(b2 + c),     0.f);
        o.y = fmaxf(fmaf(acc[q].y, inv, 0.f) + __ldg(b2 + c + 1), 0.f);
        *(float2*)&g_out2[(size_t)n * D2 + c] = o;
    }
}

// ---------------- GEMM tiles ----------------
#define SMSTRIDE 80
#define TILE_B   (128 * SMSTRIDE)     // 10240 B per 128x32 fp16 chunk tile

// ================= GEMM1: persistent B-stationary =================
// B tile (128 N-rows x 96 K) resident in smem; each CTA streams MT1 M-tiles.
#define MT1 8
#define GB1_Y 49                       // 49*8 = 392 >= 391 tiles
#define GM1_SMEM (3 * TILE_B + 2 * 3 * TILE_B)    // 92160 B

__global__ __launch_bounds__(256, 2) void k_mma1(
    const uint4* __restrict__ A1, const uint4* __restrict__ B1,
    __half* __restrict__ C, int M,
    const float* __restrict__ bias,
    const float* __restrict__ avs, const float* __restrict__ avd,
    float* __restrict__ als, float* __restrict__ ald)
{
    extern __shared__ char smem[];
    const uint32_t sbase = smem_u32(smem);
    const uint32_t abase = sbase + 3 * TILE_B;
    const int tid = threadIdx.x, lane = tid & 31, wid = tid >> 5;
    const int wm = wid & 1, wn = wid >> 1;
    const int n0 = blockIdx.x * 128;
    const int head = n0 >> 8;
    const int tile0 = blockIdx.y * MT1;
    const int KW = 12;                 // uint4 per head-row (96 fp16)
    const int AST = H1 * KW;           // 48

    // hoisted epilogue constants (per CTA column set)
    float bv[4][2], av_s[4][2], av_d[4][2];
#pragma unroll
    for (int nt = 0; nt < 4; nt++) {
        int c = n0 + wn * 32 + nt * 8 + (lane & 3) * 2;
        bv[nt][0]   = bias[c]; bv[nt][1]   = bias[c + 1];
        av_s[nt][0] = avs[c];  av_s[nt][1] = avs[c + 1];
        av_d[nt][0] = avd[c];  av_d[nt][1] = avd[c + 1];
    }

    auto load_A = [&](int tile, int s) {
        uint32_t sb = abase + s * (3 * TILE_B);
        int m0 = tile * 128;
#pragma unroll
        for (int i = 0; i < 6; i++) {
            int idx = tid + i * 256;               // 0..1535
            int chunk = idx / 512, rem = idx & 511;
            int row = rem >> 2, ch = rem & 3;
            int ar = min(m0 + row, M - 1);
            CP_ASYNC16(sb + chunk * TILE_B + row * SMSTRIDE + ch * 16,
                       A1 + (size_t)ar * AST + head * KW + chunk * 4 + ch);
        }
    };

    // prologue: group0 = B (full 3 chunks) + A(tile0)
#pragma unroll
    for (int i = 0; i < 6; i++) {
        int idx = tid + i * 256;
        int chunk = idx / 512, rem = idx & 511;
        int row = rem >> 2, ch = rem & 3;
        CP_ASYNC16(sbase + chunk * TILE_B + row * SMSTRIDE + ch * 16,
                   B1 + (size_t)(n0 + row) * KW + chunk * 4 + ch);
    }
    load_A(tile0, 0);
    CP_COMMIT();

    for (int g = 0; g < MT1; g++) {
        if (g + 1 < MT1) load_A(tile0 + g + 1, (g + 1) & 1);
        CP_COMMIT();
        CP_WAIT1();
        __syncthreads();

        float acc[4][4][4];
#pragma unroll
        for (int a = 0; a < 4; a++)
#pragma unroll
            for (int b = 0; b < 4; b++)
#pragma unroll
                for (int c = 0; c < 4; c++) acc[a][b][c] = 0.f;

        uint32_t ab = abase + (g & 1) * (3 * TILE_B);
#pragma unroll
        for (int ki = 0; ki < 3; ki++) {
            uint32_t b1b = sbase + ki * TILE_B;
            uint32_t a1b = ab + ki * TILE_B;
#pragma unroll
            for (int k16 = 0; k16 < 2; k16++) {
                uint32_t bf1[8];
#pragma unroll
                for (int gg = 0; gg < 2; gg++) {
                    int nrow = wn * 32 + gg * 16 + (lane & 7) + ((lane >> 4) << 3);
                    int kb   = k16 * 32 + (((lane >> 3) & 1) << 4);
                    LDSM_X4(&bf1[gg * 4], b1b + nrow * SMSTRIDE + kb);
                }
#pragma unroll
                for (int mt = 0; mt < 4; mt++) {
                    int arow = wm * 64 + mt * 16 + (lane & 7) + (((lane >> 3) & 1) << 3);
                    int kb   = k16 * 32 + ((lane >> 4) << 4);
                    uint32_t af[4];
                    LDSM_X4(af, a1b + arow * SMSTRIDE + kb);
#pragma unroll
                    for (int nt = 0; nt < 4; nt++) MMA_FP16(acc[mt][nt], af, &bf1[nt * 2]);
                }
            }
        }

        // fused epilogue: bias + relu + store fp16 + layer2 logit atomics
        int m0 = (tile0 + g) * 128;
#pragma unroll
        for (int mt = 0; mt < 4; mt++) {
            int r = m0 + wm * 64 + mt * 16 + (lane >> 2);
            float s0 = 0.f, s1 = 0.f, d0 = 0.f, d1 = 0.f;
#pragma unroll
            for (int nt = 0; nt < 4; nt++) {
                int c = n0 + wn * 32 + nt * 8 + (lane & 3) * 2;
                float v0 = fmaxf(acc[mt][nt][0] + bv[nt][0], 0.f);
                float v1 = fmaxf(acc[mt][nt][1] + bv[nt][1], 0.f);
                float v2 = fmaxf(acc[mt][nt][2] + bv[nt][0], 0.f);
                float v3 = fmaxf(acc[mt][nt][3] + bv[nt][1], 0.f);
                if (r < M)
                    *(__half2*)&C[(size_t)r * HD1 + c] = __floats2half2_rn(v0, v1);
                if (r + 8 < M)
                    *(__half2*)&C[(size_t)(r + 8) * HD1 + c] = __floats2half2_rn(v2, v3);
                s0 = fmaf(v0, av_s[nt][0], fmaf(v1, av_s[nt][1], s0));
                s1 = fmaf(v2, av_s[nt][0], fmaf(v3, av_s[nt][1], s1));
                d0 = fmaf(v0, av_d[nt][0], fmaf(v1, av_d[nt][1], d0));
                d1 = fmaf(v2, av_d[nt][0], fmaf(v3, av_d[nt][1], d1));
            }
            s0 += __shfl_xor_sync(0xffffffffu, s0, 1); s0 += __shfl_xor_sync(0xffffffffu, s0, 2);
            s1 += __shfl_xor_sync(0xffffffffu, s1, 1); s1 += __shfl_xor_sync(0xffffffffu, s1, 2);
            d0 += __shfl_xor_sync(0xffffffffu, d0, 1); d0 += __shfl_xor_sync(0xffffffffu, d0, 2);
            d1 += __shfl_xor_sync(0xffffffffu, d1, 1); d1 += __shfl_xor_sync(0xffffffffu, d1, 2);
            if ((lane & 3) == 0) {
                if (r < M)     { atomicAdd(&als[r], s0);     atomicAdd(&ald[r], d0); }
                if (r + 8 < M) { atomicAdd(&als[r + 8], s1); atomicAdd(&ald[r + 8], d1); }
            }
        }
        __syncthreads();   // protect A stage (g&1) before it is reloaded at g+2
    }
}

// ================= GEMM2: 4-stage pipelined =================
#define GM2_SMEM (4 * 2 * TILE_B)     // 81920 B

__global__ __launch_bounds__(256, 2) void k_mma2(
    const uint4* __restrict__ A1, const uint4* __restrict__ B1,
    __half* __restrict__ C, int M)
{
    constexpr int KT = 32;
    extern __shared__ char smem[];
    const uint32_t sbase = smem_u32(smem);
    const int tid = threadIdx.x, lane = tid & 31, wid = tid >> 5;
    const int wm = wid & 1, wn = wid >> 1;
    const int m0 = blockIdx.y * 128, n0 = blockIdx.x * 128;
    const int KW = KT * 4;

    float acc[4][4][4];
#pragma unroll
    for (int a = 0; a < 4; a++)
#pragma unroll
        for (int b = 0; b < 4; b++)
#pragma unroll
            for (int c = 0; c < 4; c++) acc[a][b][c] = 0.f;

    auto load_stage = [&](int ki, int s) {
        uint32_t sb = sbase + s * (2 * TILE_B);
#pragma unroll
        for (int i = 0; i < 2; i++) {
            int idx = tid + i * 256;
            int row = idx >> 2, ch = idx & 3;
            uint32_t soff = row * SMSTRIDE + ch * 16;
            int ar = min(m0 + row, M - 1);
            CP_ASYNC16(sb + soff,          A1 + (size_t)ar * KW + ki * 4 + ch);
            CP_ASYNC16(sb + TILE_B + soff, B1 + (size_t)(n0 + row) * KW + ki * 4 + ch);
        }
    };

    load_stage(0, 0); CP_COMMIT();
    load_stage(1, 1); CP_COMMIT();
    load_stage(2, 2); CP_COMMIT();

    for (int ki = 0; ki < KT; ki++) {
        if (ki + 3 < KT) load_stage(ki + 3, (ki + 3) & 3);
        CP_COMMIT();
        CP_WAIT3();
        __syncthreads();

        uint32_t sb  = sbase + (ki & 3) * (2 * TILE_B);
        uint32_t a1b = sb, b1b = sb + TILE_B;

#pragma unroll
        for (int k16 = 0; k16 < 2; k16++) {
            uint32_t bf1[8];
#pragma unroll
            for (int g = 0; g < 2; g++) {
                int nrow = wn * 32 + g * 16 + (lane & 7) + ((lane >> 4) << 3);
                int kb   = k16 * 32 + (((lane >> 3) & 1) << 4);
                LDSM_X4(&bf1[g * 4], b1b + nrow * SMSTRIDE + kb);
            }
#pragma unroll
            for (int mt = 0; mt < 4; mt++) {
                int arow = wm * 64 + mt * 16 + (lane & 7) + (((lane >> 3) & 1) << 3);
                int kb   = k16 * 32 + ((lane >> 4) << 4);
                uint32_t af[4];
                LDSM_X4(af, a1b + arow * SMSTRIDE + kb);
#pragma unroll
                for (int nt = 0; nt < 4; nt++) MMA_FP16(acc[mt][nt], af, &bf1[nt * 2]);
            }
        }
        __syncthreads();
    }

#pragma unroll
    for (int mt = 0; mt < 4; mt++) {
        int r = m0 + wm * 64 + mt * 16 + (lane >> 2);
#pragma unroll
        for (int nt = 0; nt < 4; nt++) {
            int c = n0 + wn * 32 + nt * 8 + (lane & 3) * 2;
            if (r < M)
                *(__half2*)&C[(size_t)r * D2 + c] = __floats2half2_rn(acc[mt][nt][0], acc[mt][nt][1]);
            if (r + 8 < M)
                *(__half2*)&C[(size_t)(r + 8) * D2 + c] = __floats2half2_rn(acc[mt][nt][2], acc[mt][nt][3]);
        }
    }
}

// ---------------- pool + FC ----------------
__device__ __forceinline__ int lower_bound_batch(const int* b32, int is64, int key) {
    int lo = 0, hi = N_NODES;
    while (lo < hi) {
        int mid = (lo + hi) >> 1;
        int v = is64 ? b32[2 * mid] : b32[mid];
        if (v < key) lo = mid + 1; else hi = mid;
    }
    return lo;
}
__global__ __launch_bounds__(256) void k_pool_fc(
    const int* __restrict__ batch32, const int* __restrict__ ei32,
    const float* __restrict__ fcW, const float* __restrict__ fcb,
    float* __restrict__ out)
{
    int g = blockIdx.x, t = threadIdx.x;
    __shared__ int s_lo, s_hi;
    __shared__ float pooled[D2];
    if (t == 0) {
        int is64 = detect_i64(ei32);
        s_lo = lower_bound_batch(batch32, is64, g);
        s_hi = lower_bound_batch(batch32, is64, g + 1);
    }
    __syncthreads();
    int lo = s_lo, hi = s_hi;
    float s = 0.f;
    for (int n = lo; n < hi; n++) s += g_out2[(size_t)n * D2 + t];
    float cnt = (float)(hi - lo);
    pooled[t] = s / fmaxf(cnt, 1.f);
    __syncthreads();
    if (t < OUT_DIM) {
        float acc = fcb[t];
        for (int d = 0; d < D2; d++) acc = fmaf(pooled[d], fcW[d * OUT_DIM + t], acc);
        out[g * OUT_DIM + t] = acc;
    }
}

// ---------------- launch ----------------
extern "C" void kernel_launch(void* const* d_in, const int* in_sizes, int n_in,
                              void* d_out, int out_size)
{
    const float* x      = (const float*)d_in[0];
    const int*   ei32   = (const int*)  d_in[1];
    const int*   bat32  = (const int*)  d_in[2];
    const float* W1     = (const float*)d_in[3];
    const float* a_src1 = (const float*)d_in[4];
    const float* a_dst1 = (const float*)d_in[5];
    const float* b1     = (const float*)d_in[6];
    const float* W2     = (const float*)d_in[7];
    const float* a_src2 = (const float*)d_in[8];
    const float* a_dst2 = (const float*)d_in[9];
    const float* b2     = (const float*)d_in[10];
    const float* fcW    = (const float*)d_in[11];
    const float* fcb    = (const float*)d_in[12];
    float* out = (float*)d_out;

    uint4 *xagg, *w1, *o1, *w2;
    __half *h2;
    float *als2, *ald2, *was2, *wad2;
    cudaGetSymbolAddress((void**)&xagg, g_xagg);
    cudaGetSymbolAddress((void**)&w1,   g_w1);
    cudaGetSymbolAddress((void**)&o1,   g_o1);
    cudaGetSymbolAddress((void**)&w2,   g_w2);
    cudaGetSymbolAddress((void**)&h2,   g_h2);
    cudaGetSymbolAddress((void**)&als2, g_als2);
    cudaGetSymbolAddress((void**)&ald2, g_ald2);
    cudaGetSymbolAddress((void**)&was2, g_was2);
    cudaGetSymbolAddress((void**)&wad2, g_wad2);

    cudaFuncSetAttribute((void*)k_mma1, cudaFuncAttributeMaxDynamicSharedMemorySize, GM1_SMEM);
    cudaFuncSetAttribute((void*)k_mma2, cudaFuncAttributeMaxDynamicSharedMemorySize, GM2_SMEM);

    const int MT = (N_NODES + 127) / 128;   // 391

    k_setup  <<<SETUP_GRID, 256>>>(W1, W2, a_src1, a_dst1, a_src2, a_dst2);
    k_stage2 <<<STAGE2_GRID, 256>>>(x, ei32);
    k_scan   <<<1, 1024>>>();
    k_scatter<<<(E_TOT + 255) / 256, 256>>>();
    k_aggx   <<<(N_NODES * 32 + 255) / 256, 256>>>(x);

    // GEMM1: persistent B-stationary; out1 = relu(xagg @ W1 + b1) + fused als2/ald2
    k_mma1<<<dim3(HD1 / 128, GB1_Y), 256, GM1_SMEM>>>(
        xagg, w1, (__half*)o1, N_NODES, b1, was2, wad2, als2, ald2);

    // GEMM2: h2 = out1 @ W2 (4-stage)
    k_mma2<<<dim3(D2 / 128, MT), 256, GM2_SMEM>>>(o1, w2, h2, N_NODES);

    k_agg2<<<(N_NODES * 32 + 255) / 256, 256>>>(b2);

    k_pool_fc<<<N_GRAPHS, 256>>>(bat32, ei32, fcW, fcb, out);
}

// round 11
// speedup vs baseline: 4.6336x; 1.0310x over previous
#include <cuda_runtime.h>
#include <cuda_fp16.h>
#include <math.h>
#include <stdint.h>

// ---------------- problem constants ----------------
#define N_NODES 50000
#define N_EDGES 200000
#define E_TOT   (N_EDGES + N_NODES)   // 250000
#define F0      74
#define K1PAD   96
#define H1      4
#define D1      256
#define HD1     (H1 * D1)             // 1024
#define D2      256
#define N_GRAPHS 256
#define OUT_DIM 12
#define NEG_SLOPE 0.2f

// ---------------- scratch ----------------
__device__ __half g_h2 [(size_t)N_NODES * D2];
__device__ float  g_out2[(size_t)N_NODES * D2];
__device__ float g_als1[N_NODES * H1];
__device__ float g_ald1[N_NODES * H1];
__device__ float g_als2[N_NODES];
__device__ float g_ald2[N_NODES];
__device__ int   g_deg[N_NODES];      // zeroed by previous call's k_pool_fc (or static init)
__device__ int   g_rowptr[N_NODES + 1];
__device__ int   g_cursor[N_NODES];
__device__ int   g_elist[E_TOT];
__device__ int   g_src[E_TOT];
__device__ int   g_dst[E_TOT];

// attention projection vectors
__device__ float g_was1[K1PAD * H1];
__device__ float g_wad1[K1PAD * H1];
__device__ float g_was2[HD1];
__device__ float g_wad2[HD1];

// GEMM operands (fp16, K-major, 16B-aligned)
__device__ uint4 g_xagg[(size_t)N_NODES * H1 * K1PAD / 8];
__device__ uint4 g_w1  [(size_t)HD1 * K1PAD / 8];
__device__ uint4 g_o1  [(size_t)N_NODES * HD1 / 8];
__device__ uint4 g_w2  [(size_t)D2 * HD1 / 8];

// ---------------- PTX helpers ----------------
__device__ __forceinline__ uint32_t smem_u32(const void* p) {
    uint32_t a;
    asm("{ .reg .u64 t; cvta.to.shared.u64 t, %1; cvt.u32.u64 %0, t; }" : "=r"(a) : "l"(p));
    return a;
}
#define CP_ASYNC16(dst, src) \
    asm volatile("cp.async.cg.shared.global [%0], [%1], 16;" :: "r"(dst), "l"(src))
#define CP_COMMIT() asm volatile("cp.async.commit_group;" ::: "memory")
#define CP_WAIT1()  asm volatile("cp.async.wait_group 1;" ::: "memory")
#define CP_WAIT3()  asm volatile("cp.async.wait_group 3;" ::: "memory")

#define LDSM_X4(r, addr) \
    asm volatile("ldmatrix.sync.aligned.m8n8.x4.shared.b16 {%0,%1,%2,%3}, [%4];" \
        : "=r"((r)[0]), "=r"((r)[1]), "=r"((r)[2]), "=r"((r)[3]) : "r"(addr))

#define MMA_FP16(d, a, b) \
    asm volatile("mma.sync.aligned.m16n8k16.row.col.f32.f16.f16.f32 " \
        "{%0,%1,%2,%3}, {%4,%5,%6,%7}, {%8,%9}, {%0,%1,%2,%3};" \
        : "+f"((d)[0]), "+f"((d)[1]), "+f"((d)[2]), "+f"((d)[3]) \
        : "r"((a)[0]), "r"((a)[1]), "r"((a)[2]), "r"((a)[3]), "r"((b)[0]), "r"((b)[1]))

// ---------------- misc ----------------
__device__ __forceinline__ int detect_i64(const int* p) {
    return (p[1] | p[3] | p[5] | p[7]) == 0;
}
__device__ __forceinline__ float leaky(float v) { return v >= 0.f ? v : NEG_SLOPE * v; }

// ---------------- launch 0: setup (weights, attvecs, edge decode) ----------
#define PW1_B 384
#define PW2_B 1024
#define AV1_B 37
#define AV2_B 128
#define PE_B  ((E_TOT + 255) / 256)   // 977
#define SETUP_GRID (PW1_B + PW2_B + AV1_B + AV2_B + PE_B)

__global__ __launch_bounds__(256) void k_setup(
    const float* __restrict__ W1, const float* __restrict__ W2,
    const float* __restrict__ as1, const float* __restrict__ ad1,
    const float* __restrict__ as2, const float* __restrict__ ad2,
    const int* __restrict__ ei32)
{
    int b = blockIdx.x, t = threadIdx.x, lane = t & 31;
    if (b < PW1_B) {
        int i = b * 256 + t;
        if (i < HD1 * K1PAD) {
            int n = i / K1PAD, k = i - n * K1PAD;
            float v = (k < F0) ? W1[(size_t)k * HD1 + n] : 0.f;
            ((__half*)g_w1)[i] = __float2half_rn(v);
        }
    } else if (b < PW1_B + PW2_B) {
        int i = (b - PW1_B) * 256 + t;
        if (i < D2 * HD1) {
            int n = i >> 10, k = i & 1023;
            ((__half*)g_w2)[i] = __float2half_rn(W2[(size_t)k * D2 + n]);
        }
    } else if (b < PW1_B + PW2_B + AV1_B) {
        int w = ((b - PW1_B - PW2_B) * 256 + t) >> 5;
        if (w < F0 * H1) {
            int k = w >> 2, h = w & 3;
            float s = 0.f, d = 0.f;
            for (int j = lane; j < D1; j += 32) {
                float wv = W1[(size_t)k * HD1 + h * D1 + j];
                s = fmaf(wv, as1[h * D1 + j], s);
                d = fmaf(wv, ad1[h * D1 + j], d);
            }
#pragma unroll
            for (int o = 16; o; o >>= 1) {
                s += __shfl_xor_sync(0xffffffffu, s, o);
                d += __shfl_xor_sync(0xffffffffu, d, o);
            }
            if (lane == 0) { g_was1[k * 4 + h] = s; g_wad1[k * 4 + h] = d; }
        }
    } else if (b < PW1_B + PW2_B + AV1_B + AV2_B) {
        int w = ((b - PW1_B - PW2_B - AV1_B) * 256 + t) >> 5;
        if (w < HD1) {
            float s = 0.f, d = 0.f;
            for (int j = lane; j < D2; j += 32) {
                float wv = W2[(size_t)w * D2 + j];
                s = fmaf(wv, as2[j], s);
                d = fmaf(wv, ad2[j], d);
            }
#pragma unroll
            for (int o = 16; o; o >>= 1) {
                s += __shfl_xor_sync(0xffffffffu, s, o);
                d += __shfl_xor_sync(0xffffffffu, d, o);
            }
            if (lane == 0) { g_was2[w] = s; g_wad2[w] = d; }
        }
    } else {
        int e = (b - PW1_B - PW2_B - AV1_B - AV2_B) * 256 + t;
        if (e >= E_TOT) return;
        int is64 = detect_i64(ei32);
        int s, d;
        if (e < N_EDGES) {
            s = is64 ? ei32[2 * (size_t)e]             : ei32[e];
            d = is64 ? ei32[2 * ((size_t)N_EDGES + e)] : ei32[N_EDGES + e];
        } else {
            s = d = e - N_EDGES;
        }
        g_src[e] = s;
        g_dst[e] = d;
        atomicAdd(&g_deg[d], 1);       // deg pre-zeroed by previous pool_fc
    }
}

// ---------------- launch 1: scan (block 0) + layer-1 logits ----------------
// block 0: 1024-thread scan of deg -> rowptr/cursor. blocks 1..: 32 warps, one node each.
#define SL_GRID (1 + (N_NODES + 31) / 32)

__global__ __launch_bounds__(1024) void k_scanlogit(const float* __restrict__ x) {
    if (blockIdx.x == 0) {
        __shared__ int sums[1024];
        int t = threadIdx.x;
        const int CH = (N_NODES + 1023) / 1024;
        int b = t * CH, e = min(b + CH, N_NODES);
        int s = 0;
        for (int i = b; i < e; i++) s += g_deg[i];
        sums[t] = s;
        __syncthreads();
        for (int off = 1; off < 1024; off <<= 1) {
            int v = (t >= off) ? sums[t - off] : 0;
            __syncthreads();
            sums[t] += v;
            __syncthreads();
        }
        int run = sums[t] - s;
        for (int i = b; i < e; i++) {
            g_rowptr[i] = run;
            g_cursor[i] = run;
            run += g_deg[i];
        }
        if (t == 1023) g_rowptr[N_NODES] = sums[1023];
        return;
    }
    int n = (blockIdx.x - 1) * 32 + (threadIdx.x >> 5);
    int lane = threadIdx.x & 31;
    if (n >= N_NODES) return;
    float4 s = make_float4(0, 0, 0, 0), d = make_float4(0, 0, 0, 0);
    for (int k = lane; k < F0; k += 32) {
        float xv = __ldg(&x[(size_t)n * F0 + k]);
        float4 a = *(const float4*)(g_was1 + k * 4);
        float4 bb = *(const float4*)(g_wad1 + k * 4);
        s.x = fmaf(xv, a.x, s.x);  s.y = fmaf(xv, a.y, s.y);
        s.z = fmaf(xv, a.z, s.z);  s.w = fmaf(xv, a.w, s.w);
        d.x = fmaf(xv, bb.x, d.x); d.y = fmaf(xv, bb.y, d.y);
        d.z = fmaf(xv, bb.z, d.z); d.w = fmaf(xv, bb.w, d.w);
    }
#pragma unroll
    for (int o = 16; o; o >>= 1) {
        s.x += __shfl_xor_sync(0xffffffffu, s.x, o);
        s.y += __shfl_xor_sync(0xffffffffu, s.y, o);
        s.z += __shfl_xor_sync(0xffffffffu, s.z, o);
        s.w += __shfl_xor_sync(0xffffffffu, s.w, o);
        d.x += __shfl_xor_sync(0xffffffffu, d.x, o);
        d.y += __shfl_xor_sync(0xffffffffu, d.y, o);
        d.z += __shfl_xor_sync(0xffffffffu, d.z, o);
        d.w += __shfl_xor_sync(0xffffffffu, d.w, o);
    }
    if (lane == 0) {
        *(float4*)(g_als1 + n * 4) = s;
        *(float4*)(g_ald1 + n * 4) = d;
    }
}

// ---------------- launch 2: scatter ----------------
__global__ void k_scatter() {
    int e = blockIdx.x * blockDim.x + threadIdx.x;
    if (e >= E_TOT) return;
    int p = atomicAdd(&g_cursor[g_dst[e]], 1);
    g_elist[p] = e;
}

// ---------------- launch 3 (PROFILED): layer-1 aggregate ----------------
__global__ __launch_bounds__(256) void k_aggx(const float* __restrict__ x) {
    int n = (blockIdx.x * blockDim.x + threadIdx.x) >> 5;
    int lane = threadIdx.x & 31;
    if (n >= N_NODES) return;
    if (lane == 0) { g_als2[n] = 0.f; g_ald2[n] = 0.f; }   // mma1 accumulates later
    int start = g_rowptr[n], deg = g_rowptr[n + 1] - start;
    const float4 adn = *(const float4*)(g_ald1 + n * 4);

    float a[3][4];
#pragma unroll
    for (int g = 0; g < 3; g++)
#pragma unroll
        for (int h = 0; h < 4; h++) a[g][h] = 0.f;
    float4 den = make_float4(0, 0, 0, 0);

    for (int c0 = 0; c0 < deg; c0 += 32) {
        int j = c0 + lane;
        int srcj = 0;
        float4 e = make_float4(0, 0, 0, 0);
        if (j < deg) {
            int ed = g_elist[start + j];
            srcj = g_src[ed];
            float4 as = *(const float4*)(g_als1 + srcj * 4);
            e.x = expf(leaky(as.x + adn.x));
            e.y = expf(leaky(as.y + adn.y));
            e.z = expf(leaky(as.z + adn.z));
            e.w = expf(leaky(as.w + adn.w));
            den.x += e.x; den.y += e.y; den.z += e.z; den.w += e.w;
        }
        int cnt = min(32, deg - c0);
        for (int jj = 0; jj < cnt; jj++) {
            int s  = __shfl_sync(0xffffffffu, srcj, jj);
            float e0 = __shfl_sync(0xffffffffu, e.x, jj);
            float e1 = __shfl_sync(0xffffffffu, e.y, jj);
            float e2 = __shfl_sync(0xffffffffu, e.z, jj);
            float e3 = __shfl_sync(0xffffffffu, e.w, jj);
            const float* xr = x + (size_t)s * F0;
            float x0 = __ldg(xr + lane);
            float x1 = __ldg(xr + lane + 32);
            float x2 = (lane + 64 < F0) ? __ldg(xr + lane + 64) : 0.f;
            a[0][0] = fmaf(x0, e0, a[0][0]); a[0][1] = fmaf(x0, e1, a[0][1]);
            a[0][2] = fmaf(x0, e2, a[0][2]); a[0][3] = fmaf(x0, e3, a[0][3]);
            a[1][0] = fmaf(x1, e0, a[1][0]); a[1][1] = fmaf(x1, e1, a[1][1]);
            a[1][2] = fmaf(x1, e2, a[1][2]); a[1][3] = fmaf(x1, e3, a[1][3]);
            a[2][0] = fmaf(x2, e0, a[2][0]); a[2][1] = fmaf(x2, e1, a[2][1]);
            a[2][2] = fmaf(x2, e2, a[2][2]); a[2][3] = fmaf(x2, e3, a[2][3]);
        }
    }
#pragma unroll
    for (int o = 16; o; o >>= 1) {
        den.x += __shfl_xor_sync(0xffffffffu, den.x, o);
        den.y += __shfl_xor_sync(0xffffffffu, den.y, o);
        den.z += __shfl_xor_sync(0xffffffffu, den.z, o);
        den.w += __shfl_xor_sync(0xffffffffu, den.w, o);
    }
    float inv[4];
    inv[0] = 1.f / (den.x + 1e-16f);
    inv[1] = 1.f / (den.y + 1e-16f);
    inv[2] = 1.f / (den.z + 1e-16f);
    inv[3] = 1.f / (den.w + 1e-16f);

    __half* xa = (__half*)g_xagg + (size_t)n * (H1 * K1PAD);
#pragma unroll
    for (int g = 0; g < 3; g++) {
        int col = lane + 32 * g;
#pragma unroll
        for (int h = 0; h < 4; h++)
            xa[h * K1PAD + col] = __float2half_rn(a[g][h] * inv[h]);
    }
}

// ---------------- layer-2 aggregate ----------------
__global__ __launch_bounds__(256) void k_agg2(const float* __restrict__ b2) {
    int n = (blockIdx.x * blockDim.x + threadIdx.x) >> 5;
    int lane = threadIdx.x & 31;
    if (n >= N_NODES) return;
    int start = g_rowptr[n], deg = g_rowptr[n + 1] - start;
    const float adn = g_ald2[n];

    float2 acc[4];
#pragma unroll
    for (int q = 0; q < 4; q++) acc[q] = make_float2(0.f, 0.f);
    float den = 0.f;

    for (int c0 = 0; c0 < deg; c0 += 32) {
        int j = c0 + lane;
        int srcj = 0;
        float e = 0.f;
        if (j < deg) {
            int ed = g_elist[start + j];
            srcj = g_src[ed];
            e = expf(leaky(g_als2[srcj] + adn));
            den += e;
        }
        int cnt = min(32, deg - c0);
        for (int jj = 0; jj < cnt; jj++) {
            int s   = __shfl_sync(0xffffffffu, srcj, jj);
            float ev = __shfl_sync(0xffffffffu, e, jj);
            const __half2* hr = (const __half2*)(g_h2 + (size_t)s * D2);
#pragma unroll
            for (int q = 0; q < 4; q++) {
                float2 v = __half22float2(__ldg(hr + lane + 32 * q));
                acc[q].x = fmaf(v.x, ev, acc[q].x);
                acc[q].y = fmaf(v.y, ev, acc[q].y);
            }
        }
    }
#pragma unroll
    for (int o = 16; o; o >>= 1) den += __shfl_xor_sync(0xffffffffu, den, o);
    float inv = 1.f / (den + 1e-16f);

#pragma unroll
    for (int q = 0; q < 4; q++) {
        int c = 2 * (lane + 32 * q);
        float2 o;
        o.x = fmaxf(fmaf(acc[q].x, inv, 0.f) + __ldg(b2 + c),     0.f);
        o.y = fmaxf(fmaf(acc[q].y, inv, 0.f) + __ldg(b2 + c + 1), 0.f);
        *(float2*)&g_out2[(size_t)n * D2 + c] = o;
    }
}

// ---------------- GEMM tiles ----------------
#define SMSTRIDE 80
#define TILE_B   (128 * SMSTRIDE)

// ================= GEMM1: persistent B-stationary =================
#define MT1 8
#define GB1_Y 49
#define GM1_SMEM (3 * TILE_B + 2 * 3 * TILE_B)    // 92160 B

__global__ __launch_bounds__(256, 2) void k_mma1(
    const uint4* __restrict__ A1, const uint4* __restrict__ B1,
    __half* __restrict__ C, int M,
    const float* __restrict__ bias,
    const float* __restrict__ avs, const float* __restrict__ avd,
    float* __restrict__ als, float* __restrict__ ald)
{
    extern __shared__ char smem[];
    const uint32_t sbase = smem_u32(smem);
    const uint32_t abase = sbase + 3 * TILE_B;
    const int tid = threadIdx.x, lane = tid & 31, wid = tid >> 5;
    const int wm = wid & 1, wn = wid >> 1;
    const int n0 = blockIdx.x * 128;
    const int head = n0 >> 8;
    const int tile0 = blockIdx.y * MT1;
    const int KW = 12;
    const int AST = H1 * KW;

    float bv[4][2], av_s[4][2], av_d[4][2];
#pragma unroll
    for (int nt = 0; nt < 4; nt++) {
        int c = n0 + wn * 32 + nt * 8 + (lane & 3) * 2;
        bv[nt][0]   = bias[c]; bv[nt][1]   = bias[c + 1];
        av_s[nt][0] = avs[c];  av_s[nt][1] = avs[c + 1];
        av_d[nt][0] = avd[c];  av_d[nt][1] = avd[c + 1];
    }

    auto load_A = [&](int tile, int s) {
        uint32_t sb = abase + s * (3 * TILE_B);
        int m0 = tile * 128;
#pragma unroll
        for (int i = 0; i < 6; i++) {
            int idx = tid + i * 256;
            int chunk = idx / 512, rem = idx & 511;
            int row = rem >> 2, ch = rem & 3;
            int ar = min(m0 + row, M - 1);
            CP_ASYNC16(sb + chunk * TILE_B + row * SMSTRIDE + ch * 16,
                       A1 + (size_t)ar * AST + head * KW + chunk * 4 + ch);
        }
    };

#pragma unroll
    for (int i = 0; i < 6; i++) {
        int idx = tid + i * 256;
        int chunk = idx / 512, rem = idx & 511;
        int row = rem >> 2, ch = rem & 3;
        CP_ASYNC16(sbase + chunk * TILE_B + row * SMSTRIDE + ch * 16,
                   B1 + (size_t)(n0 + row) * KW + chunk * 4 + ch);
    }
    load_A(tile0, 0);
    CP_COMMIT();

    for (int g = 0; g < MT1; g++) {
        if (g + 1 < MT1) load_A(tile0 + g + 1, (g + 1) & 1);
        CP_COMMIT();
        CP_WAIT1();
        __syncthreads();

        float acc[4][4][4];
#pragma unroll
        for (int a = 0; a < 4; a++)
#pragma unroll
            for (int b = 0; b < 4; b++)
#pragma unroll
                for (int c = 0; c < 4; c++) acc[a][b][c] = 0.f;

        uint32_t ab = abase + (g & 1) * (3 * TILE_B);
#pragma unroll
        for (int ki = 0; ki < 3; ki++) {
            uint32_t b1b = sbase + ki * TILE_B;
            uint32_t a1b = ab + ki * TILE_B;
#pragma unroll
            for (int k16 = 0; k16 < 2; k16++) {
                uint32_t bf1[8];
#pragma unroll
                for (int gg = 0; gg < 2; gg++) {
                    int nrow = wn * 32 + gg * 16 + (lane & 7) + ((lane >> 4) << 3);
                    int kb   = k16 * 32 + (((lane >> 3) & 1) << 4);
                    LDSM_X4(&bf1[gg * 4], b1b + nrow * SMSTRIDE + kb);
                }
#pragma unroll
                for (int mt = 0; mt < 4; mt++) {
                    int arow = wm * 64 + mt * 16 + (lane & 7) + (((lane >> 3) & 1) << 3);
                    int kb   = k16 * 32 + ((lane >> 4) << 4);
                    uint32_t af[4];
                    LDSM_X4(af, a1b + arow * SMSTRIDE + kb);
#pragma unroll
                    for (int nt = 0; nt < 4; nt++) MMA_FP16(acc[mt][nt], af, &bf1[nt * 2]);
                }
            }
        }

        int m0 = (tile0 + g) * 128;
#pragma unroll
        for (int mt = 0; mt < 4; mt++) {
            int r = m0 + wm * 64 + mt * 16 + (lane >> 2);
            float s0 = 0.f, s1 = 0.f, d0 = 0.f, d1 = 0.f;
#pragma unroll
            for (int nt = 0; nt < 4; nt++) {
                int c = n0 + wn * 32 + nt * 8 + (lane & 3) * 2;
                float v0 = fmaxf(acc[mt][nt][0] + bv[nt][0], 0.f);
                float v1 = fmaxf(acc[mt][nt][1] + bv[nt][1], 0.f);
                float v2 = fmaxf(acc[mt][nt][2] + bv[nt][0], 0.f);
                float v3 = fmaxf(acc[mt][nt][3] + bv[nt][1], 0.f);
                if (r < M)
                    *(__half2*)&C[(size_t)r * HD1 + c] = __floats2half2_rn(v0, v1);
                if (r + 8 < M)
                    *(__half2*)&C[(size_t)(r + 8) * HD1 + c] = __floats2half2_rn(v2, v3);
                s0 = fmaf(v0, av_s[nt][0], fmaf(v1, av_s[nt][1], s0));
                s1 = fmaf(v2, av_s[nt][0], fmaf(v3, av_s[nt][1], s1));
                d0 = fmaf(v0, av_d[nt][0], fmaf(v1, av_d[nt][1], d0));
                d1 = fmaf(v2, av_d[nt][0], fmaf(v3, av_d[nt][1], d1));
            }
            s0 += __shfl_xor_sync(0xffffffffu, s0, 1); s0 += __shfl_xor_sync(0xffffffffu, s0, 2);
            s1 += __shfl_xor_sync(0xffffffffu, s1, 1); s1 += __shfl_xor_sync(0xffffffffu, s1, 2);
            d0 += __shfl_xor_sync(0xffffffffu, d0, 1); d0 += __shfl_xor_sync(0xffffffffu, d0, 2);
            d1 += __shfl_xor_sync(0xffffffffu, d1, 1); d1 += __shfl_xor_sync(0xffffffffu, d1, 2);
            if ((lane & 3) == 0) {
                if (r < M)     { atomicAdd(&als[r], s0);     atomicAdd(&ald[r], d0); }
                if (r + 8 < M) { atomicAdd(&als[r + 8], s1); atomicAdd(&ald[r + 8], d1); }
            }
        }
        __syncthreads();
    }
}

// ================= GEMM2: 4-stage pipelined =================
#define GM2_SMEM (4 * 2 * TILE_B)     // 81920 B

__global__ __launch_bounds__(256, 2) void k_mma2(
    const uint4* __restrict__ A1, const uint4* __restrict__ B1,
    __half* __restrict__ C, int M)
{
    constexpr int KT = 32;
    extern __shared__ char smem[];
    const uint32_t sbase = smem_u32(smem);
    const int tid = threadIdx.x, lane = tid & 31, wid = tid >> 5;
    const int wm = wid & 1, wn = wid >> 1;
    const int m0 = blockIdx.y * 128, n0 = blockIdx.x * 128;
    const int KW = KT * 4;

    float acc[4][4][4];
#pragma unroll
    for (int a = 0; a < 4; a++)
#pragma unroll
        for (int b = 0; b < 4; b++)
#pragma unroll
            for (int c = 0; c < 4; c++) acc[a][b][c] = 0.f;

    auto load_stage = [&](int ki, int s) {
        uint32_t sb = sbase + s * (2 * TILE_B);
#pragma unroll
        for (int i = 0; i < 2; i++) {
            int idx = tid + i * 256;
            int row = idx >> 2, ch = idx & 3;
            uint32_t soff = row * SMSTRIDE + ch * 16;
            int ar = min(m0 + row, M - 1);
            CP_ASYNC16(sb + soff,          A1 + (size_t)ar * KW + ki * 4 + ch);
            CP_ASYNC16(sb + TILE_B + soff, B1 + (size_t)(n0 + row) * KW + ki * 4 + ch);
        }
    };

    load_stage(0, 0); CP_COMMIT();
    load_stage(1, 1); CP_COMMIT();
    load_stage(2, 2); CP_COMMIT();

    for (int ki = 0; ki < KT; ki++) {
        if (ki + 3 < KT) load_stage(ki + 3, (ki + 3) & 3);
        CP_COMMIT();
        CP_WAIT3();
        __syncthreads();

        uint32_t sb  = sbase + (ki & 3) * (2 * TILE_B);
        uint32_t a1b = sb, b1b = sb + TILE_B;

#pragma unroll
        for (int k16 = 0; k16 < 2; k16++) {
            uint32_t bf1[8];
#pragma unroll
            for (int g = 0; g < 2; g++) {
                int nrow = wn * 32 + g * 16 + (lane & 7) + ((lane >> 4) << 3);
                int kb   = k16 * 32 + (((lane >> 3) & 1) << 4);
                LDSM_X4(&bf1[g * 4], b1b + nrow * SMSTRIDE + kb);
            }
#pragma unroll
            for (int mt = 0; mt < 4; mt++) {
                int arow = wm * 64 + mt * 16 + (lane & 7) + (((lane >> 3) & 1) << 3);
                int kb   = k16 * 32 + ((lane >> 4) << 4);
                uint32_t af[4];
                LDSM_X4(af, a1b + arow * SMSTRIDE + kb);
#pragma unroll
                for (int nt = 0; nt < 4; nt++) MMA_FP16(acc[mt][nt], af, &bf1[nt * 2]);
            }
        }
        __syncthreads();
    }

#pragma unroll
    for (int mt = 0; mt < 4; mt++) {
        int r = m0 + wm * 64 + mt * 16 + (lane >> 2);
#pragma unroll
        for (int nt = 0; nt < 4; nt++) {
            int c = n0 + wn * 32 + nt * 8 + (lane & 3) * 2;
            if (r < M)
                *(__half2*)&C[(size_t)r * D2 + c] = __floats2half2_rn(acc[mt][nt][0], acc[mt][nt][1]);
            if (r + 8 < M)
                *(__half2*)&C[(size_t)(r + 8) * D2 + c] = __floats2half2_rn(acc[mt][nt][2], acc[mt][nt][3]);
        }
    }
}

// ---------------- pool + FC (+ deg cleanup for next call) ----------------
__device__ __forceinline__ int lower_bound_batch(const int* b32, int is64, int key) {
    int lo = 0, hi = N_NODES;
    while (lo < hi) {
        int mid = (lo + hi) >> 1;
        int v = is64 ? b32[2 * mid] : b32[mid];
        if (v < key) lo = mid + 1; else hi = mid;
    }
    return lo;
}
__global__ __launch_bounds__(256) void k_pool_fc(
    const int* __restrict__ batch32, const int* __restrict__ ei32,
    const float* __restrict__ fcW, const float* __restrict__ fcb,
    float* __restrict__ out)
{
    int g = blockIdx.x, t = threadIdx.x;
    // deg cleanup for next call (grid 256x256 = 65536 threads covers 50000)
    int gid = g * 256 + t;
    if (gid < N_NODES) g_deg[gid] = 0;

    __shared__ int s_lo, s_hi;
    __shared__ float pooled[D2];
    if (t == 0) {
        int is64 = detect_i64(ei32);
        s_lo = lower_bound_batch(batch32, is64, g);
        s_hi = lower_bound_batch(batch32, is64, g + 1);
    }
    __syncthreads();
    int lo = s_lo, hi = s_hi;
    float s = 0.f;
    for (int n = lo; n < hi; n++) s += g_out2[(size_t)n * D2 + t];
    float cnt = (float)(hi - lo);
    pooled[t] = s / fmaxf(cnt, 1.f);
    __syncthreads();
    if (t < OUT_DIM) {
        float acc = fcb[t];
        for (int d = 0; d < D2; d++) acc = fmaf(pooled[d], fcW[d * OUT_DIM + t], acc);
        out[g * OUT_DIM + t] = acc;
    }
}

// ---------------- launch ----------------
extern "C" void kernel_launch(void* const* d_in, const int* in_sizes, int n_in,
                              void* d_out, int out_size)
{
    const float* x      = (const float*)d_in[0];
    const int*   ei32   = (const int*)  d_in[1];
    const int*   bat32  = (const int*)  d_in[2];
    const float* W1     = (const float*)d_in[3];
    const float* a_src1 = (const float*)d_in[4];
    const float* a_dst1 = (const float*)d_in[5];
    const float* b1     = (const float*)d_in[6];
    const float* W2     = (const float*)d_in[7];
    const float* a_src2 = (const float*)d_in[8];
    const float* a_dst2 = (const float*)d_in[9];
    const float* b2     = (const float*)d_in[10];
    const float* fcW    = (const float*)d_in[11];
    const float* fcb    = (const float*)d_in[12];
    float* out = (float*)d_out;

    uint4 *xagg, *w1, *o1, *w2;
    __half *h2;
    float *als2, *ald2, *was2, *wad2;
    cudaGetSymbolAddress((void**)&xagg, g_xagg);
    cudaGetSymbolAddress((void**)&w1,   g_w1);
    cudaGetSymbolAddress((void**)&o1,   g_o1);
    cudaGetSymbolAddress((void**)&w2,   g_w2);
    cudaGetSymbolAddress((void**)&h2,   g_h2);
    cudaGetSymbolAddress((void**)&als2, g_als2);
    cudaGetSymbolAddress((void**)&ald2, g_ald2);
    cudaGetSymbolAddress((void**)&was2, g_was2);
    cudaGetSymbolAddress((void**)&wad2, g_wad2);

    cudaFuncSetAttribute((void*)k_mma1, cudaFuncAttributeMaxDynamicSharedMemorySize, GM1_SMEM);
    cudaFuncSetAttribute((void*)k_mma2, cudaFuncAttributeMaxDynamicSharedMemorySize, GM2_SMEM);

    const int MT = (N_NODES + 127) / 128;   // 391

    k_setup    <<<SETUP_GRID, 256>>>(W1, W2, a_src1, a_dst1, a_src2, a_dst2, ei32);  // 0
    k_scanlogit<<<SL_GRID, 1024>>>(x);                                               // 1
    k_scatter  <<<(E_TOT + 255) / 256, 256>>>();                                     // 2
    k_aggx     <<<(N_NODES * 32 + 255) / 256, 256>>>(x);                             // 3 (profiled)

    k_mma1<<<dim3(HD1 / 128, GB1_Y), 256, GM1_SMEM>>>(
        xagg, w1, (__half*)o1, N_NODES, b1, was2, wad2, als2, ald2);                 // 4

    k_mma2<<<dim3(D2 / 128, MT), 256, GM2_SMEM>>>(o1, w2, h2, N_NODES);              // 5

    k_agg2<<<(N_NODES * 32 + 255) / 256, 256>>>(b2);                                 // 6

    k_pool_fc<<<N_GRAPHS, 256>>>(bat32, ei32, fcW, fcb, out);                        // 7
}